// round 10
// baseline (speedup 1.0000x reference)
#include <cuda_runtime.h>
#include <cuda_fp16.h>
#include <stdint.h>
#include <math.h>

typedef unsigned int u32;

#define NN 50000
#define EE 800000
#define ET (EE + NN)
#define TDIM 64

// ---------------- scratch (static device globals; no allocation) ----------------
__device__ int    g_deg[NN];
__device__ int    g_rowptr[NN + 1];
__device__ int    g_cursor[NN];
__device__ int    g_colsrc[ET];
__device__ float4 g_alphaE0[EE];    // per original edge (pre-CSR)
__device__ float4 g_alphaE1[EE];
__device__ float4 g_aE0c[ET];       // CSR-ordered
__device__ float4 g_aE1c[ET];
__device__ __half g_xh[(size_t)NN * 128];
__device__ __half g_w0h[128 * 256];
__device__ __half g_w1h[256 * 64];
__device__ __half g_hh0[(size_t)NN * 256];
__device__ __half g_out0h[(size_t)NN * 256];
__device__ __half g_hh1[(size_t)NN * 64];
__device__ float4 g_ss0[NN], g_sd0[NN], g_ss1[NN], g_sd1[NN];
__device__ float4 g_ve0[TDIM];
__device__ float4 g_ve1[TDIM];
__device__ float4 g_self0, g_self1;

// ---------------- PTX helpers ----------------
__device__ __forceinline__ void ldsm_x4(u32& r0, u32& r1, u32& r2, u32& r3, u32 addr) {
    asm volatile("ldmatrix.sync.aligned.m8n8.x4.shared.b16 {%0,%1,%2,%3}, [%4];"
                 : "=r"(r0), "=r"(r1), "=r"(r2), "=r"(r3) : "r"(addr));
}
__device__ __forceinline__ void ldsm_x4_trans(u32& r0, u32& r1, u32& r2, u32& r3, u32 addr) {
    asm volatile("ldmatrix.sync.aligned.m8n8.x4.trans.shared.b16 {%0,%1,%2,%3}, [%4];"
                 : "=r"(r0), "=r"(r1), "=r"(r2), "=r"(r3) : "r"(addr));
}
__device__ __forceinline__ void mma16816(float& c0, float& c1, float& c2, float& c3,
                                         u32 a0, u32 a1, u32 a2, u32 a3,
                                         u32 b0, u32 b1) {
    asm volatile(
        "mma.sync.aligned.m16n8k16.row.col.f32.f16.f16.f32 "
        "{%0,%1,%2,%3}, {%4,%5,%6,%7}, {%8,%9}, {%0,%1,%2,%3};"
        : "+f"(c0), "+f"(c1), "+f"(c2), "+f"(c3)
        : "r"(a0), "r"(a1), "r"(a2), "r"(a3), "r"(b0), "r"(b1));
}
__device__ __forceinline__ void cp_async16(u32 saddr, const void* gaddr, int src_bytes) {
    asm volatile("cp.async.ca.shared.global [%0], [%1], 16, %2;"
                 :: "r"(saddr), "l"(gaddr), "r"(src_bytes));
}
#define CP_COMMIT()  asm volatile("cp.async.commit_group;")
#define CP_WAIT(n)   asm volatile("cp.async.wait_group %0;" :: "n"(n))

// ---------------- fp32 -> fp16 convert ----------------
__global__ void cvt_kernel(const float* __restrict__ in, __half* __restrict__ out, int n4) {
    int i = blockIdx.x * blockDim.x + threadIdx.x;
    if (i < n4) {
        float4 v = *(const float4*)(in + (size_t)i * 4);
        __half2 a = __floats2half2_rn(v.x, v.y);
        __half2 b = __floats2half2_rn(v.z, v.w);
        *(__half2*)(out + (size_t)i * 4) = a;
        *(__half2*)(out + (size_t)i * 4 + 2) = b;
    }
}

// ---------------- init deg (self loops) ----------------
__global__ void init_kernel(int* deg, int n) {
    int i = blockIdx.x * blockDim.x + threadIdx.x;
    if (i < n) deg[i] = 1;
}

// ---------------- prep ----------------
__global__ void prep_kernel(const float* __restrict__ le0, const float* __restrict__ ae0,
                            const float* __restrict__ le1, const float* __restrict__ ae1) {
    int tid = threadIdx.x;
    int td = tid >> 2, hh = tid & 3;
    float s0 = 0.f;
    for (int c = 0; c < 64; c++) s0 += le0[td * 256 + hh * 64 + c] * ae0[hh * 64 + c];
    ((float*)g_ve0)[td * 4 + hh] = s0;
    float s1 = 0.f;
    for (int c = 0; c < 16; c++) s1 += le1[td * 64 + hh * 16 + c] * ae1[hh * 16 + c];
    ((float*)g_ve1)[td * 4 + hh] = s1;
    __syncthreads();
    if (td == 0) {
        float a = 0.f, b = 0.f;
        for (int t2 = 0; t2 < TDIM; t2++) {
            a += ((float*)g_ve0)[t2 * 4 + hh];
            b += ((float*)g_ve1)[t2 * 4 + hh];
        }
        ((float*)&g_self0)[hh] = a;
        ((float*)&g_self1)[hh] = b;
    }
}

// ---------------- per-edge time features + fused deg count ----------------
__global__ void edge_feat_kernel(const float* __restrict__ ts,
                                 const float* __restrict__ tw,
                                 const float* __restrict__ tb,
                                 const int* __restrict__ dst,
                                 int* __restrict__ deg,
                                 float4* __restrict__ aE0, float4* __restrict__ aE1,
                                 int e) {
    __shared__ float2 swb[TDIM];
    __shared__ float4 sv0[TDIM];
    __shared__ float4 sv1[TDIM];
    int tid = threadIdx.x;
    if (tid < TDIM) {
        swb[tid] = make_float2(tw[tid], tb[tid]);
        sv0[tid] = g_ve0[tid];
        sv1[tid] = g_ve1[tid];
    }
    __syncthreads();
    int iA = blockIdx.x * 512 + tid;
    int iB = iA + 256;
    float tA = (iA < e) ? ts[iA] : 0.f;
    float tB = (iB < e) ? ts[iB] : 0.f;
    if (iA < e) atomicAdd(&deg[dst[iA]], 1);
    if (iB < e) atomicAdd(&deg[dst[iB]], 1);
    float4 A0 = make_float4(0, 0, 0, 0), A1 = A0, B0 = A0, B1 = A0;
    #pragma unroll 8
    for (int td = 0; td < TDIM; td++) {
        float2 wb = swb[td];
        float4 v0 = sv0[td];
        float4 v1 = sv1[td];
        float aA = fabsf(__cosf(fmaf(tA, wb.x, wb.y)));
        float aB = fabsf(__cosf(fmaf(tB, wb.x, wb.y)));
        A0.x = fmaf(aA, v0.x, A0.x); A0.y = fmaf(aA, v0.y, A0.y);
        A0.z = fmaf(aA, v0.z, A0.z); A0.w = fmaf(aA, v0.w, A0.w);
        A1.x = fmaf(aA, v1.x, A1.x); A1.y = fmaf(aA, v1.y, A1.y);
        A1.z = fmaf(aA, v1.z, A1.z); A1.w = fmaf(aA, v1.w, A1.w);
        B0.x = fmaf(aB, v0.x, B0.x); B0.y = fmaf(aB, v0.y, B0.y);
        B0.z = fmaf(aB, v0.z, B0.z); B0.w = fmaf(aB, v0.w, B0.w);
        B1.x = fmaf(aB, v1.x, B1.x); B1.y = fmaf(aB, v1.y, B1.y);
        B1.z = fmaf(aB, v1.z, B1.z); B1.w = fmaf(aB, v1.w, B1.w);
    }
    if (iA < e) { aE0[iA] = A0; aE1[iA] = A1; }
    if (iB < e) { aE0[iB] = B0; aE1[iB] = B1; }
}

// ---------------- CSR scan ----------------
__global__ void scan_kernel(const int* __restrict__ deg, int* __restrict__ rowptr,
                            int* __restrict__ cursor, int n) {
    const int T = 1024;
    __shared__ int wsum[32];
    __shared__ int stotal;
    int t = threadIdx.x;
    int CH = (n + T - 1) / T;
    int s0 = t * CH, s1 = min(s0 + CH, n);
    int sum = 0;
    for (int i = s0; i < s1; i++) sum += deg[i];
    int lane = t & 31, wid = t >> 5;
    int v = sum;
    #pragma unroll
    for (int off = 1; off < 32; off <<= 1) {
        int x = __shfl_up_sync(0xffffffffu, v, off);
        if (lane >= off) v += x;
    }
    if (lane == 31) wsum[wid] = v;
    __syncthreads();
    if (wid == 0) {
        int w = wsum[lane];
        #pragma unroll
        for (int off = 1; off < 32; off <<= 1) {
            int x = __shfl_up_sync(0xffffffffu, w, off);
            if (lane >= off) w += x;
        }
        wsum[lane] = w;
        if (lane == 31) stotal = w;
    }
    __syncthreads();
    int excl = v - sum + (wid ? wsum[wid - 1] : 0);
    int run = excl;
    for (int i = s0; i < s1; i++) {
        rowptr[i] = run;
        cursor[i] = run;
        run += deg[i];
    }
    if (t == T - 1) rowptr[n] = stotal;
}

// ---------------- scatter: build colsrc + permute aE into CSR order ----------------
__global__ void scatter_kernel(const int* __restrict__ src, const int* __restrict__ dst,
                               const float4* __restrict__ aE0, const float4* __restrict__ aE1,
                               int* cursor, int* colsrc,
                               float4* __restrict__ aE0c, float4* __restrict__ aE1c,
                               int e, int n) {
    int i = blockIdx.x * blockDim.x + threadIdx.x;
    int tot = e + n;
    if (i >= tot) return;
    if (i < e) {
        int d = dst[i];
        int p = atomicAdd(&cursor[d], 1);
        colsrc[p] = src[i];
        aE0c[p] = aE0[i];
        aE1c[p] = aE1[i];
    } else {
        int node = i - e;
        int p = atomicAdd(&cursor[node], 1);
        colsrc[p] = node;
        aE0c[p] = g_self0;
        aE1c[p] = g_self1;
    }
}

// ---------------- fp16 tensor-core GEMM with cp.async double buffering ----------------
// BM=128, BN=64, BK=32; 256 threads, warp tile 32x32, mma.m16n8k16.
__global__ void hgemm_kernel(const __half* __restrict__ A, const __half* __restrict__ B,
                             __half* __restrict__ C, int M, int K, int N) {
    __shared__ __half As[2][128][40];   // per stage: 10240 B
    __shared__ __half Bs[2][32][72];    // per stage: 4608 B
    const int AS_B = 128 * 40 * 2;
    const int BS_B = 32 * 72 * 2;
    int bm = blockIdx.y * 128, bn = blockIdx.x * 64;
    int tid = threadIdx.x;
    int wid = tid >> 5, lane = tid & 31;
    int wm = (wid >> 1) * 32, wn = (wid & 1) * 32;
    float acc[2][4][4];
    #pragma unroll
    for (int mt = 0; mt < 2; mt++)
        #pragma unroll
        for (int nt = 0; nt < 4; nt++)
            #pragma unroll
            for (int r = 0; r < 4; r++) acc[mt][nt][r] = 0.f;

    u32 as_base = (u32)__cvta_generic_to_shared(&As[0][0][0]);
    u32 bs_base = (u32)__cvta_generic_to_shared(&Bs[0][0][0]);

    // load indices (constant per thread)
    int a_row0 = tid >> 2, a_c8 = (tid & 3) * 8;          // + it*64 rows
    int b_row = tid >> 3, b_c8 = (tid & 7) * 8;

    // prologue: stage 0
    {
        #pragma unroll
        for (int it = 0; it < 2; it++) {
            int row = a_row0 + it * 64;
            int gm = bm + row;
            int ok = (gm < M);
            const void* g = A + (size_t)(ok ? gm : 0) * K + a_c8;
            cp_async16(as_base + (u32)(row * 40 + a_c8) * 2, g, ok ? 16 : 0);
        }
        cp_async16(bs_base + (u32)(b_row * 72 + b_c8) * 2,
                   B + (size_t)b_row * N + bn + b_c8, 16);
        CP_COMMIT();
    }

    int KT = K >> 5;
    for (int kt = 0; kt < KT; kt++) {
        if (kt + 1 < KT) {
            int st = (kt + 1) & 1;
            int k0 = (kt + 1) * 32;
            #pragma unroll
            for (int it = 0; it < 2; it++) {
                int row = a_row0 + it * 64;
                int gm = bm + row;
                int ok = (gm < M);
                const void* g = A + (size_t)(ok ? gm : 0) * K + k0 + a_c8;
                cp_async16(as_base + (u32)(st * AS_B) + (u32)(row * 40 + a_c8) * 2, g, ok ? 16 : 0);
            }
            cp_async16(bs_base + (u32)(st * BS_B) + (u32)(b_row * 72 + b_c8) * 2,
                       B + (size_t)(k0 + b_row) * N + bn + b_c8, 16);
            CP_COMMIT();
            CP_WAIT(1);
        } else {
            CP_WAIT(0);
        }
        __syncthreads();
        u32 ab = as_base + (u32)((kt & 1) * AS_B);
        u32 bb = bs_base + (u32)((kt & 1) * BS_B);
        #pragma unroll
        for (int kk = 0; kk < 32; kk += 16) {
            u32 a0[4], a1[4], b0[4], b1[4];
            {
                int arow = wm + (lane & 15);
                int acol = kk + (lane >> 4) * 8;
                ldsm_x4(a0[0], a0[1], a0[2], a0[3], ab + (u32)(arow * 40 + acol) * 2);
            }
            {
                int arow = wm + 16 + (lane & 15);
                int acol = kk + (lane >> 4) * 8;
                ldsm_x4(a1[0], a1[1], a1[2], a1[3], ab + (u32)(arow * 40 + acol) * 2);
            }
            {
                int brow = kk + (lane & 15);
                int bcol = wn + (lane >> 4) * 8;
                ldsm_x4_trans(b0[0], b0[1], b0[2], b0[3], bb + (u32)(brow * 72 + bcol) * 2);
            }
            {
                int brow = kk + (lane & 15);
                int bcol = wn + 16 + (lane >> 4) * 8;
                ldsm_x4_trans(b1[0], b1[1], b1[2], b1[3], bb + (u32)(brow * 72 + bcol) * 2);
            }
            #pragma unroll
            for (int mt = 0; mt < 2; mt++) {
                u32* am = (mt == 0) ? a0 : a1;
                mma16816(acc[mt][0][0], acc[mt][0][1], acc[mt][0][2], acc[mt][0][3],
                         am[0], am[1], am[2], am[3], b0[0], b0[1]);
                mma16816(acc[mt][1][0], acc[mt][1][1], acc[mt][1][2], acc[mt][1][3],
                         am[0], am[1], am[2], am[3], b0[2], b0[3]);
                mma16816(acc[mt][2][0], acc[mt][2][1], acc[mt][2][2], acc[mt][2][3],
                         am[0], am[1], am[2], am[3], b1[0], b1[1]);
                mma16816(acc[mt][3][0], acc[mt][3][1], acc[mt][3][2], acc[mt][3][3],
                         am[0], am[1], am[2], am[3], b1[2], b1[3]);
            }
        }
        __syncthreads();
    }
    #pragma unroll
    for (int mt = 0; mt < 2; mt++) {
        #pragma unroll
        for (int r = 0; r < 2; r++) {
            int row = bm + wm + mt * 16 + r * 8 + (lane >> 2);
            if (row < M) {
                #pragma unroll
                for (int nt = 0; nt < 4; nt++) {
                    __half2 h = __floats2half2_rn(acc[mt][nt][r * 2 + 0], acc[mt][nt][r * 2 + 1]);
                    *(__half2*)(C + (size_t)row * N + bn + wn + nt * 8 + (lane & 3) * 2) = h;
                }
            }
        }
    }
}

// ---------------- coalesced per-(node,head) attention scores ----------------
template <int C>
__global__ void score_kernel(const __half* __restrict__ h, const float* __restrict__ asrc,
                             const float* __restrict__ adst, float* __restrict__ ssrc,
                             float* __restrict__ sdst, int n) {
    int warp = (blockIdx.x * blockDim.x + threadIdx.x) >> 5;
    int lane = threadIdx.x & 31;
    if (warp >= n) return;
    float sp = 0.f, dp = 0.f;
    if (C == 64) {
        uint4 raw = *(const uint4*)(h + (size_t)warp * 256 + lane * 8);
        __half2 hv[4];
        hv[0] = *(__half2*)&raw.x; hv[1] = *(__half2*)&raw.y;
        hv[2] = *(__half2*)&raw.z; hv[3] = *(__half2*)&raw.w;
        #pragma unroll
        for (int j = 0; j < 4; j++) {
            float2 f = __half22float2(hv[j]);
            int c0 = lane * 8 + j * 2;
            sp = fmaf(f.x, __ldg(asrc + c0), sp);
            sp = fmaf(f.y, __ldg(asrc + c0 + 1), sp);
            dp = fmaf(f.x, __ldg(adst + c0), dp);
            dp = fmaf(f.y, __ldg(adst + c0 + 1), dp);
        }
    } else {
        float2 f = __half22float2(__ldg((const __half2*)(h + (size_t)warp * 64) + lane));
        int c0 = lane * 2;
        sp = fmaf(f.x, __ldg(asrc + c0), 0.f);
        sp = fmaf(f.y, __ldg(asrc + c0 + 1), sp);
        dp = fmaf(f.x, __ldg(adst + c0), 0.f);
        dp = fmaf(f.y, __ldg(adst + c0 + 1), dp);
    }
    #pragma unroll
    for (int off = 4; off; off >>= 1) {
        sp += __shfl_down_sync(0xffffffffu, sp, off, 8);
        dp += __shfl_down_sync(0xffffffffu, dp, off, 8);
    }
    if ((lane & 7) == 0) {
        int head = lane >> 3;
        ssrc[warp * 4 + head] = sp;
        sdst[warp * 4 + head] = dp;
    }
}

// ---------------- single-pass softmax + aggregation, warp/node, shuffle-broadcast ----
template <int C, typename OutT>
__global__ void agg_kernel(const int* __restrict__ rowptr, const int* __restrict__ colsrc,
                           const float4* __restrict__ aEc,
                           const float4* __restrict__ ssrc, const float4* __restrict__ sdst,
                           const __half* __restrict__ hh, const float* __restrict__ bias,
                           OutT* __restrict__ outp, int n_nodes) {
    int warp = (blockIdx.x * blockDim.x + threadIdx.x) >> 5;
    int lane = threadIdx.x & 31;
    if (warp >= n_nodes) return;
    int node = warp;
    int base = rowptr[node], end = rowptr[node + 1];
    float4 sd = __ldg(sdst + node);
    int myhead = lane >> 3;  // C==64: lane covers ch lane*8..+7 (one head); C==16: ch 2lane,2lane+1
    float t0 = 0.f, t1 = 0.f, t2 = 0.f, t3 = 0.f;

    float accA[8];
    #pragma unroll
    for (int k = 0; k < 8; k++) accA[k] = 0.f;
    float2 acc16 = make_float2(0.f, 0.f);

    for (int chunk = base; chunk < end; chunk += 32) {
        int j = chunk + lane;
        float e0 = 0.f, e1 = 0.f, e2 = 0.f, e3 = 0.f;
        int s = 0;
        if (j < end) {
            s = colsrc[j];
            float4 ss = __ldg(ssrc + s);
            float4 ae = __ldg(aEc + j);
            float a0 = ss.x + sd.x + ae.x; a0 = a0 >= 0.f ? a0 : 0.2f * a0;
            float a1 = ss.y + sd.y + ae.y; a1 = a1 >= 0.f ? a1 : 0.2f * a1;
            float a2 = ss.z + sd.z + ae.z; a2 = a2 >= 0.f ? a2 : 0.2f * a2;
            float a3 = ss.w + sd.w + ae.w; a3 = a3 >= 0.f ? a3 : 0.2f * a3;
            e0 = __expf(a0); e1 = __expf(a1); e2 = __expf(a2); e3 = __expf(a3);
            t0 += e0; t1 += e1; t2 += e2; t3 += e3;
        }
        int cnt = min(32, end - chunk);
        #pragma unroll 2
        for (int q = 0; q < cnt; q++) {
            int sq   = __shfl_sync(0xffffffffu, s, q);
            float q0 = __shfl_sync(0xffffffffu, e0, q);
            float q1 = __shfl_sync(0xffffffffu, e1, q);
            float q2 = __shfl_sync(0xffffffffu, e2, q);
            float q3 = __shfl_sync(0xffffffffu, e3, q);
            float eh = myhead == 0 ? q0 : myhead == 1 ? q1 : myhead == 2 ? q2 : q3;
            if (C == 64) {
                uint4 raw = __ldg((const uint4*)(hh + (size_t)sq * 256) + lane);
                __half2 hv0 = *(__half2*)&raw.x, hv1 = *(__half2*)&raw.y;
                __half2 hv2 = *(__half2*)&raw.z, hv3 = *(__half2*)&raw.w;
                float2 f0 = __half22float2(hv0), f1 = __half22float2(hv1);
                float2 f2 = __half22float2(hv2), f3 = __half22float2(hv3);
                accA[0] = fmaf(f0.x, eh, accA[0]); accA[1] = fmaf(f0.y, eh, accA[1]);
                accA[2] = fmaf(f1.x, eh, accA[2]); accA[3] = fmaf(f1.y, eh, accA[3]);
                accA[4] = fmaf(f2.x, eh, accA[4]); accA[5] = fmaf(f2.y, eh, accA[5]);
                accA[6] = fmaf(f3.x, eh, accA[6]); accA[7] = fmaf(f3.y, eh, accA[7]);
            } else {
                float2 f = __half22float2(__ldg((const __half2*)(hh + (size_t)sq * 64) + lane));
                acc16.x = fmaf(f.x, eh, acc16.x);
                acc16.y = fmaf(f.y, eh, acc16.y);
            }
        }
    }
    #pragma unroll
    for (int off = 16; off; off >>= 1) {
        t0 += __shfl_xor_sync(0xffffffffu, t0, off);
        t1 += __shfl_xor_sync(0xffffffffu, t1, off);
        t2 += __shfl_xor_sync(0xffffffffu, t2, off);
        t3 += __shfl_xor_sync(0xffffffffu, t3, off);
    }
    float iv = 1.f / ((myhead == 0 ? t0 : myhead == 1 ? t1 : myhead == 2 ? t2 : t3) + 1e-16f);
    if (C == 64) {
        float4 bv0 = *(const float4*)(bias + lane * 8);
        float4 bv1 = *(const float4*)(bias + lane * 8 + 4);
        float o0 = accA[0] * iv + bv0.x, o1 = accA[1] * iv + bv0.y;
        float o2 = accA[2] * iv + bv0.z, o3 = accA[3] * iv + bv0.w;
        float o4 = accA[4] * iv + bv1.x, o5 = accA[5] * iv + bv1.y;
        float o6 = accA[6] * iv + bv1.z, o7 = accA[7] * iv + bv1.w;
        if (sizeof(OutT) == 2) {
            __half* op = (__half*)outp + (size_t)node * 256 + lane * 8;
            __half2 h0 = __floats2half2_rn(o0, o1), h1 = __floats2half2_rn(o2, o3);
            __half2 h2 = __floats2half2_rn(o4, o5), h3 = __floats2half2_rn(o6, o7);
            uint4 pack;
            pack.x = *(u32*)&h0; pack.y = *(u32*)&h1; pack.z = *(u32*)&h2; pack.w = *(u32*)&h3;
            *(uint4*)op = pack;
        } else {
            float* op = (float*)outp + (size_t)node * 256 + lane * 8;
            *(float4*)op = make_float4(o0, o1, o2, o3);
            *(float4*)(op + 4) = make_float4(o4, o5, o6, o7);
        }
    } else {
        float2 bv = *(const float2*)(bias + 2 * lane);
        float ox = acc16.x * iv + bv.x;
        float oy = acc16.y * iv + bv.y;
        if (sizeof(OutT) == 2) {
            *(__half2*)((__half*)outp + (size_t)node * 64 + 2 * lane) = __floats2half2_rn(ox, oy);
        } else {
            *(float2*)((float*)outp + (size_t)node * 64 + 2 * lane) = make_float2(ox, oy);
        }
    }
}

// ---------------- launch ----------------
extern "C" void kernel_launch(void* const* d_in, const int* in_sizes, int n_in,
                              void* d_out, int out_size) {
    const float* x   = (const float*)d_in[0];
    const int*   ei  = (const int*)d_in[1];
    const float* ts  = (const float*)d_in[2];
    const float* tw  = (const float*)d_in[3];
    const float* tb  = (const float*)d_in[4];
    const float* W0  = (const float*)d_in[5];
    const float* as0 = (const float*)d_in[6];
    const float* ad0 = (const float*)d_in[7];
    const float* le0 = (const float*)d_in[8];
    const float* ae0 = (const float*)d_in[9];
    const float* b0  = (const float*)d_in[10];
    const float* W1  = (const float*)d_in[11];
    const float* as1 = (const float*)d_in[12];
    const float* ad1 = (const float*)d_in[13];
    const float* le1 = (const float*)d_in[14];
    const float* ae1 = (const float*)d_in[15];
    const float* b1  = (const float*)d_in[16];

    int n = in_sizes[0] / 128;   // 50000
    int e = in_sizes[2];         // 800000
    int tot = e + n;
    const int* srcp = ei;
    const int* dstp = ei + e;

    void *p_xh, *p_w0h, *p_w1h, *p_hh0, *p_out0h, *p_hh1;
    void *p_aE0, *p_aE1, *p_aE0c, *p_aE1c, *p_ss0, *p_sd0, *p_ss1, *p_sd1;
    void *p_deg, *p_rowptr, *p_cursor, *p_colsrc;
    cudaGetSymbolAddress(&p_xh, g_xh);
    cudaGetSymbolAddress(&p_w0h, g_w0h);
    cudaGetSymbolAddress(&p_w1h, g_w1h);
    cudaGetSymbolAddress(&p_hh0, g_hh0);
    cudaGetSymbolAddress(&p_out0h, g_out0h);
    cudaGetSymbolAddress(&p_hh1, g_hh1);
    cudaGetSymbolAddress(&p_aE0, g_alphaE0);
    cudaGetSymbolAddress(&p_aE1, g_alphaE1);
    cudaGetSymbolAddress(&p_aE0c, g_aE0c);
    cudaGetSymbolAddress(&p_aE1c, g_aE1c);
    cudaGetSymbolAddress(&p_ss0, g_ss0);
    cudaGetSymbolAddress(&p_sd0, g_sd0);
    cudaGetSymbolAddress(&p_ss1, g_ss1);
    cudaGetSymbolAddress(&p_sd1, g_sd1);
    cudaGetSymbolAddress(&p_deg, g_deg);
    cudaGetSymbolAddress(&p_rowptr, g_rowptr);
    cudaGetSymbolAddress(&p_cursor, g_cursor);
    cudaGetSymbolAddress(&p_colsrc, g_colsrc);

    __half* xh     = (__half*)p_xh;
    __half* w0h    = (__half*)p_w0h;
    __half* w1h    = (__half*)p_w1h;
    __half* hh0    = (__half*)p_hh0;
    __half* out0h  = (__half*)p_out0h;
    __half* hh1    = (__half*)p_hh1;
    float4* aE0    = (float4*)p_aE0;
    float4* aE1    = (float4*)p_aE1;
    float4* aE0c   = (float4*)p_aE0c;
    float4* aE1c   = (float4*)p_aE1c;
    float4* ss0    = (float4*)p_ss0;
    float4* sd0    = (float4*)p_sd0;
    float4* ss1    = (float4*)p_ss1;
    float4* sd1    = (float4*)p_sd1;
    int* deg       = (int*)p_deg;
    int* rowptr    = (int*)p_rowptr;
    int* cursor    = (int*)p_cursor;
    int* colsrc    = (int*)p_colsrc;

    // keep hgemm0 as 4th launch (ncu window)
    prep_kernel<<<1, 256>>>(le0, ae0, le1, ae1);
    cvt_kernel<<<(n * 128 / 4 + 255) / 256, 256>>>(x, xh, n * 128 / 4);
    cvt_kernel<<<(128 * 256 / 4 + 255) / 256, 256>>>(W0, w0h, 128 * 256 / 4);
    hgemm_kernel<<<dim3(256 / 64, (n + 127) / 128), 256>>>(xh, w0h, hh0, n, 128, 256);
    cvt_kernel<<<(256 * 64 / 4 + 255) / 256, 256>>>(W1, w1h, 256 * 64 / 4);
    init_kernel<<<(n + 255) / 256, 256>>>(deg, n);
    edge_feat_kernel<<<(e + 511) / 512, 256>>>(ts, tw, tb, dstp, deg, aE0, aE1, e);
    scan_kernel<<<1, 1024>>>(deg, rowptr, cursor, n);
    scatter_kernel<<<(tot + 255) / 256, 256>>>(srcp, dstp, aE0, aE1, cursor, colsrc,
                                               aE0c, aE1c, e, n);
    // layer 0 attention
    score_kernel<64><<<(n * 32 + 255) / 256, 256>>>(hh0, as0, ad0, (float*)ss0, (float*)sd0, n);
    agg_kernel<64, __half><<<(n * 32 + 255) / 256, 256>>>(rowptr, colsrc, aE0c, ss0, sd0,
                                                          hh0, b0, out0h, n);
    // layer 1
    hgemm_kernel<<<dim3(64 / 64, (n + 127) / 128), 256>>>(out0h, w1h, hh1, n, 256, 64);
    score_kernel<16><<<(n * 32 + 255) / 256, 256>>>(hh1, as1, ad1, (float*)ss1, (float*)sd1, n);
    agg_kernel<16, float><<<(n * 32 + 255) / 256, 256>>>(rowptr, colsrc, aE1c, ss1, sd1,
                                                         hh1, b1, (float*)d_out, n);
}

// round 11
// speedup vs baseline: 1.1888x; 1.1888x over previous
#include <cuda_runtime.h>
#include <cuda_fp16.h>
#include <stdint.h>
#include <math.h>

typedef unsigned int u32;

#define NN 50000
#define EE 800000
#define ET (EE + NN)
#define TDIM 64

// ---------------- scratch (static device globals; no allocation) ----------------
__device__ int    g_deg[NN];
__device__ int    g_rowptr[NN + 1];
__device__ int    g_cursor[NN];
__device__ int    g_colsrc[ET];
__device__ float4 g_alphaE0[EE];    // per original edge (pre-CSR)
__device__ float4 g_alphaE1[EE];
__device__ float4 g_aE0c[ET];       // CSR-ordered
__device__ float4 g_aE1c[ET];
__device__ float4 g_aCSR[ET];       // exp(alpha) scratch, CSR order
__device__ __half g_xh[(size_t)NN * 128];
__device__ __half g_w0h[128 * 256];
__device__ __half g_w1h[256 * 64];
__device__ __half g_hh0[(size_t)NN * 256];
__device__ __half g_out0h[(size_t)NN * 256];
__device__ __half g_hh1[(size_t)NN * 64];
__device__ float4 g_ss0[NN], g_sd0[NN], g_ss1[NN], g_sd1[NN];
__device__ float4 g_ve0[TDIM];
__device__ float4 g_ve1[TDIM];
__device__ float4 g_self0, g_self1;

// ---------------- PTX helpers ----------------
__device__ __forceinline__ void ldsm_x4(u32& r0, u32& r1, u32& r2, u32& r3, u32 addr) {
    asm volatile("ldmatrix.sync.aligned.m8n8.x4.shared.b16 {%0,%1,%2,%3}, [%4];"
                 : "=r"(r0), "=r"(r1), "=r"(r2), "=r"(r3) : "r"(addr));
}
__device__ __forceinline__ void ldsm_x4_trans(u32& r0, u32& r1, u32& r2, u32& r3, u32 addr) {
    asm volatile("ldmatrix.sync.aligned.m8n8.x4.trans.shared.b16 {%0,%1,%2,%3}, [%4];"
                 : "=r"(r0), "=r"(r1), "=r"(r2), "=r"(r3) : "r"(addr));
}
__device__ __forceinline__ void mma16816(float& c0, float& c1, float& c2, float& c3,
                                         u32 a0, u32 a1, u32 a2, u32 a3,
                                         u32 b0, u32 b1) {
    asm volatile(
        "mma.sync.aligned.m16n8k16.row.col.f32.f16.f16.f32 "
        "{%0,%1,%2,%3}, {%4,%5,%6,%7}, {%8,%9}, {%0,%1,%2,%3};"
        : "+f"(c0), "+f"(c1), "+f"(c2), "+f"(c3)
        : "r"(a0), "r"(a1), "r"(a2), "r"(a3), "r"(b0), "r"(b1));
}
__device__ __forceinline__ void cp_async16(u32 saddr, const void* gaddr, int src_bytes) {
    asm volatile("cp.async.ca.shared.global [%0], [%1], 16, %2;"
                 :: "r"(saddr), "l"(gaddr), "r"(src_bytes));
}
#define CP_COMMIT()  asm volatile("cp.async.commit_group;")
#define CP_WAIT(n)   asm volatile("cp.async.wait_group %0;" :: "n"(n))

// ---------------- fp32 -> fp16 convert ----------------
__global__ void cvt_kernel(const float* __restrict__ in, __half* __restrict__ out, int n4) {
    int i = blockIdx.x * blockDim.x + threadIdx.x;
    if (i < n4) {
        float4 v = *(const float4*)(in + (size_t)i * 4);
        __half2 a = __floats2half2_rn(v.x, v.y);
        __half2 b = __floats2half2_rn(v.z, v.w);
        *(__half2*)(out + (size_t)i * 4) = a;
        *(__half2*)(out + (size_t)i * 4 + 2) = b;
    }
}

// ---------------- init deg (self loops) ----------------
__global__ void init_kernel(int* deg, int n) {
    int i = blockIdx.x * blockDim.x + threadIdx.x;
    if (i < n) deg[i] = 1;
}

// ---------------- prep ----------------
__global__ void prep_kernel(const float* __restrict__ le0, const float* __restrict__ ae0,
                            const float* __restrict__ le1, const float* __restrict__ ae1) {
    int tid = threadIdx.x;
    int td = tid >> 2, hh = tid & 3;
    float s0 = 0.f;
    for (int c = 0; c < 64; c++) s0 += le0[td * 256 + hh * 64 + c] * ae0[hh * 64 + c];
    ((float*)g_ve0)[td * 4 + hh] = s0;
    float s1 = 0.f;
    for (int c = 0; c < 16; c++) s1 += le1[td * 64 + hh * 16 + c] * ae1[hh * 16 + c];
    ((float*)g_ve1)[td * 4 + hh] = s1;
    __syncthreads();
    if (td == 0) {
        float a = 0.f, b = 0.f;
        for (int t2 = 0; t2 < TDIM; t2++) {
            a += ((float*)g_ve0)[t2 * 4 + hh];
            b += ((float*)g_ve1)[t2 * 4 + hh];
        }
        ((float*)&g_self0)[hh] = a;
        ((float*)&g_self1)[hh] = b;
    }
}

// ---------------- per-edge time features + fused deg count ----------------
__global__ void edge_feat_kernel(const float* __restrict__ ts,
                                 const float* __restrict__ tw,
                                 const float* __restrict__ tb,
                                 const int* __restrict__ dst,
                                 int* __restrict__ deg,
                                 float4* __restrict__ aE0, float4* __restrict__ aE1,
                                 int e) {
    __shared__ float2 swb[TDIM];
    __shared__ float4 sv0[TDIM];
    __shared__ float4 sv1[TDIM];
    int tid = threadIdx.x;
    if (tid < TDIM) {
        swb[tid] = make_float2(tw[tid], tb[tid]);
        sv0[tid] = g_ve0[tid];
        sv1[tid] = g_ve1[tid];
    }
    __syncthreads();
    int iA = blockIdx.x * 512 + tid;
    int iB = iA + 256;
    float tA = (iA < e) ? ts[iA] : 0.f;
    float tB = (iB < e) ? ts[iB] : 0.f;
    if (iA < e) atomicAdd(&deg[dst[iA]], 1);
    if (iB < e) atomicAdd(&deg[dst[iB]], 1);
    float4 A0 = make_float4(0, 0, 0, 0), A1 = A0, B0 = A0, B1 = A0;
    #pragma unroll 8
    for (int td = 0; td < TDIM; td++) {
        float2 wb = swb[td];
        float4 v0 = sv0[td];
        float4 v1 = sv1[td];
        float aA = fabsf(__cosf(fmaf(tA, wb.x, wb.y)));
        float aB = fabsf(__cosf(fmaf(tB, wb.x, wb.y)));
        A0.x = fmaf(aA, v0.x, A0.x); A0.y = fmaf(aA, v0.y, A0.y);
        A0.z = fmaf(aA, v0.z, A0.z); A0.w = fmaf(aA, v0.w, A0.w);
        A1.x = fmaf(aA, v1.x, A1.x); A1.y = fmaf(aA, v1.y, A1.y);
        A1.z = fmaf(aA, v1.z, A1.z); A1.w = fmaf(aA, v1.w, A1.w);
        B0.x = fmaf(aB, v0.x, B0.x); B0.y = fmaf(aB, v0.y, B0.y);
        B0.z = fmaf(aB, v0.z, B0.z); B0.w = fmaf(aB, v0.w, B0.w);
        B1.x = fmaf(aB, v1.x, B1.x); B1.y = fmaf(aB, v1.y, B1.y);
        B1.z = fmaf(aB, v1.z, B1.z); B1.w = fmaf(aB, v1.w, B1.w);
    }
    if (iA < e) { aE0[iA] = A0; aE1[iA] = A1; }
    if (iB < e) { aE0[iB] = B0; aE1[iB] = B1; }
}

// ---------------- CSR scan ----------------
__global__ void scan_kernel(const int* __restrict__ deg, int* __restrict__ rowptr,
                            int* __restrict__ cursor, int n) {
    const int T = 1024;
    __shared__ int wsum[32];
    __shared__ int stotal;
    int t = threadIdx.x;
    int CH = (n + T - 1) / T;
    int s0 = t * CH, s1 = min(s0 + CH, n);
    int sum = 0;
    for (int i = s0; i < s1; i++) sum += deg[i];
    int lane = t & 31, wid = t >> 5;
    int v = sum;
    #pragma unroll
    for (int off = 1; off < 32; off <<= 1) {
        int x = __shfl_up_sync(0xffffffffu, v, off);
        if (lane >= off) v += x;
    }
    if (lane == 31) wsum[wid] = v;
    __syncthreads();
    if (wid == 0) {
        int w = wsum[lane];
        #pragma unroll
        for (int off = 1; off < 32; off <<= 1) {
            int x = __shfl_up_sync(0xffffffffu, w, off);
            if (lane >= off) w += x;
        }
        wsum[lane] = w;
        if (lane == 31) stotal = w;
    }
    __syncthreads();
    int excl = v - sum + (wid ? wsum[wid - 1] : 0);
    int run = excl;
    for (int i = s0; i < s1; i++) {
        rowptr[i] = run;
        cursor[i] = run;
        run += deg[i];
    }
    if (t == T - 1) rowptr[n] = stotal;
}

// ---------------- scatter: build colsrc + permute aE into CSR order ----------------
__global__ void scatter_kernel(const int* __restrict__ src, const int* __restrict__ dst,
                               const float4* __restrict__ aE0, const float4* __restrict__ aE1,
                               int* cursor, int* colsrc,
                               float4* __restrict__ aE0c, float4* __restrict__ aE1c,
                               int e, int n) {
    int i = blockIdx.x * blockDim.x + threadIdx.x;
    int tot = e + n;
    if (i >= tot) return;
    if (i < e) {
        int d = dst[i];
        int p = atomicAdd(&cursor[d], 1);
        colsrc[p] = src[i];
        aE0c[p] = aE0[i];
        aE1c[p] = aE1[i];
    } else {
        int node = i - e;
        int p = atomicAdd(&cursor[node], 1);
        colsrc[p] = node;
        aE0c[p] = g_self0;
        aE1c[p] = g_self1;
    }
}

// ---------------- fp16 tensor-core GEMM with cp.async double buffering ----------------
__global__ void hgemm_kernel(const __half* __restrict__ A, const __half* __restrict__ B,
                             __half* __restrict__ C, int M, int K, int N) {
    __shared__ __half As[2][128][40];
    __shared__ __half Bs[2][32][72];
    const int AS_B = 128 * 40 * 2;
    const int BS_B = 32 * 72 * 2;
    int bm = blockIdx.y * 128, bn = blockIdx.x * 64;
    int tid = threadIdx.x;
    int wid = tid >> 5, lane = tid & 31;
    int wm = (wid >> 1) * 32, wn = (wid & 1) * 32;
    float acc[2][4][4];
    #pragma unroll
    for (int mt = 0; mt < 2; mt++)
        #pragma unroll
        for (int nt = 0; nt < 4; nt++)
            #pragma unroll
            for (int r = 0; r < 4; r++) acc[mt][nt][r] = 0.f;

    u32 as_base = (u32)__cvta_generic_to_shared(&As[0][0][0]);
    u32 bs_base = (u32)__cvta_generic_to_shared(&Bs[0][0][0]);

    int a_row0 = tid >> 2, a_c8 = (tid & 3) * 8;
    int b_row = tid >> 3, b_c8 = (tid & 7) * 8;

    {
        #pragma unroll
        for (int it = 0; it < 2; it++) {
            int row = a_row0 + it * 64;
            int gm = bm + row;
            int ok = (gm < M);
            const void* g = A + (size_t)(ok ? gm : 0) * K + a_c8;
            cp_async16(as_base + (u32)(row * 40 + a_c8) * 2, g, ok ? 16 : 0);
        }
        cp_async16(bs_base + (u32)(b_row * 72 + b_c8) * 2,
                   B + (size_t)b_row * N + bn + b_c8, 16);
        CP_COMMIT();
    }

    int KT = K >> 5;
    for (int kt = 0; kt < KT; kt++) {
        if (kt + 1 < KT) {
            int st = (kt + 1) & 1;
            int k0 = (kt + 1) * 32;
            #pragma unroll
            for (int it = 0; it < 2; it++) {
                int row = a_row0 + it * 64;
                int gm = bm + row;
                int ok = (gm < M);
                const void* g = A + (size_t)(ok ? gm : 0) * K + k0 + a_c8;
                cp_async16(as_base + (u32)(st * AS_B) + (u32)(row * 40 + a_c8) * 2, g, ok ? 16 : 0);
            }
            cp_async16(bs_base + (u32)(st * BS_B) + (u32)(b_row * 72 + b_c8) * 2,
                       B + (size_t)(k0 + b_row) * N + bn + b_c8, 16);
            CP_COMMIT();
            CP_WAIT(1);
        } else {
            CP_WAIT(0);
        }
        __syncthreads();
        u32 ab = as_base + (u32)((kt & 1) * AS_B);
        u32 bb = bs_base + (u32)((kt & 1) * BS_B);
        #pragma unroll
        for (int kk = 0; kk < 32; kk += 16) {
            u32 a0[4], a1[4], b0[4], b1[4];
            {
                int arow = wm + (lane & 15);
                int acol = kk + (lane >> 4) * 8;
                ldsm_x4(a0[0], a0[1], a0[2], a0[3], ab + (u32)(arow * 40 + acol) * 2);
            }
            {
                int arow = wm + 16 + (lane & 15);
                int acol = kk + (lane >> 4) * 8;
                ldsm_x4(a1[0], a1[1], a1[2], a1[3], ab + (u32)(arow * 40 + acol) * 2);
            }
            {
                int brow = kk + (lane & 15);
                int bcol = wn + (lane >> 4) * 8;
                ldsm_x4_trans(b0[0], b0[1], b0[2], b0[3], bb + (u32)(brow * 72 + bcol) * 2);
            }
            {
                int brow = kk + (lane & 15);
                int bcol = wn + 16 + (lane >> 4) * 8;
                ldsm_x4_trans(b1[0], b1[1], b1[2], b1[3], bb + (u32)(brow * 72 + bcol) * 2);
            }
            #pragma unroll
            for (int mt = 0; mt < 2; mt++) {
                u32* am = (mt == 0) ? a0 : a1;
                mma16816(acc[mt][0][0], acc[mt][0][1], acc[mt][0][2], acc[mt][0][3],
                         am[0], am[1], am[2], am[3], b0[0], b0[1]);
                mma16816(acc[mt][1][0], acc[mt][1][1], acc[mt][1][2], acc[mt][1][3],
                         am[0], am[1], am[2], am[3], b0[2], b0[3]);
                mma16816(acc[mt][2][0], acc[mt][2][1], acc[mt][2][2], acc[mt][2][3],
                         am[0], am[1], am[2], am[3], b1[0], b1[1]);
                mma16816(acc[mt][3][0], acc[mt][3][1], acc[mt][3][2], acc[mt][3][3],
                         am[0], am[1], am[2], am[3], b1[2], b1[3]);
            }
        }
        __syncthreads();
    }
    #pragma unroll
    for (int mt = 0; mt < 2; mt++) {
        #pragma unroll
        for (int r = 0; r < 2; r++) {
            int row = bm + wm + mt * 16 + r * 8 + (lane >> 2);
            if (row < M) {
                #pragma unroll
                for (int nt = 0; nt < 4; nt++) {
                    __half2 h = __floats2half2_rn(acc[mt][nt][r * 2 + 0], acc[mt][nt][r * 2 + 1]);
                    *(__half2*)(C + (size_t)row * N + bn + wn + nt * 8 + (lane & 3) * 2) = h;
                }
            }
        }
    }
}

// ---------------- coalesced per-(node,head) attention scores ----------------
template <int C>
__global__ void score_kernel(const __half* __restrict__ h, const float* __restrict__ asrc,
                             const float* __restrict__ adst, float* __restrict__ ssrc,
                             float* __restrict__ sdst, int n) {
    int warp = (blockIdx.x * blockDim.x + threadIdx.x) >> 5;
    int lane = threadIdx.x & 31;
    if (warp >= n) return;
    float sp = 0.f, dp = 0.f;
    if (C == 64) {
        uint4 raw = *(const uint4*)(h + (size_t)warp * 256 + lane * 8);
        __half2 hv[4];
        hv[0] = *(__half2*)&raw.x; hv[1] = *(__half2*)&raw.y;
        hv[2] = *(__half2*)&raw.z; hv[3] = *(__half2*)&raw.w;
        #pragma unroll
        for (int j = 0; j < 4; j++) {
            float2 f = __half22float2(hv[j]);
            int c0 = lane * 8 + j * 2;
            sp = fmaf(f.x, __ldg(asrc + c0), sp);
            sp = fmaf(f.y, __ldg(asrc + c0 + 1), sp);
            dp = fmaf(f.x, __ldg(adst + c0), dp);
            dp = fmaf(f.y, __ldg(adst + c0 + 1), dp);
        }
    } else {
        float2 f = __half22float2(__ldg((const __half2*)(h + (size_t)warp * 64) + lane));
        int c0 = lane * 2;
        sp = fmaf(f.x, __ldg(asrc + c0), 0.f);
        sp = fmaf(f.y, __ldg(asrc + c0 + 1), sp);
        dp = fmaf(f.x, __ldg(adst + c0), 0.f);
        dp = fmaf(f.y, __ldg(adst + c0 + 1), dp);
    }
    #pragma unroll
    for (int off = 4; off; off >>= 1) {
        sp += __shfl_down_sync(0xffffffffu, sp, off, 8);
        dp += __shfl_down_sync(0xffffffffu, dp, off, 8);
    }
    if ((lane & 7) == 0) {
        int head = lane >> 3;
        ssrc[warp * 4 + head] = sp;
        sdst[warp * 4 + head] = dp;
    }
}

// ---------------- 2-pass softmax + aggregation, warp/node ----------------
// pass2: per-lane head-constant weight, one LDG.128 per edge (C=64), 2-edge unroll.
template <int C, typename OutT>
__global__ void agg_kernel(const int* __restrict__ rowptr, const int* __restrict__ colsrc,
                           const float4* __restrict__ aEc,
                           const float4* __restrict__ ssrc, const float4* __restrict__ sdst,
                           const __half* __restrict__ hh, const float* __restrict__ bias,
                           float4* __restrict__ aCSR, OutT* __restrict__ outp, int n_nodes) {
    int warp = (blockIdx.x * blockDim.x + threadIdx.x) >> 5;
    int lane = threadIdx.x & 31;
    if (warp >= n_nodes) return;
    int node = warp;
    int base = rowptr[node], end = rowptr[node + 1];
    float4 sd = __ldg(sdst + node);
    int myhead = lane >> 3;
    // pass1: alpha -> leaky -> exp -> store aCSR + sums
    float t0 = 0.f, t1 = 0.f, t2 = 0.f, t3 = 0.f;
    for (int j = base + lane; j < end; j += 32) {
        int s = colsrc[j];
        float4 ss = __ldg(ssrc + s);
        float4 ae = __ldg(aEc + j);
        float a0 = ss.x + sd.x + ae.x; a0 = a0 >= 0.f ? a0 : 0.2f * a0;
        float a1 = ss.y + sd.y + ae.y; a1 = a1 >= 0.f ? a1 : 0.2f * a1;
        float a2 = ss.z + sd.z + ae.z; a2 = a2 >= 0.f ? a2 : 0.2f * a2;
        float a3 = ss.w + sd.w + ae.w; a3 = a3 >= 0.f ? a3 : 0.2f * a3;
        float e0 = __expf(a0), e1 = __expf(a1);
        float e2 = __expf(a2), e3 = __expf(a3);
        aCSR[j] = make_float4(e0, e1, e2, e3);
        t0 += e0; t1 += e1; t2 += e2; t3 += e3;
    }
    #pragma unroll
    for (int off = 16; off; off >>= 1) {
        t0 += __shfl_xor_sync(0xffffffffu, t0, off);
        t1 += __shfl_xor_sync(0xffffffffu, t1, off);
        t2 += __shfl_xor_sync(0xffffffffu, t2, off);
        t3 += __shfl_xor_sync(0xffffffffu, t3, off);
    }
    float iv = 1.f / ((myhead == 0 ? t0 : myhead == 1 ? t1 : myhead == 2 ? t2 : t3) + 1e-16f);
    __syncwarp();
    const float* aS = (const float*)aCSR;   // scalar view: weight for (edge j, head) at j*4+head
    if (C == 64) {
        float accA[8];
        #pragma unroll
        for (int k = 0; k < 8; k++) accA[k] = 0.f;
        int j = base;
        for (; j + 2 <= end; j += 2) {
            int sA = colsrc[j], sB = colsrc[j + 1];
            float eA = __ldg(aS + j * 4 + myhead);
            float eB = __ldg(aS + (j + 1) * 4 + myhead);
            uint4 rA = __ldg((const uint4*)(hh + (size_t)sA * 256) + lane);
            uint4 rB = __ldg((const uint4*)(hh + (size_t)sB * 256) + lane);
            float2 fA0 = __half22float2(*(__half2*)&rA.x), fA1 = __half22float2(*(__half2*)&rA.y);
            float2 fA2 = __half22float2(*(__half2*)&rA.z), fA3 = __half22float2(*(__half2*)&rA.w);
            float2 fB0 = __half22float2(*(__half2*)&rB.x), fB1 = __half22float2(*(__half2*)&rB.y);
            float2 fB2 = __half22float2(*(__half2*)&rB.z), fB3 = __half22float2(*(__half2*)&rB.w);
            accA[0] = fmaf(fA0.x, eA, accA[0]); accA[1] = fmaf(fA0.y, eA, accA[1]);
            accA[2] = fmaf(fA1.x, eA, accA[2]); accA[3] = fmaf(fA1.y, eA, accA[3]);
            accA[4] = fmaf(fA2.x, eA, accA[4]); accA[5] = fmaf(fA2.y, eA, accA[5]);
            accA[6] = fmaf(fA3.x, eA, accA[6]); accA[7] = fmaf(fA3.y, eA, accA[7]);
            accA[0] = fmaf(fB0.x, eB, accA[0]); accA[1] = fmaf(fB0.y, eB, accA[1]);
            accA[2] = fmaf(fB1.x, eB, accA[2]); accA[3] = fmaf(fB1.y, eB, accA[3]);
            accA[4] = fmaf(fB2.x, eB, accA[4]); accA[5] = fmaf(fB2.y, eB, accA[5]);
            accA[6] = fmaf(fB3.x, eB, accA[6]); accA[7] = fmaf(fB3.y, eB, accA[7]);
        }
        if (j < end) {
            int s = colsrc[j];
            float ew = __ldg(aS + j * 4 + myhead);
            uint4 r = __ldg((const uint4*)(hh + (size_t)s * 256) + lane);
            float2 f0 = __half22float2(*(__half2*)&r.x), f1 = __half22float2(*(__half2*)&r.y);
            float2 f2 = __half22float2(*(__half2*)&r.z), f3 = __half22float2(*(__half2*)&r.w);
            accA[0] = fmaf(f0.x, ew, accA[0]); accA[1] = fmaf(f0.y, ew, accA[1]);
            accA[2] = fmaf(f1.x, ew, accA[2]); accA[3] = fmaf(f1.y, ew, accA[3]);
            accA[4] = fmaf(f2.x, ew, accA[4]); accA[5] = fmaf(f2.y, ew, accA[5]);
            accA[6] = fmaf(f3.x, ew, accA[6]); accA[7] = fmaf(f3.y, ew, accA[7]);
        }
        float4 bv0 = *(const float4*)(bias + lane * 8);
        float4 bv1 = *(const float4*)(bias + lane * 8 + 4);
        float o0 = accA[0] * iv + bv0.x, o1 = accA[1] * iv + bv0.y;
        float o2 = accA[2] * iv + bv0.z, o3 = accA[3] * iv + bv0.w;
        float o4 = accA[4] * iv + bv1.x, o5 = accA[5] * iv + bv1.y;
        float o6 = accA[6] * iv + bv1.z, o7 = accA[7] * iv + bv1.w;
        if (sizeof(OutT) == 2) {
            __half2 h0 = __floats2half2_rn(o0, o1), h1 = __floats2half2_rn(o2, o3);
            __half2 h2 = __floats2half2_rn(o4, o5), h3 = __floats2half2_rn(o6, o7);
            uint4 pack;
            pack.x = *(u32*)&h0; pack.y = *(u32*)&h1; pack.z = *(u32*)&h2; pack.w = *(u32*)&h3;
            *(uint4*)((__half*)outp + (size_t)node * 256 + lane * 8) = pack;
        } else {
            float* op = (float*)outp + (size_t)node * 256 + lane * 8;
            *(float4*)op = make_float4(o0, o1, o2, o3);
            *(float4*)(op + 4) = make_float4(o4, o5, o6, o7);
        }
    } else {  // C == 16, HC = 64: lane covers channels 2*lane, 2*lane+1 (head = lane>>3)
        float2 acc = make_float2(0.f, 0.f);
        int j = base;
        for (; j + 2 <= end; j += 2) {
            int sA = colsrc[j], sB = colsrc[j + 1];
            float eA = __ldg(aS + j * 4 + myhead);
            float eB = __ldg(aS + (j + 1) * 4 + myhead);
            float2 fA = __half22float2(__ldg((const __half2*)(hh + (size_t)sA * 64) + lane));
            float2 fB = __half22float2(__ldg((const __half2*)(hh + (size_t)sB * 64) + lane));
            acc.x = fmaf(fA.x, eA, acc.x);
            acc.y = fmaf(fA.y, eA, acc.y);
            acc.x = fmaf(fB.x, eB, acc.x);
            acc.y = fmaf(fB.y, eB, acc.y);
        }
        if (j < end) {
            int s = colsrc[j];
            float ew = __ldg(aS + j * 4 + myhead);
            float2 f = __half22float2(__ldg((const __half2*)(hh + (size_t)s * 64) + lane));
            acc.x = fmaf(f.x, ew, acc.x);
            acc.y = fmaf(f.y, ew, acc.y);
        }
        float2 bv = *(const float2*)(bias + 2 * lane);
        float ox = acc.x * iv + bv.x;
        float oy = acc.y * iv + bv.y;
        if (sizeof(OutT) == 2) {
            *(__half2*)((__half*)outp + (size_t)node * 64 + 2 * lane) = __floats2half2_rn(ox, oy);
        } else {
            *(float2*)((float*)outp + (size_t)node * 64 + 2 * lane) = make_float2(ox, oy);
        }
    }
}

// ---------------- launch ----------------
extern "C" void kernel_launch(void* const* d_in, const int* in_sizes, int n_in,
                              void* d_out, int out_size) {
    const float* x   = (const float*)d_in[0];
    const int*   ei  = (const int*)d_in[1];
    const float* ts  = (const float*)d_in[2];
    const float* tw  = (const float*)d_in[3];
    const float* tb  = (const float*)d_in[4];
    const float* W0  = (const float*)d_in[5];
    const float* as0 = (const float*)d_in[6];
    const float* ad0 = (const float*)d_in[7];
    const float* le0 = (const float*)d_in[8];
    const float* ae0 = (const float*)d_in[9];
    const float* b0  = (const float*)d_in[10];
    const float* W1  = (const float*)d_in[11];
    const float* as1 = (const float*)d_in[12];
    const float* ad1 = (const float*)d_in[13];
    const float* le1 = (const float*)d_in[14];
    const float* ae1 = (const float*)d_in[15];
    const float* b1  = (const float*)d_in[16];

    int n = in_sizes[0] / 128;   // 50000
    int e = in_sizes[2];         // 800000
    int tot = e + n;
    const int* srcp = ei;
    const int* dstp = ei + e;

    void *p_xh, *p_w0h, *p_w1h, *p_hh0, *p_out0h, *p_hh1;
    void *p_aE0, *p_aE1, *p_aE0c, *p_aE1c, *p_aCSR, *p_ss0, *p_sd0, *p_ss1, *p_sd1;
    void *p_deg, *p_rowptr, *p_cursor, *p_colsrc;
    cudaGetSymbolAddress(&p_xh, g_xh);
    cudaGetSymbolAddress(&p_w0h, g_w0h);
    cudaGetSymbolAddress(&p_w1h, g_w1h);
    cudaGetSymbolAddress(&p_hh0, g_hh0);
    cudaGetSymbolAddress(&p_out0h, g_out0h);
    cudaGetSymbolAddress(&p_hh1, g_hh1);
    cudaGetSymbolAddress(&p_aE0, g_alphaE0);
    cudaGetSymbolAddress(&p_aE1, g_alphaE1);
    cudaGetSymbolAddress(&p_aE0c, g_aE0c);
    cudaGetSymbolAddress(&p_aE1c, g_aE1c);
    cudaGetSymbolAddress(&p_aCSR, g_aCSR);
    cudaGetSymbolAddress(&p_ss0, g_ss0);
    cudaGetSymbolAddress(&p_sd0, g_sd0);
    cudaGetSymbolAddress(&p_ss1, g_ss1);
    cudaGetSymbolAddress(&p_sd1, g_sd1);
    cudaGetSymbolAddress(&p_deg, g_deg);
    cudaGetSymbolAddress(&p_rowptr, g_rowptr);
    cudaGetSymbolAddress(&p_cursor, g_cursor);
    cudaGetSymbolAddress(&p_colsrc, g_colsrc);

    __half* xh     = (__half*)p_xh;
    __half* w0h    = (__half*)p_w0h;
    __half* w1h    = (__half*)p_w1h;
    __half* hh0    = (__half*)p_hh0;
    __half* out0h  = (__half*)p_out0h;
    __half* hh1    = (__half*)p_hh1;
    float4* aE0    = (float4*)p_aE0;
    float4* aE1    = (float4*)p_aE1;
    float4* aE0c   = (float4*)p_aE0c;
    float4* aE1c   = (float4*)p_aE1c;
    float4* aCSR   = (float4*)p_aCSR;
    float4* ss0    = (float4*)p_ss0;
    float4* sd0    = (float4*)p_sd0;
    float4* ss1    = (float4*)p_ss1;
    float4* sd1    = (float4*)p_sd1;
    int* deg       = (int*)p_deg;
    int* rowptr    = (int*)p_rowptr;
    int* cursor    = (int*)p_cursor;
    int* colsrc    = (int*)p_colsrc;

    // keep hgemm0 as 4th launch (ncu window)
    prep_kernel<<<1, 256>>>(le0, ae0, le1, ae1);
    cvt_kernel<<<(n * 128 / 4 + 255) / 256, 256>>>(x, xh, n * 128 / 4);
    cvt_kernel<<<(128 * 256 / 4 + 255) / 256, 256>>>(W0, w0h, 128 * 256 / 4);
    hgemm_kernel<<<dim3(256 / 64, (n + 127) / 128), 256>>>(xh, w0h, hh0, n, 128, 256);
    cvt_kernel<<<(256 * 64 / 4 + 255) / 256, 256>>>(W1, w1h, 256 * 64 / 4);
    init_kernel<<<(n + 255) / 256, 256>>>(deg, n);
    edge_feat_kernel<<<(e + 511) / 512, 256>>>(ts, tw, tb, dstp, deg, aE0, aE1, e);
    scan_kernel<<<1, 1024>>>(deg, rowptr, cursor, n);
    scatter_kernel<<<(tot + 255) / 256, 256>>>(srcp, dstp, aE0, aE1, cursor, colsrc,
                                               aE0c, aE1c, e, n);
    // layer 0 attention
    score_kernel<64><<<(n * 32 + 255) / 256, 256>>>(hh0, as0, ad0, (float*)ss0, (float*)sd0, n);
    agg_kernel<64, __half><<<(n * 32 + 255) / 256, 256>>>(rowptr, colsrc, aE0c, ss0, sd0,
                                                          hh0, b0, aCSR, out0h, n);
    // layer 1
    hgemm_kernel<<<dim3(64 / 64, (n + 127) / 128), 256>>>(out0h, w1h, hh1, n, 256, 64);
    score_kernel<16><<<(n * 32 + 255) / 256, 256>>>(hh1, as1, ad1, (float*)ss1, (float*)sd1, n);
    agg_kernel<16, float><<<(n * 32 + 255) / 256, 256>>>(rowptr, colsrc, aE1c, ss1, sd1,
                                                         hh1, b1, aCSR, (float*)d_out, n);
}

// round 12
// speedup vs baseline: 1.4239x; 1.1977x over previous
#include <cuda_runtime.h>
#include <cuda_fp16.h>
#include <stdint.h>
#include <math.h>

typedef unsigned int u32;
typedef unsigned long long u64;

#define NN 50000
#define EE 800000
#define ET (EE + NN)
#define TDIM 64

// ---------------- scratch (static device globals; no allocation) ----------------
__device__ int    g_deg[NN];
__device__ int    g_rowptr[NN + 1];
__device__ int    g_cursor[NN];
__device__ int    g_colsrc[ET];
__device__ float4 g_alphaE0[EE];
__device__ float4 g_alphaE1[EE];
__device__ float4 g_aE0c[ET];
__device__ float4 g_aE1c[ET];
__device__ float4 g_aCSR[ET];
__device__ __half g_xh[(size_t)NN * 128];
__device__ __half g_w0h[128 * 256];
__device__ __half g_w1h[256 * 64];
__device__ __half g_hh0[(size_t)NN * 256];
__device__ __half g_out0h[(size_t)NN * 256];
__device__ __half g_hh1[(size_t)NN * 64];
__device__ float4 g_ss0[NN], g_sd0[NN], g_ss1[NN], g_sd1[NN];
__device__ float4 g_ve0[TDIM];
__device__ float4 g_ve1[TDIM];
__device__ float4 g_self0, g_self1;

// ---------------- PTX helpers ----------------
__device__ __forceinline__ void ldsm_x4(u32& r0, u32& r1, u32& r2, u32& r3, u32 addr) {
    asm volatile("ldmatrix.sync.aligned.m8n8.x4.shared.b16 {%0,%1,%2,%3}, [%4];"
                 : "=r"(r0), "=r"(r1), "=r"(r2), "=r"(r3) : "r"(addr));
}
__device__ __forceinline__ void ldsm_x4_trans(u32& r0, u32& r1, u32& r2, u32& r3, u32 addr) {
    asm volatile("ldmatrix.sync.aligned.m8n8.x4.trans.shared.b16 {%0,%1,%2,%3}, [%4];"
                 : "=r"(r0), "=r"(r1), "=r"(r2), "=r"(r3) : "r"(addr));
}
__device__ __forceinline__ void mma16816(float& c0, float& c1, float& c2, float& c3,
                                         u32 a0, u32 a1, u32 a2, u32 a3,
                                         u32 b0, u32 b1) {
    asm volatile(
        "mma.sync.aligned.m16n8k16.row.col.f32.f16.f16.f32 "
        "{%0,%1,%2,%3}, {%4,%5,%6,%7}, {%8,%9}, {%0,%1,%2,%3};"
        : "+f"(c0), "+f"(c1), "+f"(c2), "+f"(c3)
        : "r"(a0), "r"(a1), "r"(a2), "r"(a3), "r"(b0), "r"(b1));
}
__device__ __forceinline__ void cp_async16(u32 saddr, const void* gaddr, int src_bytes) {
    asm volatile("cp.async.ca.shared.global [%0], [%1], 16, %2;"
                 :: "r"(saddr), "l"(gaddr), "r"(src_bytes));
}
#define CP_COMMIT()  asm volatile("cp.async.commit_group;")
#define CP_WAIT(n)   asm volatile("cp.async.wait_group %0;" :: "n"(n))

// packed fp32x2 FMA (PTX ISA 8.6, sm_100+): d = a*b + d on two lanes
__device__ __forceinline__ void ffma2(u64& d, u64 a, u64 b) {
    asm("fma.rn.f32x2 %0, %1, %2, %0;" : "+l"(d) : "l"(a), "l"(b));
}
__device__ __forceinline__ u64 pack2(float lo, float hi) {
    u64 r;
    asm("mov.b64 %0, {%1, %2};" : "=l"(r) : "f"(lo), "f"(hi));
    return r;
}
__device__ __forceinline__ void unpack2(float& lo, float& hi, u64 v) {
    asm("mov.b64 {%0, %1}, %2;" : "=f"(lo), "=f"(hi) : "l"(v));
}

// ---------------- setup: prep (block 0) + deg init + 3x fp32->fp16 cvt ----------------
__global__ void setup_kernel(const float* __restrict__ le0, const float* __restrict__ ae0,
                             const float* __restrict__ le1, const float* __restrict__ ae1,
                             const float* __restrict__ x, const float* __restrict__ W0,
                             const float* __restrict__ W1,
                             int* __restrict__ deg,
                             __half* __restrict__ xh, __half* __restrict__ w0h,
                             __half* __restrict__ w1h, int n) {
    int tid = threadIdx.x;
    if (blockIdx.x == 0) {
        // prep: ve[td][h] = sum_c lin_edge[td, h*C+c] * att_edge[h,c]; self = col sums
        int td = tid >> 2, hh = tid & 3;
        float s0 = 0.f;
        for (int c = 0; c < 64; c++) s0 += le0[td * 256 + hh * 64 + c] * ae0[hh * 64 + c];
        ((float*)g_ve0)[td * 4 + hh] = s0;
        float s1 = 0.f;
        for (int c = 0; c < 16; c++) s1 += le1[td * 64 + hh * 16 + c] * ae1[hh * 16 + c];
        ((float*)g_ve1)[td * 4 + hh] = s1;
        __syncthreads();
        if (td == 0) {
            float a = 0.f, b = 0.f;
            for (int t2 = 0; t2 < TDIM; t2++) {
                a += ((float*)g_ve0)[t2 * 4 + hh];
                b += ((float*)g_ve1)[t2 * 4 + hh];
            }
            ((float*)&g_self0)[hh] = a;
            ((float*)&g_self1)[hh] = b;
        }
        return;
    }
    int gid = (blockIdx.x - 1) * 256 + tid;
    int stride = (gridDim.x - 1) * 256;
    // deg init
    for (int i = gid; i < n; i += stride) deg[i] = 1;
    // cvt x (n*32 float4s), W0 (8192), W1 (4096)
    int nx4 = n * 32;
    for (int i = gid; i < nx4; i += stride) {
        float4 v = *(const float4*)(x + (size_t)i * 4);
        *(__half2*)(xh + (size_t)i * 4) = __floats2half2_rn(v.x, v.y);
        *(__half2*)(xh + (size_t)i * 4 + 2) = __floats2half2_rn(v.z, v.w);
    }
    for (int i = gid; i < 8192; i += stride) {
        float4 v = *(const float4*)(W0 + (size_t)i * 4);
        *(__half2*)(w0h + (size_t)i * 4) = __floats2half2_rn(v.x, v.y);
        *(__half2*)(w0h + (size_t)i * 4 + 2) = __floats2half2_rn(v.z, v.w);
    }
    for (int i = gid; i < 4096; i += stride) {
        float4 v = *(const float4*)(W1 + (size_t)i * 4);
        *(__half2*)(w1h + (size_t)i * 4) = __floats2half2_rn(v.x, v.y);
        *(__half2*)(w1h + (size_t)i * 4 + 2) = __floats2half2_rn(v.z, v.w);
    }
}

// ---------------- per-edge time features + fused deg count (f32x2 packed dots) --------
__global__ void edge_feat_kernel(const float* __restrict__ ts,
                                 const float* __restrict__ tw,
                                 const float* __restrict__ tb,
                                 const int* __restrict__ dst,
                                 int* __restrict__ deg,
                                 float4* __restrict__ aE0, float4* __restrict__ aE1,
                                 int e) {
    __shared__ float2 swb[TDIM];
    __shared__ u64 pv0a[TDIM], pv0b[TDIM], pv1a[TDIM], pv1b[TDIM];
    int tid = threadIdx.x;
    if (tid < TDIM) {
        swb[tid] = make_float2(tw[tid], tb[tid]);
        float4 v0 = g_ve0[tid];
        float4 v1 = g_ve1[tid];
        pv0a[tid] = pack2(v0.x, v0.y);
        pv0b[tid] = pack2(v0.z, v0.w);
        pv1a[tid] = pack2(v1.x, v1.y);
        pv1b[tid] = pack2(v1.z, v1.w);
    }
    __syncthreads();
    int iA = blockIdx.x * 512 + tid;
    int iB = iA + 256;
    float tA = (iA < e) ? ts[iA] : 0.f;
    float tB = (iB < e) ? ts[iB] : 0.f;
    if (iA < e) atomicAdd(&deg[dst[iA]], 1);
    if (iB < e) atomicAdd(&deg[dst[iB]], 1);
    u64 A0xy = 0, A0zw = 0, A1xy = 0, A1zw = 0;
    u64 B0xy = 0, B0zw = 0, B1xy = 0, B1zw = 0;
    #pragma unroll 8
    for (int td = 0; td < TDIM; td++) {
        float2 wb = swb[td];
        float aA = fabsf(__cosf(fmaf(tA, wb.x, wb.y)));
        float aB = fabsf(__cosf(fmaf(tB, wb.x, wb.y)));
        u64 ccA = pack2(aA, aA);
        u64 ccB = pack2(aB, aB);
        u64 v0a = pv0a[td], v0b = pv0b[td], v1a = pv1a[td], v1b = pv1b[td];
        ffma2(A0xy, ccA, v0a); ffma2(A0zw, ccA, v0b);
        ffma2(A1xy, ccA, v1a); ffma2(A1zw, ccA, v1b);
        ffma2(B0xy, ccB, v0a); ffma2(B0zw, ccB, v0b);
        ffma2(B1xy, ccB, v1a); ffma2(B1zw, ccB, v1b);
    }
    if (iA < e) {
        float4 r0, r1;
        unpack2(r0.x, r0.y, A0xy); unpack2(r0.z, r0.w, A0zw);
        unpack2(r1.x, r1.y, A1xy); unpack2(r1.z, r1.w, A1zw);
        aE0[iA] = r0; aE1[iA] = r1;
    }
    if (iB < e) {
        float4 r0, r1;
        unpack2(r0.x, r0.y, B0xy); unpack2(r0.z, r0.w, B0zw);
        unpack2(r1.x, r1.y, B1xy); unpack2(r1.z, r1.w, B1zw);
        aE0[iB] = r0; aE1[iB] = r1;
    }
}

// ---------------- CSR scan: tiled, coalesced ----------------
__global__ void scan_kernel(const int* __restrict__ deg, int* __restrict__ rowptr,
                            int* __restrict__ cursor, int n) {
    __shared__ int wsum[32];
    __shared__ int carry;
    int t = threadIdx.x;
    int lane = t & 31, wid = t >> 5;
    if (t == 0) carry = 0;
    __syncthreads();
    for (int base = 0; base < n; base += 1024) {
        int i = base + t;
        int v = (i < n) ? deg[i] : 0;
        int incl = v;
        #pragma unroll
        for (int off = 1; off < 32; off <<= 1) {
            int x = __shfl_up_sync(0xffffffffu, incl, off);
            if (lane >= off) incl += x;
        }
        if (lane == 31) wsum[wid] = incl;
        __syncthreads();
        if (wid == 0) {
            int w = wsum[lane];
            #pragma unroll
            for (int off = 1; off < 32; off <<= 1) {
                int x = __shfl_up_sync(0xffffffffu, w, off);
                if (lane >= off) w += x;
            }
            wsum[lane] = w;
        }
        __syncthreads();
        int excl = carry + (wid ? wsum[wid - 1] : 0) + incl - v;
        if (i < n) { rowptr[i] = excl; cursor[i] = excl; }
        int total = wsum[31];
        __syncthreads();
        if (t == 0) carry += total;
        __syncthreads();
    }
    if (t == 0) rowptr[n] = carry;
}

// ---------------- scatter: build colsrc + permute aE into CSR order ----------------
__global__ void scatter_kernel(const int* __restrict__ src, const int* __restrict__ dst,
                               const float4* __restrict__ aE0, const float4* __restrict__ aE1,
                               int* cursor, int* colsrc,
                               float4* __restrict__ aE0c, float4* __restrict__ aE1c,
                               int e, int n) {
    int i = blockIdx.x * blockDim.x + threadIdx.x;
    int tot = e + n;
    if (i >= tot) return;
    if (i < e) {
        int d = dst[i];
        int p = atomicAdd(&cursor[d], 1);
        colsrc[p] = src[i];
        aE0c[p] = aE0[i];
        aE1c[p] = aE1[i];
    } else {
        int node = i - e;
        int p = atomicAdd(&cursor[node], 1);
        colsrc[p] = node;
        aE0c[p] = g_self0;
        aE1c[p] = g_self1;
    }
}

// ---------------- fp16 tensor-core GEMM with cp.async double buffering ----------------
__global__ void hgemm_kernel(const __half* __restrict__ A, const __half* __restrict__ B,
                             __half* __restrict__ C, int M, int K, int N) {
    __shared__ __half As[2][128][40];
    __shared__ __half Bs[2][32][72];
    const int AS_B = 128 * 40 * 2;
    const int BS_B = 32 * 72 * 2;
    int bm = blockIdx.y * 128, bn = blockIdx.x * 64;
    int tid = threadIdx.x;
    int wid = tid >> 5, lane = tid & 31;
    int wm = (wid >> 1) * 32, wn = (wid & 1) * 32;
    float acc[2][4][4];
    #pragma unroll
    for (int mt = 0; mt < 2; mt++)
        #pragma unroll
        for (int nt = 0; nt < 4; nt++)
            #pragma unroll
            for (int r = 0; r < 4; r++) acc[mt][nt][r] = 0.f;

    u32 as_base = (u32)__cvta_generic_to_shared(&As[0][0][0]);
    u32 bs_base = (u32)__cvta_generic_to_shared(&Bs[0][0][0]);

    int a_row0 = tid >> 2, a_c8 = (tid & 3) * 8;
    int b_row = tid >> 3, b_c8 = (tid & 7) * 8;

    {
        #pragma unroll
        for (int it = 0; it < 2; it++) {
            int row = a_row0 + it * 64;
            int gm = bm + row;
            int ok = (gm < M);
            const void* g = A + (size_t)(ok ? gm : 0) * K + a_c8;
            cp_async16(as_base + (u32)(row * 40 + a_c8) * 2, g, ok ? 16 : 0);
        }
        cp_async16(bs_base + (u32)(b_row * 72 + b_c8) * 2,
                   B + (size_t)b_row * N + bn + b_c8, 16);
        CP_COMMIT();
    }

    int KT = K >> 5;
    for (int kt = 0; kt < KT; kt++) {
        if (kt + 1 < KT) {
            int st = (kt + 1) & 1;
            int k0 = (kt + 1) * 32;
            #pragma unroll
            for (int it = 0; it < 2; it++) {
                int row = a_row0 + it * 64;
                int gm = bm + row;
                int ok = (gm < M);
                const void* g = A + (size_t)(ok ? gm : 0) * K + k0 + a_c8;
                cp_async16(as_base + (u32)(st * AS_B) + (u32)(row * 40 + a_c8) * 2, g, ok ? 16 : 0);
            }
            cp_async16(bs_base + (u32)(st * BS_B) + (u32)(b_row * 72 + b_c8) * 2,
                       B + (size_t)(k0 + b_row) * N + bn + b_c8, 16);
            CP_COMMIT();
            CP_WAIT(1);
        } else {
            CP_WAIT(0);
        }
        __syncthreads();
        u32 ab = as_base + (u32)((kt & 1) * AS_B);
        u32 bb = bs_base + (u32)((kt & 1) * BS_B);
        #pragma unroll
        for (int kk = 0; kk < 32; kk += 16) {
            u32 a0[4], a1[4], b0[4], b1[4];
            {
                int arow = wm + (lane & 15);
                int acol = kk + (lane >> 4) * 8;
                ldsm_x4(a0[0], a0[1], a0[2], a0[3], ab + (u32)(arow * 40 + acol) * 2);
            }
            {
                int arow = wm + 16 + (lane & 15);
                int acol = kk + (lane >> 4) * 8;
                ldsm_x4(a1[0], a1[1], a1[2], a1[3], ab + (u32)(arow * 40 + acol) * 2);
            }
            {
                int brow = kk + (lane & 15);
                int bcol = wn + (lane >> 4) * 8;
                ldsm_x4_trans(b0[0], b0[1], b0[2], b0[3], bb + (u32)(brow * 72 + bcol) * 2);
            }
            {
                int brow = kk + (lane & 15);
                int bcol = wn + 16 + (lane >> 4) * 8;
                ldsm_x4_trans(b1[0], b1[1], b1[2], b1[3], bb + (u32)(brow * 72 + bcol) * 2);
            }
            #pragma unroll
            for (int mt = 0; mt < 2; mt++) {
                u32* am = (mt == 0) ? a0 : a1;
                mma16816(acc[mt][0][0], acc[mt][0][1], acc[mt][0][2], acc[mt][0][3],
                         am[0], am[1], am[2], am[3], b0[0], b0[1]);
                mma16816(acc[mt][1][0], acc[mt][1][1], acc[mt][1][2], acc[mt][1][3],
                         am[0], am[1], am[2], am[3], b0[2], b0[3]);
                mma16816(acc[mt][2][0], acc[mt][2][1], acc[mt][2][2], acc[mt][2][3],
                         am[0], am[1], am[2], am[3], b1[0], b1[1]);
                mma16816(acc[mt][3][0], acc[mt][3][1], acc[mt][3][2], acc[mt][3][3],
                         am[0], am[1], am[2], am[3], b1[2], b1[3]);
            }
        }
        __syncthreads();
    }
    #pragma unroll
    for (int mt = 0; mt < 2; mt++) {
        #pragma unroll
        for (int r = 0; r < 2; r++) {
            int row = bm + wm + mt * 16 + r * 8 + (lane >> 2);
            if (row < M) {
                #pragma unroll
                for (int nt = 0; nt < 4; nt++) {
                    __half2 h = __floats2half2_rn(acc[mt][nt][r * 2 + 0], acc[mt][nt][r * 2 + 1]);
                    *(__half2*)(C + (size_t)row * N + bn + wn + nt * 8 + (lane & 3) * 2) = h;
                }
            }
        }
    }
}

// ---------------- coalesced per-(node,head) attention scores ----------------
template <int C>
__global__ void score_kernel(const __half* __restrict__ h, const float* __restrict__ asrc,
                             const float* __restrict__ adst, float* __restrict__ ssrc,
                             float* __restrict__ sdst, int n) {
    int warp = (blockIdx.x * blockDim.x + threadIdx.x) >> 5;
    int lane = threadIdx.x & 31;
    if (warp >= n) return;
    float sp = 0.f, dp = 0.f;
    if (C == 64) {
        uint4 raw = *(const uint4*)(h + (size_t)warp * 256 + lane * 8);
        __half2 hv[4];
        hv[0] = *(__half2*)&raw.x; hv[1] = *(__half2*)&raw.y;
        hv[2] = *(__half2*)&raw.z; hv[3] = *(__half2*)&raw.w;
        #pragma unroll
        for (int j = 0; j < 4; j++) {
            float2 f = __half22float2(hv[j]);
            int c0 = lane * 8 + j * 2;
            sp = fmaf(f.x, __ldg(asrc + c0), sp);
            sp = fmaf(f.y, __ldg(asrc + c0 + 1), sp);
            dp = fmaf(f.x, __ldg(adst + c0), dp);
            dp = fmaf(f.y, __ldg(adst + c0 + 1), dp);
        }
    } else {
        float2 f = __half22float2(__ldg((const __half2*)(h + (size_t)warp * 64) + lane));
        int c0 = lane * 2;
        sp = fmaf(f.x, __ldg(asrc + c0), 0.f);
        sp = fmaf(f.y, __ldg(asrc + c0 + 1), sp);
        dp = fmaf(f.x, __ldg(adst + c0), 0.f);
        dp = fmaf(f.y, __ldg(adst + c0 + 1), dp);
    }
    #pragma unroll
    for (int off = 4; off; off >>= 1) {
        sp += __shfl_down_sync(0xffffffffu, sp, off, 8);
        dp += __shfl_down_sync(0xffffffffu, dp, off, 8);
    }
    if ((lane & 7) == 0) {
        int head = lane >> 3;
        ssrc[warp * 4 + head] = sp;
        sdst[warp * 4 + head] = dp;
    }
}

// ---------------- 2-pass softmax + aggregation, warp/node, 4-edge unroll ----------------
template <int C, typename OutT>
__global__ void agg_kernel(const int* __restrict__ rowptr, const int* __restrict__ colsrc,
                           const float4* __restrict__ aEc,
                           const float4* __restrict__ ssrc, const float4* __restrict__ sdst,
                           const __half* __restrict__ hh, const float* __restrict__ bias,
                           float4* __restrict__ aCSR, OutT* __restrict__ outp, int n_nodes) {
    int warp = (blockIdx.x * blockDim.x + threadIdx.x) >> 5;
    int lane = threadIdx.x & 31;
    if (warp >= n_nodes) return;
    int node = warp;
    int base = rowptr[node], end = rowptr[node + 1];
    float4 sd = __ldg(sdst + node);
    int myhead = lane >> 3;
    // pass1
    float t0 = 0.f, t1 = 0.f, t2 = 0.f, t3 = 0.f;
    for (int j = base + lane; j < end; j += 32) {
        int s = colsrc[j];
        float4 ss = __ldg(ssrc + s);
        float4 ae = __ldg(aEc + j);
        float a0 = ss.x + sd.x + ae.x; a0 = a0 >= 0.f ? a0 : 0.2f * a0;
        float a1 = ss.y + sd.y + ae.y; a1 = a1 >= 0.f ? a1 : 0.2f * a1;
        float a2 = ss.z + sd.z + ae.z; a2 = a2 >= 0.f ? a2 : 0.2f * a2;
        float a3 = ss.w + sd.w + ae.w; a3 = a3 >= 0.f ? a3 : 0.2f * a3;
        float e0 = __expf(a0), e1 = __expf(a1);
        float e2 = __expf(a2), e3 = __expf(a3);
        aCSR[j] = make_float4(e0, e1, e2, e3);
        t0 += e0; t1 += e1; t2 += e2; t3 += e3;
    }
    #pragma unroll
    for (int off = 16; off; off >>= 1) {
        t0 += __shfl_xor_sync(0xffffffffu, t0, off);
        t1 += __shfl_xor_sync(0xffffffffu, t1, off);
        t2 += __shfl_xor_sync(0xffffffffu, t2, off);
        t3 += __shfl_xor_sync(0xffffffffu, t3, off);
    }
    float iv = 1.f / ((myhead == 0 ? t0 : myhead == 1 ? t1 : myhead == 2 ? t2 : t3) + 1e-16f);
    __syncwarp();
    const float* aS = (const float*)aCSR;
    if (C == 64) {
        float accA[8];
        #pragma unroll
        for (int k = 0; k < 8; k++) accA[k] = 0.f;
        int j = base;
        for (; j + 4 <= end; j += 4) {
            int s0 = colsrc[j], s1 = colsrc[j + 1], s2 = colsrc[j + 2], s3 = colsrc[j + 3];
            float e0 = __ldg(aS + (j + 0) * 4 + myhead);
            float e1 = __ldg(aS + (j + 1) * 4 + myhead);
            float e2 = __ldg(aS + (j + 2) * 4 + myhead);
            float e3 = __ldg(aS + (j + 3) * 4 + myhead);
            uint4 r0 = __ldg((const uint4*)(hh + (size_t)s0 * 256) + lane);
            uint4 r1 = __ldg((const uint4*)(hh + (size_t)s1 * 256) + lane);
            uint4 r2 = __ldg((const uint4*)(hh + (size_t)s2 * 256) + lane);
            uint4 r3 = __ldg((const uint4*)(hh + (size_t)s3 * 256) + lane);
            #pragma unroll
            for (int q = 0; q < 4; q++) {
                uint4 r = q == 0 ? r0 : q == 1 ? r1 : q == 2 ? r2 : r3;
                float ew = q == 0 ? e0 : q == 1 ? e1 : q == 2 ? e2 : e3;
                float2 f0 = __half22float2(*(__half2*)&r.x), f1 = __half22float2(*(__half2*)&r.y);
                float2 f2 = __half22float2(*(__half2*)&r.z), f3 = __half22float2(*(__half2*)&r.w);
                accA[0] = fmaf(f0.x, ew, accA[0]); accA[1] = fmaf(f0.y, ew, accA[1]);
                accA[2] = fmaf(f1.x, ew, accA[2]); accA[3] = fmaf(f1.y, ew, accA[3]);
                accA[4] = fmaf(f2.x, ew, accA[4]); accA[5] = fmaf(f2.y, ew, accA[5]);
                accA[6] = fmaf(f3.x, ew, accA[6]); accA[7] = fmaf(f3.y, ew, accA[7]);
            }
        }
        for (; j < end; j++) {
            int s = colsrc[j];
            float ew = __ldg(aS + j * 4 + myhead);
            uint4 r = __ldg((const uint4*)(hh + (size_t)s * 256) + lane);
            float2 f0 = __half22float2(*(__half2*)&r.x), f1 = __half22float2(*(__half2*)&r.y);
            float2 f2 = __half22float2(*(__half2*)&r.z), f3 = __half22float2(*(__half2*)&r.w);
            accA[0] = fmaf(f0.x, ew, accA[0]); accA[1] = fmaf(f0.y, ew, accA[1]);
            accA[2] = fmaf(f1.x, ew, accA[2]); accA[3] = fmaf(f1.y, ew, accA[3]);
            accA[4] = fmaf(f2.x, ew, accA[4]); accA[5] = fmaf(f2.y, ew, accA[5]);
            accA[6] = fmaf(f3.x, ew, accA[6]); accA[7] = fmaf(f3.y, ew, accA[7]);
        }
        float4 bv0 = *(const float4*)(bias + lane * 8);
        float4 bv1 = *(const float4*)(bias + lane * 8 + 4);
        float o0 = accA[0] * iv + bv0.x, o1 = accA[1] * iv + bv0.y;
        float o2 = accA[2] * iv + bv0.z, o3 = accA[3] * iv + bv0.w;
        float o4 = accA[4] * iv + bv1.x, o5 = accA[5] * iv + bv1.y;
        float o6 = accA[6] * iv + bv1.z, o7 = accA[7] * iv + bv1.w;
        if (sizeof(OutT) == 2) {
            __half2 h0 = __floats2half2_rn(o0, o1), h1 = __floats2half2_rn(o2, o3);
            __half2 h2 = __floats2half2_rn(o4, o5), h3 = __floats2half2_rn(o6, o7);
            uint4 pack;
            pack.x = *(u32*)&h0; pack.y = *(u32*)&h1; pack.z = *(u32*)&h2; pack.w = *(u32*)&h3;
            *(uint4*)((__half*)outp + (size_t)node * 256 + lane * 8) = pack;
        } else {
            float* op = (float*)outp + (size_t)node * 256 + lane * 8;
            *(float4*)op = make_float4(o0, o1, o2, o3);
            *(float4*)(op + 4) = make_float4(o4, o5, o6, o7);
        }
    } else {  // C == 16
        float2 acc = make_float2(0.f, 0.f);
        int j = base;
        for (; j + 4 <= end; j += 4) {
            int s0 = colsrc[j], s1 = colsrc[j + 1], s2 = colsrc[j + 2], s3 = colsrc[j + 3];
            float e0 = __ldg(aS + (j + 0) * 4 + myhead);
            float e1 = __ldg(aS + (j + 1) * 4 + myhead);
            float e2 = __ldg(aS + (j + 2) * 4 + myhead);
            float e3 = __ldg(aS + (j + 3) * 4 + myhead);
            float2 f0 = __half22float2(__ldg((const __half2*)(hh + (size_t)s0 * 64) + lane));
            float2 f1 = __half22float2(__ldg((const __half2*)(hh + (size_t)s1 * 64) + lane));
            float2 f2 = __half22float2(__ldg((const __half2*)(hh + (size_t)s2 * 64) + lane));
            float2 f3 = __half22float2(__ldg((const __half2*)(hh + (size_t)s3 * 64) + lane));
            acc.x = fmaf(f0.x, e0, acc.x); acc.y = fmaf(f0.y, e0, acc.y);
            acc.x = fmaf(f1.x, e1, acc.x); acc.y = fmaf(f1.y, e1, acc.y);
            acc.x = fmaf(f2.x, e2, acc.x); acc.y = fmaf(f2.y, e2, acc.y);
            acc.x = fmaf(f3.x, e3, acc.x); acc.y = fmaf(f3.y, e3, acc.y);
        }
        for (; j < end; j++) {
            int s = colsrc[j];
            float ew = __ldg(aS + j * 4 + myhead);
            float2 f = __half22float2(__ldg((const __half2*)(hh + (size_t)s * 64) + lane));
            acc.x = fmaf(f.x, ew, acc.x);
            acc.y = fmaf(f.y, ew, acc.y);
        }
        float2 bv = *(const float2*)(bias + 2 * lane);
        float ox = acc.x * iv + bv.x;
        float oy = acc.y * iv + bv.y;
        if (sizeof(OutT) == 2) {
            *(__half2*)((__half*)outp + (size_t)node * 64 + 2 * lane) = __floats2half2_rn(ox, oy);
        } else {
            *(float2*)((float*)outp + (size_t)node * 64 + 2 * lane) = make_float2(ox, oy);
        }
    }
}

// ---------------- launch ----------------
extern "C" void kernel_launch(void* const* d_in, const int* in_sizes, int n_in,
                              void* d_out, int out_size) {
    const float* x   = (const float*)d_in[0];
    const int*   ei  = (const int*)d_in[1];
    const float* ts  = (const float*)d_in[2];
    const float* tw  = (const float*)d_in[3];
    const float* tb  = (const float*)d_in[4];
    const float* W0  = (const float*)d_in[5];
    const float* as0 = (const float*)d_in[6];
    const float* ad0 = (const float*)d_in[7];
    const float* le0 = (const float*)d_in[8];
    const float* ae0 = (const float*)d_in[9];
    const float* b0  = (const float*)d_in[10];
    const float* W1  = (const float*)d_in[11];
    const float* as1 = (const float*)d_in[12];
    const float* ad1 = (const float*)d_in[13];
    const float* le1 = (const float*)d_in[14];
    const float* ae1 = (const float*)d_in[15];
    const float* b1  = (const float*)d_in[16];

    int n = in_sizes[0] / 128;   // 50000
    int e = in_sizes[2];         // 800000
    int tot = e + n;
    const int* srcp = ei;
    const int* dstp = ei + e;

    void *p_xh, *p_w0h, *p_w1h, *p_hh0, *p_out0h, *p_hh1;
    void *p_aE0, *p_aE1, *p_aE0c, *p_aE1c, *p_aCSR, *p_ss0, *p_sd0, *p_ss1, *p_sd1;
    void *p_deg, *p_rowptr, *p_cursor, *p_colsrc;
    cudaGetSymbolAddress(&p_xh, g_xh);
    cudaGetSymbolAddress(&p_w0h, g_w0h);
    cudaGetSymbolAddress(&p_w1h, g_w1h);
    cudaGetSymbolAddress(&p_hh0, g_hh0);
    cudaGetSymbolAddress(&p_out0h, g_out0h);
    cudaGetSymbolAddress(&p_hh1, g_hh1);
    cudaGetSymbolAddress(&p_aE0, g_alphaE0);
    cudaGetSymbolAddress(&p_aE1, g_alphaE1);
    cudaGetSymbolAddress(&p_aE0c, g_aE0c);
    cudaGetSymbolAddress(&p_aE1c, g_aE1c);
    cudaGetSymbolAddress(&p_aCSR, g_aCSR);
    cudaGetSymbolAddress(&p_ss0, g_ss0);
    cudaGetSymbolAddress(&p_sd0, g_sd0);
    cudaGetSymbolAddress(&p_ss1, g_ss1);
    cudaGetSymbolAddress(&p_sd1, g_sd1);
    cudaGetSymbolAddress(&p_deg, g_deg);
    cudaGetSymbolAddress(&p_rowptr, g_rowptr);
    cudaGetSymbolAddress(&p_cursor, g_cursor);
    cudaGetSymbolAddress(&p_colsrc, g_colsrc);

    __half* xh     = (__half*)p_xh;
    __half* w0h    = (__half*)p_w0h;
    __half* w1h    = (__half*)p_w1h;
    __half* hh0    = (__half*)p_hh0;
    __half* out0h  = (__half*)p_out0h;
    __half* hh1    = (__half*)p_hh1;
    float4* aE0    = (float4*)p_aE0;
    float4* aE1    = (float4*)p_aE1;
    float4* aE0c   = (float4*)p_aE0c;
    float4* aE1c   = (float4*)p_aE1c;
    float4* aCSR   = (float4*)p_aCSR;
    float4* ss0    = (float4*)p_ss0;
    float4* sd0    = (float4*)p_sd0;
    float4* ss1    = (float4*)p_ss1;
    float4* sd1    = (float4*)p_sd1;
    int* deg       = (int*)p_deg;
    int* rowptr    = (int*)p_rowptr;
    int* cursor    = (int*)p_cursor;
    int* colsrc    = (int*)p_colsrc;

    setup_kernel<<<1 + 512, 256>>>(le0, ae0, le1, ae1, x, W0, W1, deg, xh, w0h, w1h, n);
    edge_feat_kernel<<<(e + 511) / 512, 256>>>(ts, tw, tb, dstp, deg, aE0, aE1, e);
    hgemm_kernel<<<dim3(256 / 64, (n + 127) / 128), 256>>>(xh, w0h, hh0, n, 128, 256);
    scan_kernel<<<1, 1024>>>(deg, rowptr, cursor, n);
    scatter_kernel<<<(tot + 255) / 256, 256>>>(srcp, dstp, aE0, aE1, cursor, colsrc,
                                               aE0c, aE1c, e, n);
    score_kernel<64><<<(n * 32 + 255) / 256, 256>>>(hh0, as0, ad0, (float*)ss0, (float*)sd0, n);
    agg_kernel<64, __half><<<(n * 32 + 255) / 256, 256>>>(rowptr, colsrc, aE0c, ss0, sd0,
                                                          hh0, b0, aCSR, out0h, n);
    hgemm_kernel<<<dim3(64 / 64, (n + 127) / 128), 256>>>(out0h, w1h, hh1, n, 256, 64);
    score_kernel<16><<<(n * 32 + 255) / 256, 256>>>(hh1, as1, ad1, (float*)ss1, (float*)sd1, n);
    agg_kernel<16, float><<<(n * 32 + 255) / 256, 256>>>(rowptr, colsrc, aE1c, ss1, sd1,
                                                         hh1, b1, aCSR, (float*)d_out, n);
}

// round 13
// speedup vs baseline: 1.6098x; 1.1306x over previous
#include <cuda_runtime.h>
#include <cuda_fp16.h>
#include <stdint.h>
#include <math.h>

typedef unsigned int u32;
typedef unsigned long long u64;

#define NN 50000
#define EE 800000
#define ET (EE + NN)
#define TDIM 64
#define SCAN_TILE 4096   // 1024 threads x 4 elems

// ---------------- scratch (static device globals; no allocation) ----------------
__device__ int    g_deg[NN];
__device__ int    g_rowptr[NN + 1];
__device__ int    g_cursor[NN];
__device__ int    g_blocksum[64];
__device__ int    g_blockoff[64];
__device__ int    g_colsrc[ET];
__device__ float4 g_alphaE0[EE];
__device__ float4 g_alphaE1[EE];
__device__ float4 g_aE0c[ET];
__device__ float4 g_aE1c[ET];
__device__ float4 g_aCSR[ET];
__device__ __half g_xh[(size_t)NN * 128];
__device__ __half g_w0h[128 * 256];
__device__ __half g_w1h[256 * 64];
__device__ __half g_hh0[(size_t)NN * 256];
__device__ __half g_out0h[(size_t)NN * 256];
__device__ __half g_hh1[(size_t)NN * 64];
__device__ float4 g_ss0[NN], g_sd0[NN], g_ss1[NN], g_sd1[NN];
__device__ float4 g_ve0[TDIM];
__device__ float4 g_ve1[TDIM];
__device__ float4 g_self0, g_self1;

// ---------------- PTX helpers ----------------
__device__ __forceinline__ void ldsm_x4(u32& r0, u32& r1, u32& r2, u32& r3, u32 addr) {
    asm volatile("ldmatrix.sync.aligned.m8n8.x4.shared.b16 {%0,%1,%2,%3}, [%4];"
                 : "=r"(r0), "=r"(r1), "=r"(r2), "=r"(r3) : "r"(addr));
}
__device__ __forceinline__ void ldsm_x4_trans(u32& r0, u32& r1, u32& r2, u32& r3, u32 addr) {
    asm volatile("ldmatrix.sync.aligned.m8n8.x4.trans.shared.b16 {%0,%1,%2,%3}, [%4];"
                 : "=r"(r0), "=r"(r1), "=r"(r2), "=r"(r3) : "r"(addr));
}
__device__ __forceinline__ void mma16816(float& c0, float& c1, float& c2, float& c3,
                                         u32 a0, u32 a1, u32 a2, u32 a3,
                                         u32 b0, u32 b1) {
    asm volatile(
        "mma.sync.aligned.m16n8k16.row.col.f32.f16.f16.f32 "
        "{%0,%1,%2,%3}, {%4,%5,%6,%7}, {%8,%9}, {%0,%1,%2,%3};"
        : "+f"(c0), "+f"(c1), "+f"(c2), "+f"(c3)
        : "r"(a0), "r"(a1), "r"(a2), "r"(a3), "r"(b0), "r"(b1));
}
__device__ __forceinline__ void cp_async16(u32 saddr, const void* gaddr, int src_bytes) {
    asm volatile("cp.async.ca.shared.global [%0], [%1], 16, %2;"
                 :: "r"(saddr), "l"(gaddr), "r"(src_bytes));
}
#define CP_COMMIT()  asm volatile("cp.async.commit_group;")
#define CP_WAIT(n)   asm volatile("cp.async.wait_group %0;" :: "n"(n))

__device__ __forceinline__ void ffma2(u64& d, u64 a, u64 b) {
    asm("fma.rn.f32x2 %0, %1, %2, %0;" : "+l"(d) : "l"(a), "l"(b));
}
__device__ __forceinline__ u64 pack2(float lo, float hi) {
    u64 r;
    asm("mov.b64 %0, {%1, %2};" : "=l"(r) : "f"(lo), "f"(hi));
    return r;
}
__device__ __forceinline__ void unpack2(float& lo, float& hi, u64 v) {
    asm("mov.b64 {%0, %1}, %2;" : "=f"(lo), "=f"(hi) : "l"(v));
}

// ---------------- setup: prep (block 0) + deg init + 3x fp32->fp16 cvt ----------------
__global__ void setup_kernel(const float* __restrict__ le0, const float* __restrict__ ae0,
                             const float* __restrict__ le1, const float* __restrict__ ae1,
                             const float* __restrict__ x, const float* __restrict__ W0,
                             const float* __restrict__ W1,
                             int* __restrict__ deg,
                             __half* __restrict__ xh, __half* __restrict__ w0h,
                             __half* __restrict__ w1h, int n) {
    int tid = threadIdx.x;
    if (blockIdx.x == 0) {
        int td = tid >> 2, hh = tid & 3;
        float s0 = 0.f;
        for (int c = 0; c < 64; c++) s0 += le0[td * 256 + hh * 64 + c] * ae0[hh * 64 + c];
        ((float*)g_ve0)[td * 4 + hh] = s0;
        float s1 = 0.f;
        for (int c = 0; c < 16; c++) s1 += le1[td * 64 + hh * 16 + c] * ae1[hh * 16 + c];
        ((float*)g_ve1)[td * 4 + hh] = s1;
        __syncthreads();
        if (td == 0) {
            float a = 0.f, b = 0.f;
            for (int t2 = 0; t2 < TDIM; t2++) {
                a += ((float*)g_ve0)[t2 * 4 + hh];
                b += ((float*)g_ve1)[t2 * 4 + hh];
            }
            ((float*)&g_self0)[hh] = a;
            ((float*)&g_self1)[hh] = b;
        }
        return;
    }
    int gid = (blockIdx.x - 1) * 256 + tid;
    int stride = (gridDim.x - 1) * 256;
    for (int i = gid; i < n; i += stride) deg[i] = 1;
    int nx4 = n * 32;
    for (int i = gid; i < nx4; i += stride) {
        float4 v = *(const float4*)(x + (size_t)i * 4);
        *(__half2*)(xh + (size_t)i * 4) = __floats2half2_rn(v.x, v.y);
        *(__half2*)(xh + (size_t)i * 4 + 2) = __floats2half2_rn(v.z, v.w);
    }
    for (int i = gid; i < 8192; i += stride) {
        float4 v = *(const float4*)(W0 + (size_t)i * 4);
        *(__half2*)(w0h + (size_t)i * 4) = __floats2half2_rn(v.x, v.y);
        *(__half2*)(w0h + (size_t)i * 4 + 2) = __floats2half2_rn(v.z, v.w);
    }
    for (int i = gid; i < 4096; i += stride) {
        float4 v = *(const float4*)(W1 + (size_t)i * 4);
        *(__half2*)(w1h + (size_t)i * 4) = __floats2half2_rn(v.x, v.y);
        *(__half2*)(w1h + (size_t)i * 4 + 2) = __floats2half2_rn(v.z, v.w);
    }
}

// ---------------- per-edge time features + fused deg count (f32x2 packed dots) --------
__global__ void edge_feat_kernel(const float* __restrict__ ts,
                                 const float* __restrict__ tw,
                                 const float* __restrict__ tb,
                                 const int* __restrict__ dst,
                                 int* __restrict__ deg,
                                 float4* __restrict__ aE0, float4* __restrict__ aE1,
                                 int e) {
    __shared__ float2 swb[TDIM];
    __shared__ u64 pv0a[TDIM], pv0b[TDIM], pv1a[TDIM], pv1b[TDIM];
    int tid = threadIdx.x;
    if (tid < TDIM) {
        swb[tid] = make_float2(tw[tid], tb[tid]);
        float4 v0 = g_ve0[tid];
        float4 v1 = g_ve1[tid];
        pv0a[tid] = pack2(v0.x, v0.y);
        pv0b[tid] = pack2(v0.z, v0.w);
        pv1a[tid] = pack2(v1.x, v1.y);
        pv1b[tid] = pack2(v1.z, v1.w);
    }
    __syncthreads();
    int iA = blockIdx.x * 512 + tid;
    int iB = iA + 256;
    float tA = (iA < e) ? ts[iA] : 0.f;
    float tB = (iB < e) ? ts[iB] : 0.f;
    if (iA < e) atomicAdd(&deg[dst[iA]], 1);
    if (iB < e) atomicAdd(&deg[dst[iB]], 1);
    u64 A0xy = 0, A0zw = 0, A1xy = 0, A1zw = 0;
    u64 B0xy = 0, B0zw = 0, B1xy = 0, B1zw = 0;
    #pragma unroll 8
    for (int td = 0; td < TDIM; td++) {
        float2 wb = swb[td];
        float aA = fabsf(__cosf(fmaf(tA, wb.x, wb.y)));
        float aB = fabsf(__cosf(fmaf(tB, wb.x, wb.y)));
        u64 ccA = pack2(aA, aA);
        u64 ccB = pack2(aB, aB);
        u64 v0a = pv0a[td], v0b = pv0b[td], v1a = pv1a[td], v1b = pv1b[td];
        ffma2(A0xy, ccA, v0a); ffma2(A0zw, ccA, v0b);
        ffma2(A1xy, ccA, v1a); ffma2(A1zw, ccA, v1b);
        ffma2(B0xy, ccB, v0a); ffma2(B0zw, ccB, v0b);
        ffma2(B1xy, ccB, v1a); ffma2(B1zw, ccB, v1b);
    }
    if (iA < e) {
        float4 r0, r1;
        unpack2(r0.x, r0.y, A0xy); unpack2(r0.z, r0.w, A0zw);
        unpack2(r1.x, r1.y, A1xy); unpack2(r1.z, r1.w, A1zw);
        aE0[iA] = r0; aE1[iA] = r1;
    }
    if (iB < e) {
        float4 r0, r1;
        unpack2(r0.x, r0.y, B0xy); unpack2(r0.z, r0.w, B0zw);
        unpack2(r1.x, r1.y, B1xy); unpack2(r1.z, r1.w, B1zw);
        aE0[iB] = r0; aE1[iB] = r1;
    }
}

// ---------------- multi-block scan, phase 1: per-block exclusive scan + block sums ----
__global__ void scan1_kernel(const int* __restrict__ deg, int* __restrict__ rowptr,
                             int* __restrict__ blocksum, int n) {
    __shared__ int wsum[32];
    int t = threadIdx.x;
    int lane = t & 31, wid = t >> 5;
    int base = blockIdx.x * SCAN_TILE + t * 4;
    int4 v = make_int4(0, 0, 0, 0);
    if (base + 3 < n) {
        v = *(const int4*)(deg + base);
    } else {
        if (base + 0 < n) v.x = deg[base + 0];
        if (base + 1 < n) v.y = deg[base + 1];
        if (base + 2 < n) v.z = deg[base + 2];
        if (base + 3 < n) v.w = deg[base + 3];
    }
    int mysum = v.x + v.y + v.z + v.w;
    int incl = mysum;
    #pragma unroll
    for (int off = 1; off < 32; off <<= 1) {
        int x = __shfl_up_sync(0xffffffffu, incl, off);
        if (lane >= off) incl += x;
    }
    if (lane == 31) wsum[wid] = incl;
    __syncthreads();
    if (wid == 0) {
        int w = (lane < 32) ? wsum[lane] : 0;
        #pragma unroll
        for (int off = 1; off < 32; off <<= 1) {
            int x = __shfl_up_sync(0xffffffffu, w, off);
            if (lane >= off) w += x;
        }
        wsum[lane] = w;
    }
    __syncthreads();
    int excl = (wid ? wsum[wid - 1] : 0) + incl - mysum;
    int4 o;
    o.x = excl;
    o.y = o.x + v.x;
    o.z = o.y + v.y;
    o.w = o.z + v.z;
    if (base + 3 < n) {
        *(int4*)(rowptr + base) = o;
    } else {
        if (base + 0 < n) rowptr[base + 0] = o.x;
        if (base + 1 < n) rowptr[base + 1] = o.y;
        if (base + 2 < n) rowptr[base + 2] = o.z;
        if (base + 3 < n) rowptr[base + 3] = o.w;
    }
    if (t == 1023) blocksum[blockIdx.x] = wsum[31];
}

// ---------------- phase 2: scan the block sums (single warp) ----------------
__global__ void scan2_kernel(const int* __restrict__ blocksum, int* __restrict__ blockoff,
                             int* __restrict__ rowptr, int n, int nb) {
    int lane = threadIdx.x;
    int v = (lane < nb) ? blocksum[lane] : 0;
    int incl = v;
    #pragma unroll
    for (int off = 1; off < 32; off <<= 1) {
        int x = __shfl_up_sync(0xffffffffu, incl, off);
        if (lane >= off) incl += x;
    }
    if (lane < nb) blockoff[lane] = incl - v;
    if (lane == 31) rowptr[n] = incl;
}

// ---------------- phase 3: add block offsets; write cursor ----------------
__global__ void scan3_kernel(int* __restrict__ rowptr, int* __restrict__ cursor,
                             const int* __restrict__ blockoff, int n) {
    int i = blockIdx.x * blockDim.x + threadIdx.x;
    if (i < n) {
        int val = rowptr[i] + blockoff[i / SCAN_TILE];
        rowptr[i] = val;
        cursor[i] = val;
    }
}

// ---------------- scatter: build colsrc + permute aE into CSR order ----------------
__global__ void scatter_kernel(const int* __restrict__ src, const int* __restrict__ dst,
                               const float4* __restrict__ aE0, const float4* __restrict__ aE1,
                               int* cursor, int* colsrc,
                               float4* __restrict__ aE0c, float4* __restrict__ aE1c,
                               int e, int n) {
    int i = blockIdx.x * blockDim.x + threadIdx.x;
    int tot = e + n;
    if (i >= tot) return;
    if (i < e) {
        int d = dst[i];
        int p = atomicAdd(&cursor[d], 1);
        colsrc[p] = src[i];
        aE0c[p] = aE0[i];
        aE1c[p] = aE1[i];
    } else {
        int node = i - e;
        int p = atomicAdd(&cursor[node], 1);
        colsrc[p] = node;
        aE0c[p] = g_self0;
        aE1c[p] = g_self1;
    }
}

// ---------------- fp16 tensor-core GEMM with cp.async double buffering ----------------
__global__ void hgemm_kernel(const __half* __restrict__ A, const __half* __restrict__ B,
                             __half* __restrict__ C, int M, int K, int N) {
    __shared__ __half As[2][128][40];
    __shared__ __half Bs[2][32][72];
    const int AS_B = 128 * 40 * 2;
    const int BS_B = 32 * 72 * 2;
    int bm = blockIdx.y * 128, bn = blockIdx.x * 64;
    int tid = threadIdx.x;
    int wid = tid >> 5, lane = tid & 31;
    int wm = (wid >> 1) * 32, wn = (wid & 1) * 32;
    float acc[2][4][4];
    #pragma unroll
    for (int mt = 0; mt < 2; mt++)
        #pragma unroll
        for (int nt = 0; nt < 4; nt++)
            #pragma unroll
            for (int r = 0; r < 4; r++) acc[mt][nt][r] = 0.f;

    u32 as_base = (u32)__cvta_generic_to_shared(&As[0][0][0]);
    u32 bs_base = (u32)__cvta_generic_to_shared(&Bs[0][0][0]);

    int a_row0 = tid >> 2, a_c8 = (tid & 3) * 8;
    int b_row = tid >> 3, b_c8 = (tid & 7) * 8;

    {
        #pragma unroll
        for (int it = 0; it < 2; it++) {
            int row = a_row0 + it * 64;
            int gm = bm + row;
            int ok = (gm < M);
            const void* g = A + (size_t)(ok ? gm : 0) * K + a_c8;
            cp_async16(as_base + (u32)(row * 40 + a_c8) * 2, g, ok ? 16 : 0);
        }
        cp_async16(bs_base + (u32)(b_row * 72 + b_c8) * 2,
                   B + (size_t)b_row * N + bn + b_c8, 16);
        CP_COMMIT();
    }

    int KT = K >> 5;
    for (int kt = 0; kt < KT; kt++) {
        if (kt + 1 < KT) {
            int st = (kt + 1) & 1;
            int k0 = (kt + 1) * 32;
            #pragma unroll
            for (int it = 0; it < 2; it++) {
                int row = a_row0 + it * 64;
                int gm = bm + row;
                int ok = (gm < M);
                const void* g = A + (size_t)(ok ? gm : 0) * K + k0 + a_c8;
                cp_async16(as_base + (u32)(st * AS_B) + (u32)(row * 40 + a_c8) * 2, g, ok ? 16 : 0);
            }
            cp_async16(bs_base + (u32)(st * BS_B) + (u32)(b_row * 72 + b_c8) * 2,
                       B + (size_t)(k0 + b_row) * N + bn + b_c8, 16);
            CP_COMMIT();
            CP_WAIT(1);
        } else {
            CP_WAIT(0);
        }
        __syncthreads();
        u32 ab = as_base + (u32)((kt & 1) * AS_B);
        u32 bb = bs_base + (u32)((kt & 1) * BS_B);
        #pragma unroll
        for (int kk = 0; kk < 32; kk += 16) {
            u32 a0[4], a1[4], b0[4], b1[4];
            {
                int arow = wm + (lane & 15);
                int acol = kk + (lane >> 4) * 8;
                ldsm_x4(a0[0], a0[1], a0[2], a0[3], ab + (u32)(arow * 40 + acol) * 2);
            }
            {
                int arow = wm + 16 + (lane & 15);
                int acol = kk + (lane >> 4) * 8;
                ldsm_x4(a1[0], a1[1], a1[2], a1[3], ab + (u32)(arow * 40 + acol) * 2);
            }
            {
                int brow = kk + (lane & 15);
                int bcol = wn + (lane >> 4) * 8;
                ldsm_x4_trans(b0[0], b0[1], b0[2], b0[3], bb + (u32)(brow * 72 + bcol) * 2);
            }
            {
                int brow = kk + (lane & 15);
                int bcol = wn + 16 + (lane >> 4) * 8;
                ldsm_x4_trans(b1[0], b1[1], b1[2], b1[3], bb + (u32)(brow * 72 + bcol) * 2);
            }
            #pragma unroll
            for (int mt = 0; mt < 2; mt++) {
                u32* am = (mt == 0) ? a0 : a1;
                mma16816(acc[mt][0][0], acc[mt][0][1], acc[mt][0][2], acc[mt][0][3],
                         am[0], am[1], am[2], am[3], b0[0], b0[1]);
                mma16816(acc[mt][1][0], acc[mt][1][1], acc[mt][1][2], acc[mt][1][3],
                         am[0], am[1], am[2], am[3], b0[2], b0[3]);
                mma16816(acc[mt][2][0], acc[mt][2][1], acc[mt][2][2], acc[mt][2][3],
                         am[0], am[1], am[2], am[3], b1[0], b1[1]);
                mma16816(acc[mt][3][0], acc[mt][3][1], acc[mt][3][2], acc[mt][3][3],
                         am[0], am[1], am[2], am[3], b1[2], b1[3]);
            }
        }
        __syncthreads();
    }
    #pragma unroll
    for (int mt = 0; mt < 2; mt++) {
        #pragma unroll
        for (int r = 0; r < 2; r++) {
            int row = bm + wm + mt * 16 + r * 8 + (lane >> 2);
            if (row < M) {
                #pragma unroll
                for (int nt = 0; nt < 4; nt++) {
                    __half2 h = __floats2half2_rn(acc[mt][nt][r * 2 + 0], acc[mt][nt][r * 2 + 1]);
                    *(__half2*)(C + (size_t)row * N + bn + wn + nt * 8 + (lane & 3) * 2) = h;
                }
            }
        }
    }
}

// ---------------- coalesced per-(node,head) attention scores ----------------
template <int C>
__global__ void score_kernel(const __half* __restrict__ h, const float* __restrict__ asrc,
                             const float* __restrict__ adst, float* __restrict__ ssrc,
                             float* __restrict__ sdst, int n) {
    int warp = (blockIdx.x * blockDim.x + threadIdx.x) >> 5;
    int lane = threadIdx.x & 31;
    if (warp >= n) return;
    float sp = 0.f, dp = 0.f;
    if (C == 64) {
        uint4 raw = *(const uint4*)(h + (size_t)warp * 256 + lane * 8);
        __half2 hv[4];
        hv[0] = *(__half2*)&raw.x; hv[1] = *(__half2*)&raw.y;
        hv[2] = *(__half2*)&raw.z; hv[3] = *(__half2*)&raw.w;
        #pragma unroll
        for (int j = 0; j < 4; j++) {
            float2 f = __half22float2(hv[j]);
            int c0 = lane * 8 + j * 2;
            sp = fmaf(f.x, __ldg(asrc + c0), sp);
            sp = fmaf(f.y, __ldg(asrc + c0 + 1), sp);
            dp = fmaf(f.x, __ldg(adst + c0), dp);
            dp = fmaf(f.y, __ldg(adst + c0 + 1), dp);
        }
    } else {
        float2 f = __half22float2(__ldg((const __half2*)(h + (size_t)warp * 64) + lane));
        int c0 = lane * 2;
        sp = fmaf(f.x, __ldg(asrc + c0), 0.f);
        sp = fmaf(f.y, __ldg(asrc + c0 + 1), sp);
        dp = fmaf(f.x, __ldg(adst + c0), 0.f);
        dp = fmaf(f.y, __ldg(adst + c0 + 1), dp);
    }
    #pragma unroll
    for (int off = 4; off; off >>= 1) {
        sp += __shfl_down_sync(0xffffffffu, sp, off, 8);
        dp += __shfl_down_sync(0xffffffffu, dp, off, 8);
    }
    if ((lane & 7) == 0) {
        int head = lane >> 3;
        ssrc[warp * 4 + head] = sp;
        sdst[warp * 4 + head] = dp;
    }
}

// ---------------- 2-pass softmax + aggregation, warp/node, 4-edge unroll ----------------
template <int C, typename OutT>
__global__ void agg_kernel(const int* __restrict__ rowptr, const int* __restrict__ colsrc,
                           const float4* __restrict__ aEc,
                           const float4* __restrict__ ssrc, const float4* __restrict__ sdst,
                           const __half* __restrict__ hh, const float* __restrict__ bias,
                           float4* __restrict__ aCSR, OutT* __restrict__ outp, int n_nodes) {
    int warp = (blockIdx.x * blockDim.x + threadIdx.x) >> 5;
    int lane = threadIdx.x & 31;
    if (warp >= n_nodes) return;
    int node = warp;
    int base = rowptr[node], end = rowptr[node + 1];
    float4 sd = __ldg(sdst + node);
    int myhead = lane >> 3;
    float t0 = 0.f, t1 = 0.f, t2 = 0.f, t3 = 0.f;
    for (int j = base + lane; j < end; j += 32) {
        int s = colsrc[j];
        float4 ss = __ldg(ssrc + s);
        float4 ae = __ldg(aEc + j);
        float a0 = ss.x + sd.x + ae.x; a0 = a0 >= 0.f ? a0 : 0.2f * a0;
        float a1 = ss.y + sd.y + ae.y; a1 = a1 >= 0.f ? a1 : 0.2f * a1;
        float a2 = ss.z + sd.z + ae.z; a2 = a2 >= 0.f ? a2 : 0.2f * a2;
        float a3 = ss.w + sd.w + ae.w; a3 = a3 >= 0.f ? a3 : 0.2f * a3;
        float e0 = __expf(a0), e1 = __expf(a1);
        float e2 = __expf(a2), e3 = __expf(a3);
        aCSR[j] = make_float4(e0, e1, e2, e3);
        t0 += e0; t1 += e1; t2 += e2; t3 += e3;
    }
    #pragma unroll
    for (int off = 16; off; off >>= 1) {
        t0 += __shfl_xor_sync(0xffffffffu, t0, off);
        t1 += __shfl_xor_sync(0xffffffffu, t1, off);
        t2 += __shfl_xor_sync(0xffffffffu, t2, off);
        t3 += __shfl_xor_sync(0xffffffffu, t3, off);
    }
    float iv = 1.f / ((myhead == 0 ? t0 : myhead == 1 ? t1 : myhead == 2 ? t2 : t3) + 1e-16f);
    __syncwarp();
    const float* aS = (const float*)aCSR;
    if (C == 64) {
        float accA[8];
        #pragma unroll
        for (int k = 0; k < 8; k++) accA[k] = 0.f;
        int j = base;
        for (; j + 4 <= end; j += 4) {
            int s0 = colsrc[j], s1 = colsrc[j + 1], s2 = colsrc[j + 2], s3 = colsrc[j + 3];
            float e0 = __ldg(aS + (j + 0) * 4 + myhead);
            float e1 = __ldg(aS + (j + 1) * 4 + myhead);
            float e2 = __ldg(aS + (j + 2) * 4 + myhead);
            float e3 = __ldg(aS + (j + 3) * 4 + myhead);
            uint4 r0 = __ldg((const uint4*)(hh + (size_t)s0 * 256) + lane);
            uint4 r1 = __ldg((const uint4*)(hh + (size_t)s1 * 256) + lane);
            uint4 r2 = __ldg((const uint4*)(hh + (size_t)s2 * 256) + lane);
            uint4 r3 = __ldg((const uint4*)(hh + (size_t)s3 * 256) + lane);
            #pragma unroll
            for (int q = 0; q < 4; q++) {
                uint4 r = q == 0 ? r0 : q == 1 ? r1 : q == 2 ? r2 : r3;
                float ew = q == 0 ? e0 : q == 1 ? e1 : q == 2 ? e2 : e3;
                float2 f0 = __half22float2(*(__half2*)&r.x), f1 = __half22float2(*(__half2*)&r.y);
                float2 f2 = __half22float2(*(__half2*)&r.z), f3 = __half22float2(*(__half2*)&r.w);
                accA[0] = fmaf(f0.x, ew, accA[0]); accA[1] = fmaf(f0.y, ew, accA[1]);
                accA[2] = fmaf(f1.x, ew, accA[2]); accA[3] = fmaf(f1.y, ew, accA[3]);
                accA[4] = fmaf(f2.x, ew, accA[4]); accA[5] = fmaf(f2.y, ew, accA[5]);
                accA[6] = fmaf(f3.x, ew, accA[6]); accA[7] = fmaf(f3.y, ew, accA[7]);
            }
        }
        for (; j < end; j++) {
            int s = colsrc[j];
            float ew = __ldg(aS + j * 4 + myhead);
            uint4 r = __ldg((const uint4*)(hh + (size_t)s * 256) + lane);
            float2 f0 = __half22float2(*(__half2*)&r.x), f1 = __half22float2(*(__half2*)&r.y);
            float2 f2 = __half22float2(*(__half2*)&r.z), f3 = __half22float2(*(__half2*)&r.w);
            accA[0] = fmaf(f0.x, ew, accA[0]); accA[1] = fmaf(f0.y, ew, accA[1]);
            accA[2] = fmaf(f1.x, ew, accA[2]); accA[3] = fmaf(f1.y, ew, accA[3]);
            accA[4] = fmaf(f2.x, ew, accA[4]); accA[5] = fmaf(f2.y, ew, accA[5]);
            accA[6] = fmaf(f3.x, ew, accA[6]); accA[7] = fmaf(f3.y, ew, accA[7]);
        }
        float4 bv0 = *(const float4*)(bias + lane * 8);
        float4 bv1 = *(const float4*)(bias + lane * 8 + 4);
        float o0 = accA[0] * iv + bv0.x, o1 = accA[1] * iv + bv0.y;
        float o2 = accA[2] * iv + bv0.z, o3 = accA[3] * iv + bv0.w;
        float o4 = accA[4] * iv + bv1.x, o5 = accA[5] * iv + bv1.y;
        float o6 = accA[6] * iv + bv1.z, o7 = accA[7] * iv + bv1.w;
        if (sizeof(OutT) == 2) {
            __half2 h0 = __floats2half2_rn(o0, o1), h1 = __floats2half2_rn(o2, o3);
            __half2 h2 = __floats2half2_rn(o4, o5), h3 = __floats2half2_rn(o6, o7);
            uint4 pack;
            pack.x = *(u32*)&h0; pack.y = *(u32*)&h1; pack.z = *(u32*)&h2; pack.w = *(u32*)&h3;
            *(uint4*)((__half*)outp + (size_t)node * 256 + lane * 8) = pack;
        } else {
            float* op = (float*)outp + (size_t)node * 256 + lane * 8;
            *(float4*)op = make_float4(o0, o1, o2, o3);
            *(float4*)(op + 4) = make_float4(o4, o5, o6, o7);
        }
    } else {  // C == 16
        float2 acc = make_float2(0.f, 0.f);
        int j = base;
        for (; j + 4 <= end; j += 4) {
            int s0 = colsrc[j], s1 = colsrc[j + 1], s2 = colsrc[j + 2], s3 = colsrc[j + 3];
            float e0 = __ldg(aS + (j + 0) * 4 + myhead);
            float e1 = __ldg(aS + (j + 1) * 4 + myhead);
            float e2 = __ldg(aS + (j + 2) * 4 + myhead);
            float e3 = __ldg(aS + (j + 3) * 4 + myhead);
            float2 f0 = __half22float2(__ldg((const __half2*)(hh + (size_t)s0 * 64) + lane));
            float2 f1 = __half22float2(__ldg((const __half2*)(hh + (size_t)s1 * 64) + lane));
            float2 f2 = __half22float2(__ldg((const __half2*)(hh + (size_t)s2 * 64) + lane));
            float2 f3 = __half22float2(__ldg((const __half2*)(hh + (size_t)s3 * 64) + lane));
            acc.x = fmaf(f0.x, e0, acc.x); acc.y = fmaf(f0.y, e0, acc.y);
            acc.x = fmaf(f1.x, e1, acc.x); acc.y = fmaf(f1.y, e1, acc.y);
            acc.x = fmaf(f2.x, e2, acc.x); acc.y = fmaf(f2.y, e2, acc.y);
            acc.x = fmaf(f3.x, e3, acc.x); acc.y = fmaf(f3.y, e3, acc.y);
        }
        for (; j < end; j++) {
            int s = colsrc[j];
            float ew = __ldg(aS + j * 4 + myhead);
            float2 f = __half22float2(__ldg((const __half2*)(hh + (size_t)s * 64) + lane));
            acc.x = fmaf(f.x, ew, acc.x);
            acc.y = fmaf(f.y, ew, acc.y);
        }
        float2 bv = *(const float2*)(bias + 2 * lane);
        float ox = acc.x * iv + bv.x;
        float oy = acc.y * iv + bv.y;
        if (sizeof(OutT) == 2) {
            *(__half2*)((__half*)outp + (size_t)node * 64 + 2 * lane) = __floats2half2_rn(ox, oy);
        } else {
            *(float2*)((float*)outp + (size_t)node * 64 + 2 * lane) = make_float2(ox, oy);
        }
    }
}

// ---------------- launch ----------------
extern "C" void kernel_launch(void* const* d_in, const int* in_sizes, int n_in,
                              void* d_out, int out_size) {
    const float* x   = (const float*)d_in[0];
    const int*   ei  = (const int*)d_in[1];
    const float* ts  = (const float*)d_in[2];
    const float* tw  = (const float*)d_in[3];
    const float* tb  = (const float*)d_in[4];
    const float* W0  = (const float*)d_in[5];
    const float* as0 = (const float*)d_in[6];
    const float* ad0 = (const float*)d_in[7];
    const float* le0 = (const float*)d_in[8];
    const float* ae0 = (const float*)d_in[9];
    const float* b0  = (const float*)d_in[10];
    const float* W1  = (const float*)d_in[11];
    const float* as1 = (const float*)d_in[12];
    const float* ad1 = (const float*)d_in[13];
    const float* le1 = (const float*)d_in[14];
    const float* ae1 = (const float*)d_in[15];
    const float* b1  = (const float*)d_in[16];

    int n = in_sizes[0] / 128;   // 50000
    int e = in_sizes[2];         // 800000
    int tot = e + n;
    const int* srcp = ei;
    const int* dstp = ei + e;

    void *p_xh, *p_w0h, *p_w1h, *p_hh0, *p_out0h, *p_hh1;
    void *p_aE0, *p_aE1, *p_aE0c, *p_aE1c, *p_aCSR, *p_ss0, *p_sd0, *p_ss1, *p_sd1;
    void *p_deg, *p_rowptr, *p_cursor, *p_colsrc, *p_bsum, *p_boff;
    cudaGetSymbolAddress(&p_xh, g_xh);
    cudaGetSymbolAddress(&p_w0h, g_w0h);
    cudaGetSymbolAddress(&p_w1h, g_w1h);
    cudaGetSymbolAddress(&p_hh0, g_hh0);
    cudaGetSymbolAddress(&p_out0h, g_out0h);
    cudaGetSymbolAddress(&p_hh1, g_hh1);
    cudaGetSymbolAddress(&p_aE0, g_alphaE0);
    cudaGetSymbolAddress(&p_aE1, g_alphaE1);
    cudaGetSymbolAddress(&p_aE0c, g_aE0c);
    cudaGetSymbolAddress(&p_aE1c, g_aE1c);
    cudaGetSymbolAddress(&p_aCSR, g_aCSR);
    cudaGetSymbolAddress(&p_ss0, g_ss0);
    cudaGetSymbolAddress(&p_sd0, g_sd0);
    cudaGetSymbolAddress(&p_ss1, g_ss1);
    cudaGetSymbolAddress(&p_sd1, g_sd1);
    cudaGetSymbolAddress(&p_deg, g_deg);
    cudaGetSymbolAddress(&p_rowptr, g_rowptr);
    cudaGetSymbolAddress(&p_cursor, g_cursor);
    cudaGetSymbolAddress(&p_colsrc, g_colsrc);
    cudaGetSymbolAddress(&p_bsum, g_blocksum);
    cudaGetSymbolAddress(&p_boff, g_blockoff);

    __half* xh     = (__half*)p_xh;
    __half* w0h    = (__half*)p_w0h;
    __half* w1h    = (__half*)p_w1h;
    __half* hh0    = (__half*)p_hh0;
    __half* out0h  = (__half*)p_out0h;
    __half* hh1    = (__half*)p_hh1;
    float4* aE0    = (float4*)p_aE0;
    float4* aE1    = (float4*)p_aE1;
    float4* aE0c   = (float4*)p_aE0c;
    float4* aE1c   = (float4*)p_aE1c;
    float4* aCSR   = (float4*)p_aCSR;
    float4* ss0    = (float4*)p_ss0;
    float4* sd0    = (float4*)p_sd0;
    float4* ss1    = (float4*)p_ss1;
    float4* sd1    = (float4*)p_sd1;
    int* deg       = (int*)p_deg;
    int* rowptr    = (int*)p_rowptr;
    int* cursor    = (int*)p_cursor;
    int* colsrc    = (int*)p_colsrc;
    int* bsum      = (int*)p_bsum;
    int* boff      = (int*)p_boff;

    int nb = (n + SCAN_TILE - 1) / SCAN_TILE;   // 13 for n=50000

    setup_kernel<<<1 + 512, 256>>>(le0, ae0, le1, ae1, x, W0, W1, deg, xh, w0h, w1h, n);
    edge_feat_kernel<<<(e + 511) / 512, 256>>>(ts, tw, tb, dstp, deg, aE0, aE1, e);
    hgemm_kernel<<<dim3(256 / 64, (n + 127) / 128), 256>>>(xh, w0h, hh0, n, 128, 256);
    scan1_kernel<<<nb, 1024>>>(deg, rowptr, bsum, n);
    scan2_kernel<<<1, 32>>>(bsum, boff, rowptr, n, nb);
    scan3_kernel<<<(n + 255) / 256, 256>>>(rowptr, cursor, boff, n);
    scatter_kernel<<<(tot + 255) / 256, 256>>>(srcp, dstp, aE0, aE1, cursor, colsrc,
                                               aE0c, aE1c, e, n);
    score_kernel<64><<<(n * 32 + 255) / 256, 256>>>(hh0, as0, ad0, (float*)ss0, (float*)sd0, n);
    agg_kernel<64, __half><<<(n * 32 + 255) / 256, 256>>>(rowptr, colsrc, aE0c, ss0, sd0,
                                                          hh0, b0, aCSR, out0h, n);
    hgemm_kernel<<<dim3(64 / 64, (n + 127) / 128), 256>>>(out0h, w1h, hh1, n, 256, 64);
    score_kernel<16><<<(n * 32 + 255) / 256, 256>>>(hh1, as1, ad1, (float*)ss1, (float*)sd1, n);
    agg_kernel<16, float><<<(n * 32 + 255) / 256, 256>>>(rowptr, colsrc, aE1c, ss1, sd1,
                                                         hh1, b1, aCSR, (float*)d_out, n);
}

// round 14
// speedup vs baseline: 1.7973x; 1.1165x over previous
#include <cuda_runtime.h>
#include <cuda_fp16.h>
#include <stdint.h>
#include <math.h>

typedef unsigned int u32;
typedef unsigned long long u64;

#define NN 50000
#define EE 800000
#define ET (EE + NN)
#define TDIM 64
#define SCAN_TILE 4096   // 1024 threads x 4 elems

// ---------------- scratch (static device globals; no allocation) ----------------
__device__ int    g_deg[NN];
__device__ int    g_rowptr[NN + 1];
__device__ int    g_cursor[NN];
__device__ int    g_blocksum[64];
__device__ int    g_colsrc[ET];
__device__ float4 g_alphaE0[EE];
__device__ float4 g_alphaE1[EE];
__device__ float4 g_aE0c[ET];
__device__ float4 g_aE1c[ET];
__device__ float4 g_aCSR[ET];
__device__ __half g_xh[(size_t)NN * 128];
__device__ __half g_w0h[128 * 256];
__device__ __half g_w1h[256 * 64];
__device__ __half g_hh0[(size_t)NN * 256];
__device__ __half g_out0h[(size_t)NN * 256];
__device__ __half g_hh1[(size_t)NN * 64];
__device__ float4 g_ss0[NN], g_sd0[NN], g_ss1[NN], g_sd1[NN];
__device__ float4 g_ve0[TDIM];
__device__ float4 g_ve1[TDIM];
__device__ float4 g_self0, g_self1;

// ---------------- PTX helpers ----------------
__device__ __forceinline__ void ldsm_x4(u32& r0, u32& r1, u32& r2, u32& r3, u32 addr) {
    asm volatile("ldmatrix.sync.aligned.m8n8.x4.shared.b16 {%0,%1,%2,%3}, [%4];"
                 : "=r"(r0), "=r"(r1), "=r"(r2), "=r"(r3) : "r"(addr));
}
__device__ __forceinline__ void ldsm_x4_trans(u32& r0, u32& r1, u32& r2, u32& r3, u32 addr) {
    asm volatile("ldmatrix.sync.aligned.m8n8.x4.trans.shared.b16 {%0,%1,%2,%3}, [%4];"
                 : "=r"(r0), "=r"(r1), "=r"(r2), "=r"(r3) : "r"(addr));
}
__device__ __forceinline__ void mma16816(float& c0, float& c1, float& c2, float& c3,
                                         u32 a0, u32 a1, u32 a2, u32 a3,
                                         u32 b0, u32 b1) {
    asm volatile(
        "mma.sync.aligned.m16n8k16.row.col.f32.f16.f16.f32 "
        "{%0,%1,%2,%3}, {%4,%5,%6,%7}, {%8,%9}, {%0,%1,%2,%3};"
        : "+f"(c0), "+f"(c1), "+f"(c2), "+f"(c3)
        : "r"(a0), "r"(a1), "r"(a2), "r"(a3), "r"(b0), "r"(b1));
}
__device__ __forceinline__ void cp_async16(u32 saddr, const void* gaddr, int src_bytes) {
    asm volatile("cp.async.ca.shared.global [%0], [%1], 16, %2;"
                 :: "r"(saddr), "l"(gaddr), "r"(src_bytes));
}
#define CP_COMMIT()  asm volatile("cp.async.commit_group;")
#define CP_WAIT(n)   asm volatile("cp.async.wait_group %0;" :: "n"(n))

__device__ __forceinline__ void ffma2(u64& d, u64 a, u64 b) {
    asm("fma.rn.f32x2 %0, %1, %2, %0;" : "+l"(d) : "l"(a), "l"(b));
}
__device__ __forceinline__ u64 pack2(float lo, float hi) {
    u64 r;
    asm("mov.b64 %0, {%1, %2};" : "=l"(r) : "f"(lo), "f"(hi));
    return r;
}
__device__ __forceinline__ void unpack2(float& lo, float& hi, u64 v) {
    asm("mov.b64 {%0, %1}, %2;" : "=f"(lo), "=f"(hi) : "l"(v));
}

// ---------------- setup: prep (block 0) + deg init + 3x fp32->fp16 cvt ----------------
__global__ void setup_kernel(const float* __restrict__ le0, const float* __restrict__ ae0,
                             const float* __restrict__ le1, const float* __restrict__ ae1,
                             const float* __restrict__ x, const float* __restrict__ W0,
                             const float* __restrict__ W1,
                             int* __restrict__ deg,
                             __half* __restrict__ xh, __half* __restrict__ w0h,
                             __half* __restrict__ w1h, int n) {
    int tid = threadIdx.x;
    if (blockIdx.x == 0) {
        int td = tid >> 2, hh = tid & 3;
        float s0 = 0.f;
        for (int c = 0; c < 64; c++) s0 += le0[td * 256 + hh * 64 + c] * ae0[hh * 64 + c];
        ((float*)g_ve0)[td * 4 + hh] = s0;
        float s1 = 0.f;
        for (int c = 0; c < 16; c++) s1 += le1[td * 64 + hh * 16 + c] * ae1[hh * 16 + c];
        ((float*)g_ve1)[td * 4 + hh] = s1;
        __syncthreads();
        if (td == 0) {
            float a = 0.f, b = 0.f;
            for (int t2 = 0; t2 < TDIM; t2++) {
                a += ((float*)g_ve0)[t2 * 4 + hh];
                b += ((float*)g_ve1)[t2 * 4 + hh];
            }
            ((float*)&g_self0)[hh] = a;
            ((float*)&g_self1)[hh] = b;
        }
        return;
    }
    int gid = (blockIdx.x - 1) * 256 + tid;
    int stride = (gridDim.x - 1) * 256;
    for (int i = gid; i < n; i += stride) deg[i] = 1;
    int nx4 = n * 32;
    for (int i = gid; i < nx4; i += stride) {
        float4 v = *(const float4*)(x + (size_t)i * 4);
        *(__half2*)(xh + (size_t)i * 4) = __floats2half2_rn(v.x, v.y);
        *(__half2*)(xh + (size_t)i * 4 + 2) = __floats2half2_rn(v.z, v.w);
    }
    for (int i = gid; i < 8192; i += stride) {
        float4 v = *(const float4*)(W0 + (size_t)i * 4);
        *(__half2*)(w0h + (size_t)i * 4) = __floats2half2_rn(v.x, v.y);
        *(__half2*)(w0h + (size_t)i * 4 + 2) = __floats2half2_rn(v.z, v.w);
    }
    for (int i = gid; i < 4096; i += stride) {
        float4 v = *(const float4*)(W1 + (size_t)i * 4);
        *(__half2*)(w1h + (size_t)i * 4) = __floats2half2_rn(v.x, v.y);
        *(__half2*)(w1h + (size_t)i * 4 + 2) = __floats2half2_rn(v.z, v.w);
    }
}

// ---------------- per-edge time features + fused deg count ----------------
__global__ void edge_feat_kernel(const float* __restrict__ ts,
                                 const float* __restrict__ tw,
                                 const float* __restrict__ tb,
                                 const int* __restrict__ dst,
                                 int* __restrict__ deg,
                                 float4* __restrict__ aE0, float4* __restrict__ aE1,
                                 int e) {
    __shared__ float2 swb[TDIM];
    __shared__ u64 pv0a[TDIM], pv0b[TDIM], pv1a[TDIM], pv1b[TDIM];
    int tid = threadIdx.x;
    if (tid < TDIM) {
        swb[tid] = make_float2(tw[tid], tb[tid]);
        float4 v0 = g_ve0[tid];
        float4 v1 = g_ve1[tid];
        pv0a[tid] = pack2(v0.x, v0.y);
        pv0b[tid] = pack2(v0.z, v0.w);
        pv1a[tid] = pack2(v1.x, v1.y);
        pv1b[tid] = pack2(v1.z, v1.w);
    }
    __syncthreads();
    int iA = blockIdx.x * 512 + tid;
    int iB = iA + 256;
    float tA = (iA < e) ? ts[iA] : 0.f;
    float tB = (iB < e) ? ts[iB] : 0.f;
    if (iA < e) atomicAdd(&deg[dst[iA]], 1);
    if (iB < e) atomicAdd(&deg[dst[iB]], 1);
    u64 A0xy = 0, A0zw = 0, A1xy = 0, A1zw = 0;
    u64 B0xy = 0, B0zw = 0, B1xy = 0, B1zw = 0;
    #pragma unroll 8
    for (int td = 0; td < TDIM; td++) {
        float2 wb = swb[td];
        float aA = fabsf(__cosf(fmaf(tA, wb.x, wb.y)));
        float aB = fabsf(__cosf(fmaf(tB, wb.x, wb.y)));
        u64 ccA = pack2(aA, aA);
        u64 ccB = pack2(aB, aB);
        u64 v0a = pv0a[td], v0b = pv0b[td], v1a = pv1a[td], v1b = pv1b[td];
        ffma2(A0xy, ccA, v0a); ffma2(A0zw, ccA, v0b);
        ffma2(A1xy, ccA, v1a); ffma2(A1zw, ccA, v1b);
        ffma2(B0xy, ccB, v0a); ffma2(B0zw, ccB, v0b);
        ffma2(B1xy, ccB, v1a); ffma2(B1zw, ccB, v1b);
    }
    if (iA < e) {
        float4 r0, r1;
        unpack2(r0.x, r0.y, A0xy); unpack2(r0.z, r0.w, A0zw);
        unpack2(r1.x, r1.y, A1xy); unpack2(r1.z, r1.w, A1zw);
        aE0[iA] = r0; aE1[iA] = r1;
    }
    if (iB < e) {
        float4 r0, r1;
        unpack2(r0.x, r0.y, B0xy); unpack2(r0.z, r0.w, B0zw);
        unpack2(r1.x, r1.y, B1xy); unpack2(r1.z, r1.w, B1zw);
        aE0[iB] = r0; aE1[iB] = r1;
    }
}

// ---------------- multi-block scan, phase 1 ----------------
__global__ void scan1_kernel(const int* __restrict__ deg, int* __restrict__ rowptr,
                             int* __restrict__ blocksum, int n) {
    __shared__ int wsum[32];
    int t = threadIdx.x;
    int lane = t & 31, wid = t >> 5;
    int base = blockIdx.x * SCAN_TILE + t * 4;
    int4 v = make_int4(0, 0, 0, 0);
    if (base + 3 < n) {
        v = *(const int4*)(deg + base);
    } else {
        if (base + 0 < n) v.x = deg[base + 0];
        if (base + 1 < n) v.y = deg[base + 1];
        if (base + 2 < n) v.z = deg[base + 2];
        if (base + 3 < n) v.w = deg[base + 3];
    }
    int mysum = v.x + v.y + v.z + v.w;
    int incl = mysum;
    #pragma unroll
    for (int off = 1; off < 32; off <<= 1) {
        int x = __shfl_up_sync(0xffffffffu, incl, off);
        if (lane >= off) incl += x;
    }
    if (lane == 31) wsum[wid] = incl;
    __syncthreads();
    if (wid == 0) {
        int w = wsum[lane];
        #pragma unroll
        for (int off = 1; off < 32; off <<= 1) {
            int x = __shfl_up_sync(0xffffffffu, w, off);
            if (lane >= off) w += x;
        }
        wsum[lane] = w;
    }
    __syncthreads();
    int excl = (wid ? wsum[wid - 1] : 0) + incl - mysum;
    int4 o;
    o.x = excl;
    o.y = o.x + v.x;
    o.z = o.y + v.y;
    o.w = o.z + v.z;
    if (base + 3 < n) {
        *(int4*)(rowptr + base) = o;
    } else {
        if (base + 0 < n) rowptr[base + 0] = o.x;
        if (base + 1 < n) rowptr[base + 1] = o.y;
        if (base + 2 < n) rowptr[base + 2] = o.z;
        if (base + 3 < n) rowptr[base + 3] = o.w;
    }
    if (t == 1023) blocksum[blockIdx.x] = wsum[31];
}

// ---------------- phase 2+3 fused: every block re-scans block sums, applies offset ----
__global__ void scan3_kernel(int* __restrict__ rowptr, int* __restrict__ cursor,
                             const int* __restrict__ blocksum, int n, int nb) {
    __shared__ int soff[33];
    int t = threadIdx.x;
    if (t < 32) {
        int v = (t < nb) ? blocksum[t] : 0;
        int incl = v;
        #pragma unroll
        for (int off = 1; off < 32; off <<= 1) {
            int x = __shfl_up_sync(0xffffffffu, incl, off);
            if (t >= off) incl += x;
        }
        soff[t] = incl - v;
        if (t == 31) soff[32] = incl;   // total
    }
    __syncthreads();
    int i = blockIdx.x * blockDim.x + t;
    if (i < n) {
        int val = rowptr[i] + soff[i / SCAN_TILE];
        rowptr[i] = val;
        cursor[i] = val;
    }
    if (blockIdx.x == 0 && t == 0) rowptr[n] = soff[32];
}

// ---------------- scatter: build colsrc + permute aE into CSR order ----------------
__global__ void scatter_kernel(const int* __restrict__ src, const int* __restrict__ dst,
                               const float4* __restrict__ aE0, const float4* __restrict__ aE1,
                               int* cursor, int* colsrc,
                               float4* __restrict__ aE0c, float4* __restrict__ aE1c,
                               int e, int n) {
    int i = blockIdx.x * blockDim.x + threadIdx.x;
    int tot = e + n;
    if (i >= tot) return;
    if (i < e) {
        int d = dst[i];
        int p = atomicAdd(&cursor[d], 1);
        colsrc[p] = src[i];
        aE0c[p] = aE0[i];
        aE1c[p] = aE1[i];
    } else {
        int node = i - e;
        int p = atomicAdd(&cursor[node], 1);
        colsrc[p] = node;
        aE0c[p] = g_self0;
        aE1c[p] = g_self1;
    }
}

// ---------------- fp16 tensor-core GEMM (cp.async 2-stage) + optional fused score ------
// SCORE=true requires N-tile (BN=64) == head width C=64: head = blockIdx.x.
template <bool SCORE>
__global__ void hgemm_kernel(const __half* __restrict__ A, const __half* __restrict__ B,
                             __half* __restrict__ C, int M, int K, int N,
                             const float* __restrict__ asrc, const float* __restrict__ adst,
                             float* __restrict__ ssrc, float* __restrict__ sdst) {
    __shared__ __half As[2][128][40];
    __shared__ __half Bs[2][32][72];
    __shared__ float2 sred[128];
    const int AS_B = 128 * 40 * 2;
    const int BS_B = 32 * 72 * 2;
    int bm = blockIdx.y * 128, bn = blockIdx.x * 64;
    int tid = threadIdx.x;
    int wid = tid >> 5, lane = tid & 31;
    int wm = (wid >> 1) * 32, wn = (wid & 1) * 32;
    float acc[2][4][4];
    #pragma unroll
    for (int mt = 0; mt < 2; mt++)
        #pragma unroll
        for (int nt = 0; nt < 4; nt++)
            #pragma unroll
            for (int r = 0; r < 4; r++) acc[mt][nt][r] = 0.f;

    u32 as_base = (u32)__cvta_generic_to_shared(&As[0][0][0]);
    u32 bs_base = (u32)__cvta_generic_to_shared(&Bs[0][0][0]);

    int a_row0 = tid >> 2, a_c8 = (tid & 3) * 8;
    int b_row = tid >> 3, b_c8 = (tid & 7) * 8;

    {
        #pragma unroll
        for (int it = 0; it < 2; it++) {
            int row = a_row0 + it * 64;
            int gm = bm + row;
            int ok = (gm < M);
            const void* g = A + (size_t)(ok ? gm : 0) * K + a_c8;
            cp_async16(as_base + (u32)(row * 40 + a_c8) * 2, g, ok ? 16 : 0);
        }
        cp_async16(bs_base + (u32)(b_row * 72 + b_c8) * 2,
                   B + (size_t)b_row * N + bn + b_c8, 16);
        CP_COMMIT();
    }

    int KT = K >> 5;
    for (int kt = 0; kt < KT; kt++) {
        if (kt + 1 < KT) {
            int st = (kt + 1) & 1;
            int k0 = (kt + 1) * 32;
            #pragma unroll
            for (int it = 0; it < 2; it++) {
                int row = a_row0 + it * 64;
                int gm = bm + row;
                int ok = (gm < M);
                const void* g = A + (size_t)(ok ? gm : 0) * K + k0 + a_c8;
                cp_async16(as_base + (u32)(st * AS_B) + (u32)(row * 40 + a_c8) * 2, g, ok ? 16 : 0);
            }
            cp_async16(bs_base + (u32)(st * BS_B) + (u32)(b_row * 72 + b_c8) * 2,
                       B + (size_t)(k0 + b_row) * N + bn + b_c8, 16);
            CP_COMMIT();
            CP_WAIT(1);
        } else {
            CP_WAIT(0);
        }
        __syncthreads();
        u32 ab = as_base + (u32)((kt & 1) * AS_B);
        u32 bb = bs_base + (u32)((kt & 1) * BS_B);
        #pragma unroll
        for (int kk = 0; kk < 32; kk += 16) {
            u32 a0[4], a1[4], b0[4], b1[4];
            {
                int arow = wm + (lane & 15);
                int acol = kk + (lane >> 4) * 8;
                ldsm_x4(a0[0], a0[1], a0[2], a0[3], ab + (u32)(arow * 40 + acol) * 2);
            }
            {
                int arow = wm + 16 + (lane & 15);
                int acol = kk + (lane >> 4) * 8;
                ldsm_x4(a1[0], a1[1], a1[2], a1[3], ab + (u32)(arow * 40 + acol) * 2);
            }
            {
                int brow = kk + (lane & 15);
                int bcol = wn + (lane >> 4) * 8;
                ldsm_x4_trans(b0[0], b0[1], b0[2], b0[3], bb + (u32)(brow * 72 + bcol) * 2);
            }
            {
                int brow = kk + (lane & 15);
                int bcol = wn + 16 + (lane >> 4) * 8;
                ldsm_x4_trans(b1[0], b1[1], b1[2], b1[3], bb + (u32)(brow * 72 + bcol) * 2);
            }
            #pragma unroll
            for (int mt = 0; mt < 2; mt++) {
                u32* am = (mt == 0) ? a0 : a1;
                mma16816(acc[mt][0][0], acc[mt][0][1], acc[mt][0][2], acc[mt][0][3],
                         am[0], am[1], am[2], am[3], b0[0], b0[1]);
                mma16816(acc[mt][1][0], acc[mt][1][1], acc[mt][1][2], acc[mt][1][3],
                         am[0], am[1], am[2], am[3], b0[2], b0[3]);
                mma16816(acc[mt][2][0], acc[mt][2][1], acc[mt][2][2], acc[mt][2][3],
                         am[0], am[1], am[2], am[3], b1[0], b1[1]);
                mma16816(acc[mt][3][0], acc[mt][3][1], acc[mt][3][2], acc[mt][3][3],
                         am[0], am[1], am[2], am[3], b1[2], b1[3]);
            }
        }
        __syncthreads();
    }
    // store C
    #pragma unroll
    for (int mt = 0; mt < 2; mt++) {
        #pragma unroll
        for (int r = 0; r < 2; r++) {
            int row = bm + wm + mt * 16 + r * 8 + (lane >> 2);
            if (row < M) {
                #pragma unroll
                for (int nt = 0; nt < 4; nt++) {
                    __half2 h = __floats2half2_rn(acc[mt][nt][r * 2 + 0], acc[mt][nt][r * 2 + 1]);
                    *(__half2*)(C + (size_t)row * N + bn + wn + nt * 8 + (lane & 3) * 2) = h;
                }
            }
        }
    }
    if (SCORE) {
        int head = blockIdx.x;          // BN == C == 64
        // per-thread column weights: cols bn + wn + nt*8 + (lane&3)*2 + c
        float asv[8], adv[8];
        #pragma unroll
        for (int nt = 0; nt < 4; nt++)
            #pragma unroll
            for (int c = 0; c < 2; c++) {
                int col = bn + wn + nt * 8 + (lane & 3) * 2 + c;
                asv[nt * 2 + c] = __ldg(asrc + col);
                adv[nt * 2 + c] = __ldg(adst + col);
            }
        float spv[4], dpv[4];           // [mt*2 + r]
        #pragma unroll
        for (int mt = 0; mt < 2; mt++)
            #pragma unroll
            for (int r = 0; r < 2; r++) {
                float sp = 0.f, dp = 0.f;
                #pragma unroll
                for (int nt = 0; nt < 4; nt++)
                    #pragma unroll
                    for (int c = 0; c < 2; c++) {
                        float v = acc[mt][nt][r * 2 + c];
                        sp = fmaf(v, asv[nt * 2 + c], sp);
                        dp = fmaf(v, adv[nt * 2 + c], dp);
                    }
                // reduce over lane&3 group (4 consecutive lanes)
                sp += __shfl_down_sync(0xffffffffu, sp, 2, 4);
                sp += __shfl_down_sync(0xffffffffu, sp, 1, 4);
                dp += __shfl_down_sync(0xffffffffu, dp, 2, 4);
                dp += __shfl_down_sync(0xffffffffu, dp, 1, 4);
                spv[mt * 2 + r] = sp;
                dpv[mt * 2 + r] = dp;
            }
        // cross warp-pair reduce: wn==32 warp writes, wn==0 warp adds
        if ((lane & 3) == 0 && (wid & 1)) {
            #pragma unroll
            for (int mt = 0; mt < 2; mt++)
                #pragma unroll
                for (int r = 0; r < 2; r++) {
                    int rl = wm + mt * 16 + r * 8 + (lane >> 2);
                    sred[rl] = make_float2(spv[mt * 2 + r], dpv[mt * 2 + r]);
                }
        }
        __syncthreads();
        if ((lane & 3) == 0 && !(wid & 1)) {
            #pragma unroll
            for (int mt = 0; mt < 2; mt++)
                #pragma unroll
                for (int r = 0; r < 2; r++) {
                    int rl = wm + mt * 16 + r * 8 + (lane >> 2);
                    float2 o = sred[rl];
                    int row = bm + rl;
                    if (row < M) {
                        ssrc[row * 4 + head] = spv[mt * 2 + r] + o.x;
                        sdst[row * 4 + head] = dpv[mt * 2 + r] + o.y;
                    }
                }
        }
    }
}

// ---------------- coalesced per-(node,head) attention scores (layer1 only) ------------
template <int C>
__global__ void score_kernel(const __half* __restrict__ h, const float* __restrict__ asrc,
                             const float* __restrict__ adst, float* __restrict__ ssrc,
                             float* __restrict__ sdst, int n) {
    int warp = (blockIdx.x * blockDim.x + threadIdx.x) >> 5;
    int lane = threadIdx.x & 31;
    if (warp >= n) return;
    float sp, dp;
    float2 f = __half22float2(__ldg((const __half2*)(h + (size_t)warp * 64) + lane));
    int c0 = lane * 2;
    sp = fmaf(f.x, __ldg(asrc + c0), 0.f);
    sp = fmaf(f.y, __ldg(asrc + c0 + 1), sp);
    dp = fmaf(f.x, __ldg(adst + c0), 0.f);
    dp = fmaf(f.y, __ldg(adst + c0 + 1), dp);
    #pragma unroll
    for (int off = 4; off; off >>= 1) {
        sp += __shfl_down_sync(0xffffffffu, sp, off, 8);
        dp += __shfl_down_sync(0xffffffffu, dp, off, 8);
    }
    if ((lane & 7) == 0) {
        int head = lane >> 3;
        ssrc[warp * 4 + head] = sp;
        sdst[warp * 4 + head] = dp;
    }
}

// ---------------- 2-pass softmax + aggregation, warp/node, 4-edge unroll ----------------
template <int C, typename OutT>
__global__ void agg_kernel(const int* __restrict__ rowptr, const int* __restrict__ colsrc,
                           const float4* __restrict__ aEc,
                           const float4* __restrict__ ssrc, const float4* __restrict__ sdst,
                           const __half* __restrict__ hh, const float* __restrict__ bias,
                           float4* __restrict__ aCSR, OutT* __restrict__ outp, int n_nodes) {
    int warp = (blockIdx.x * blockDim.x + threadIdx.x) >> 5;
    int lane = threadIdx.x & 31;
    if (warp >= n_nodes) return;
    int node = warp;
    int base = rowptr[node], end = rowptr[node + 1];
    float4 sd = __ldg(sdst + node);
    int myhead = lane >> 3;
    float t0 = 0.f, t1 = 0.f, t2 = 0.f, t3 = 0.f;
    for (int j = base + lane; j < end; j += 32) {
        int s = colsrc[j];
        float4 ss = __ldg(ssrc + s);
        float4 ae = __ldg(aEc + j);
        float a0 = ss.x + sd.x + ae.x; a0 = a0 >= 0.f ? a0 : 0.2f * a0;
        float a1 = ss.y + sd.y + ae.y; a1 = a1 >= 0.f ? a1 : 0.2f * a1;
        float a2 = ss.z + sd.z + ae.z; a2 = a2 >= 0.f ? a2 : 0.2f * a2;
        float a3 = ss.w + sd.w + ae.w; a3 = a3 >= 0.f ? a3 : 0.2f * a3;
        float e0 = __expf(a0), e1 = __expf(a1);
        float e2 = __expf(a2), e3 = __expf(a3);
        aCSR[j] = make_float4(e0, e1, e2, e3);
        t0 += e0; t1 += e1; t2 += e2; t3 += e3;
    }
    #pragma unroll
    for (int off = 16; off; off >>= 1) {
        t0 += __shfl_xor_sync(0xffffffffu, t0, off);
        t1 += __shfl_xor_sync(0xffffffffu, t1, off);
        t2 += __shfl_xor_sync(0xffffffffu, t2, off);
        t3 += __shfl_xor_sync(0xffffffffu, t3, off);
    }
    float iv = 1.f / ((myhead == 0 ? t0 : myhead == 1 ? t1 : myhead == 2 ? t2 : t3) + 1e-16f);
    __syncwarp();
    const float* aS = (const float*)aCSR;
    if (C == 64) {
        float accA[8];
        #pragma unroll
        for (int k = 0; k < 8; k++) accA[k] = 0.f;
        int j = base;
        for (; j + 4 <= end; j += 4) {
            int s0 = colsrc[j], s1 = colsrc[j + 1], s2 = colsrc[j + 2], s3 = colsrc[j + 3];
            float e0 = __ldg(aS + (j + 0) * 4 + myhead);
            float e1 = __ldg(aS + (j + 1) * 4 + myhead);
            float e2 = __ldg(aS + (j + 2) * 4 + myhead);
            float e3 = __ldg(aS + (j + 3) * 4 + myhead);
            uint4 r0 = __ldg((const uint4*)(hh + (size_t)s0 * 256) + lane);
            uint4 r1 = __ldg((const uint4*)(hh + (size_t)s1 * 256) + lane);
            uint4 r2 = __ldg((const uint4*)(hh + (size_t)s2 * 256) + lane);
            uint4 r3 = __ldg((const uint4*)(hh + (size_t)s3 * 256) + lane);
            #pragma unroll
            for (int q = 0; q < 4; q++) {
                uint4 r = q == 0 ? r0 : q == 1 ? r1 : q == 2 ? r2 : r3;
                float ew = q == 0 ? e0 : q == 1 ? e1 : q == 2 ? e2 : e3;
                float2 f0 = __half22float2(*(__half2*)&r.x), f1 = __half22float2(*(__half2*)&r.y);
                float2 f2 = __half22float2(*(__half2*)&r.z), f3 = __half22float2(*(__half2*)&r.w);
                accA[0] = fmaf(f0.x, ew, accA[0]); accA[1] = fmaf(f0.y, ew, accA[1]);
                accA[2] = fmaf(f1.x, ew, accA[2]); accA[3] = fmaf(f1.y, ew, accA[3]);
                accA[4] = fmaf(f2.x, ew, accA[4]); accA[5] = fmaf(f2.y, ew, accA[5]);
                accA[6] = fmaf(f3.x, ew, accA[6]); accA[7] = fmaf(f3.y, ew, accA[7]);
            }
        }
        for (; j < end; j++) {
            int s = colsrc[j];
            float ew = __ldg(aS + j * 4 + myhead);
            uint4 r = __ldg((const uint4*)(hh + (size_t)s * 256) + lane);
            float2 f0 = __half22float2(*(__half2*)&r.x), f1 = __half22float2(*(__half2*)&r.y);
            float2 f2 = __half22float2(*(__half2*)&r.z), f3 = __half22float2(*(__half2*)&r.w);
            accA[0] = fmaf(f0.x, ew, accA[0]); accA[1] = fmaf(f0.y, ew, accA[1]);
            accA[2] = fmaf(f1.x, ew, accA[2]); accA[3] = fmaf(f1.y, ew, accA[3]);
            accA[4] = fmaf(f2.x, ew, accA[4]); accA[5] = fmaf(f2.y, ew, accA[5]);
            accA[6] = fmaf(f3.x, ew, accA[6]); accA[7] = fmaf(f3.y, ew, accA[7]);
        }
        float4 bv0 = *(const float4*)(bias + lane * 8);
        float4 bv1 = *(const float4*)(bias + lane * 8 + 4);
        float o0 = accA[0] * iv + bv0.x, o1 = accA[1] * iv + bv0.y;
        float o2 = accA[2] * iv + bv0.z, o3 = accA[3] * iv + bv0.w;
        float o4 = accA[4] * iv + bv1.x, o5 = accA[5] * iv + bv1.y;
        float o6 = accA[6] * iv + bv1.z, o7 = accA[7] * iv + bv1.w;
        if (sizeof(OutT) == 2) {
            __half2 h0 = __floats2half2_rn(o0, o1), h1 = __floats2half2_rn(o2, o3);
            __half2 h2 = __floats2half2_rn(o4, o5), h3 = __floats2half2_rn(o6, o7);
            uint4 pack;
            pack.x = *(u32*)&h0; pack.y = *(u32*)&h1; pack.z = *(u32*)&h2; pack.w = *(u32*)&h3;
            *(uint4*)((__half*)outp + (size_t)node * 256 + lane * 8) = pack;
        } else {
            float* op = (float*)outp + (size_t)node * 256 + lane * 8;
            *(float4*)op = make_float4(o0, o1, o2, o3);
            *(float4*)(op + 4) = make_float4(o4, o5, o6, o7);
        }
    } else {  // C == 16
        float2 acc = make_float2(0.f, 0.f);
        int j = base;
        for (; j + 4 <= end; j += 4) {
            int s0 = colsrc[j], s1 = colsrc[j + 1], s2 = colsrc[j + 2], s3 = colsrc[j + 3];
            float e0 = __ldg(aS + (j + 0) * 4 + myhead);
            float e1 = __ldg(aS + (j + 1) * 4 + myhead);
            float e2 = __ldg(aS + (j + 2) * 4 + myhead);
            float e3 = __ldg(aS + (j + 3) * 4 + myhead);
            float2 f0 = __half22float2(__ldg((const __half2*)(hh + (size_t)s0 * 64) + lane));
            float2 f1 = __half22float2(__ldg((const __half2*)(hh + (size_t)s1 * 64) + lane));
            float2 f2 = __half22float2(__ldg((const __half2*)(hh + (size_t)s2 * 64) + lane));
            float2 f3 = __half22float2(__ldg((const __half2*)(hh + (size_t)s3 * 64) + lane));
            acc.x = fmaf(f0.x, e0, acc.x); acc.y = fmaf(f0.y, e0, acc.y);
            acc.x = fmaf(f1.x, e1, acc.x); acc.y = fmaf(f1.y, e1, acc.y);
            acc.x = fmaf(f2.x, e2, acc.x); acc.y = fmaf(f2.y, e2, acc.y);
            acc.x = fmaf(f3.x, e3, acc.x); acc.y = fmaf(f3.y, e3, acc.y);
        }
        for (; j < end; j++) {
            int s = colsrc[j];
            float ew = __ldg(aS + j * 4 + myhead);
            float2 f = __half22float2(__ldg((const __half2*)(hh + (size_t)s * 64) + lane));
            acc.x = fmaf(f.x, ew, acc.x);
            acc.y = fmaf(f.y, ew, acc.y);
        }
        float2 bv = *(const float2*)(bias + 2 * lane);
        float ox = acc.x * iv + bv.x;
        float oy = acc.y * iv + bv.y;
        if (sizeof(OutT) == 2) {
            *(__half2*)((__half*)outp + (size_t)node * 64 + 2 * lane) = __floats2half2_rn(ox, oy);
        } else {
            *(float2*)((float*)outp + (size_t)node * 64 + 2 * lane) = make_float2(ox, oy);
        }
    }
}

// ---------------- launch ----------------
extern "C" void kernel_launch(void* const* d_in, const int* in_sizes, int n_in,
                              void* d_out, int out_size) {
    const float* x   = (const float*)d_in[0];
    const int*   ei  = (const int*)d_in[1];
    const float* ts  = (const float*)d_in[2];
    const float* tw  = (const float*)d_in[3];
    const float* tb  = (const float*)d_in[4];
    const float* W0  = (const float*)d_in[5];
    const float* as0 = (const float*)d_in[6];
    const float* ad0 = (const float*)d_in[7];
    const float* le0 = (const float*)d_in[8];
    const float* ae0 = (const float*)d_in[9];
    const float* b0  = (const float*)d_in[10];
    const float* W1  = (const float*)d_in[11];
    const float* as1 = (const float*)d_in[12];
    const float* ad1 = (const float*)d_in[13];
    const float* le1 = (const float*)d_in[14];
    const float* ae1 = (const float*)d_in[15];
    const float* b1  = (const float*)d_in[16];

    int n = in_sizes[0] / 128;   // 50000
    int e = in_sizes[2];         // 800000
    int tot = e + n;
    const int* srcp = ei;
    const int* dstp = ei + e;

    void *p_xh, *p_w0h, *p_w1h, *p_hh0, *p_out0h, *p_hh1;
    void *p_aE0, *p_aE1, *p_aE0c, *p_aE1c, *p_aCSR, *p_ss0, *p_sd0, *p_ss1, *p_sd1;
    void *p_deg, *p_rowptr, *p_cursor, *p_colsrc, *p_bsum;
    cudaGetSymbolAddress(&p_xh, g_xh);
    cudaGetSymbolAddress(&p_w0h, g_w0h);
    cudaGetSymbolAddress(&p_w1h, g_w1h);
    cudaGetSymbolAddress(&p_hh0, g_hh0);
    cudaGetSymbolAddress(&p_out0h, g_out0h);
    cudaGetSymbolAddress(&p_hh1, g_hh1);
    cudaGetSymbolAddress(&p_aE0, g_alphaE0);
    cudaGetSymbolAddress(&p_aE1, g_alphaE1);
    cudaGetSymbolAddress(&p_aE0c, g_aE0c);
    cudaGetSymbolAddress(&p_aE1c, g_aE1c);
    cudaGetSymbolAddress(&p_aCSR, g_aCSR);
    cudaGetSymbolAddress(&p_ss0, g_ss0);
    cudaGetSymbolAddress(&p_sd0, g_sd0);
    cudaGetSymbolAddress(&p_ss1, g_ss1);
    cudaGetSymbolAddress(&p_sd1, g_sd1);
    cudaGetSymbolAddress(&p_deg, g_deg);
    cudaGetSymbolAddress(&p_rowptr, g_rowptr);
    cudaGetSymbolAddress(&p_cursor, g_cursor);
    cudaGetSymbolAddress(&p_colsrc, g_colsrc);
    cudaGetSymbolAddress(&p_bsum, g_blocksum);

    __half* xh     = (__half*)p_xh;
    __half* w0h    = (__half*)p_w0h;
    __half* w1h    = (__half*)p_w1h;
    __half* hh0    = (__half*)p_hh0;
    __half* out0h  = (__half*)p_out0h;
    __half* hh1    = (__half*)p_hh1;
    float4* aE0    = (float4*)p_aE0;
    float4* aE1    = (float4*)p_aE1;
    float4* aE0c   = (float4*)p_aE0c;
    float4* aE1c   = (float4*)p_aE1c;
    float4* aCSR   = (float4*)p_aCSR;
    float4* ss0    = (float4*)p_ss0;
    float4* sd0    = (float4*)p_sd0;
    float4* ss1    = (float4*)p_ss1;
    float4* sd1    = (float4*)p_sd1;
    int* deg       = (int*)p_deg;
    int* rowptr    = (int*)p_rowptr;
    int* cursor    = (int*)p_cursor;
    int* colsrc    = (int*)p_colsrc;
    int* bsum      = (int*)p_bsum;

    int nb = (n + SCAN_TILE - 1) / SCAN_TILE;   // 13 for n=50000

    setup_kernel<<<1 + 512, 256>>>(le0, ae0, le1, ae1, x, W0, W1, deg, xh, w0h, w1h, n);
    edge_feat_kernel<<<(e + 511) / 512, 256>>>(ts, tw, tb, dstp, deg, aE0, aE1, e);
    hgemm_kernel<true><<<dim3(256 / 64, (n + 127) / 128), 256>>>(
        xh, w0h, hh0, n, 128, 256, as0, ad0, (float*)ss0, (float*)sd0);
    scan1_kernel<<<nb, 1024>>>(deg, rowptr, bsum, n);
    scan3_kernel<<<(n + 255) / 256, 256>>>(rowptr, cursor, bsum, n, nb);
    scatter_kernel<<<(tot + 255) / 256, 256>>>(srcp, dstp, aE0, aE1, cursor, colsrc,
                                               aE0c, aE1c, e, n);
    agg_kernel<64, __half><<<(n * 32 + 255) / 256, 256>>>(rowptr, colsrc, aE0c, ss0, sd0,
                                                          hh0, b0, aCSR, out0h, n);
    hgemm_kernel<false><<<dim3(64 / 64, (n + 127) / 128), 256>>>(
        out0h, w1h, hh1, n, 256, 64, (const float*)0, (const float*)0, (float*)0, (float*)0);
    score_kernel<16><<<(n * 32 + 255) / 256, 256>>>(hh1, as1, ad1, (float*)ss1, (float*)sd1, n);
    agg_kernel<16, float><<<(n * 32 + 255) / 256, 256>>>(rowptr, colsrc, aE1c, ss1, sd1,
                                                         hh1, b1, aCSR, (float*)d_out, n);
}

// round 15
// speedup vs baseline: 1.8606x; 1.0352x over previous
#include <cuda_runtime.h>
#include <cuda_fp16.h>
#include <stdint.h>
#include <math.h>

typedef unsigned int u32;
typedef unsigned long long u64;

#define NN 50000
#define EE 800000
#define ET (EE + NN)
#define TDIM 64
#define SCAN_TILE 4096   // 1024 threads x 4 elems

// ---------------- scratch (static device globals; no allocation) ----------------
__device__ int    g_deg[NN];
__device__ int    g_rowptr[NN + 1];
__device__ int    g_cursor[NN];
__device__ int    g_blocksum[64];
__device__ int    g_colsrc[ET];
__device__ float4 g_alphaE0[EE];
__device__ float4 g_alphaE1[EE];
__device__ float4 g_aE0c[ET];
__device__ float4 g_aE1c[ET];
__device__ float4 g_aCSR[ET];
__device__ __half g_xh[(size_t)NN * 128];
__device__ __half g_w0h[128 * 256];
__device__ __half g_w1h[256 * 64];
__device__ __half g_hh0[(size_t)NN * 256];
__device__ __half g_out0h[(size_t)NN * 256];
__device__ __half g_hh1[(size_t)NN * 64];
__device__ float4 g_ss0[NN], g_sd0[NN], g_ss1[NN], g_sd1[NN];
__device__ float4 g_ve0[TDIM];
__device__ float4 g_ve1[TDIM];
__device__ float4 g_self0, g_self1;

// ---------------- PTX helpers ----------------
__device__ __forceinline__ void ldsm_x4(u32& r0, u32& r1, u32& r2, u32& r3, u32 addr) {
    asm volatile("ldmatrix.sync.aligned.m8n8.x4.shared.b16 {%0,%1,%2,%3}, [%4];"
                 : "=r"(r0), "=r"(r1), "=r"(r2), "=r"(r3) : "r"(addr));
}
__device__ __forceinline__ void ldsm_x4_trans(u32& r0, u32& r1, u32& r2, u32& r3, u32 addr) {
    asm volatile("ldmatrix.sync.aligned.m8n8.x4.trans.shared.b16 {%0,%1,%2,%3}, [%4];"
                 : "=r"(r0), "=r"(r1), "=r"(r2), "=r"(r3) : "r"(addr));
}
__device__ __forceinline__ void mma16816(float& c0, float& c1, float& c2, float& c3,
                                         u32 a0, u32 a1, u32 a2, u32 a3,
                                         u32 b0, u32 b1) {
    asm volatile(
        "mma.sync.aligned.m16n8k16.row.col.f32.f16.f16.f32 "
        "{%0,%1,%2,%3}, {%4,%5,%6,%7}, {%8,%9}, {%0,%1,%2,%3};"
        : "+f"(c0), "+f"(c1), "+f"(c2), "+f"(c3)
        : "r"(a0), "r"(a1), "r"(a2), "r"(a3), "r"(b0), "r"(b1));
}
__device__ __forceinline__ void cp_async16(u32 saddr, const void* gaddr, int src_bytes) {
    asm volatile("cp.async.ca.shared.global [%0], [%1], 16, %2;"
                 :: "r"(saddr), "l"(gaddr), "r"(src_bytes));
}
#define CP_COMMIT()  asm volatile("cp.async.commit_group;")
#define CP_WAIT(n)   asm volatile("cp.async.wait_group %0;" :: "n"(n))

__device__ __forceinline__ void ffma2(u64& d, u64 a, u64 b) {
    asm("fma.rn.f32x2 %0, %1, %2, %0;" : "+l"(d) : "l"(a), "l"(b));
}
__device__ __forceinline__ u64 pack2(float lo, float hi) {
    u64 r;
    asm("mov.b64 %0, {%1, %2};" : "=l"(r) : "f"(lo), "f"(hi));
    return r;
}
__device__ __forceinline__ void unpack2(float& lo, float& hi, u64 v) {
    asm("mov.b64 {%0, %1}, %2;" : "=f"(lo), "=f"(hi) : "l"(v));
}

// ---------------- setup: prep (block 0) + deg init + 3x fp32->fp16 cvt ----------------
__global__ void setup_kernel(const float* __restrict__ le0, const float* __restrict__ ae0,
                             const float* __restrict__ le1, const float* __restrict__ ae1,
                             const float* __restrict__ x, const float* __restrict__ W0,
                             const float* __restrict__ W1,
                             int* __restrict__ deg,
                             __half* __restrict__ xh, __half* __restrict__ w0h,
                             __half* __restrict__ w1h, int n) {
    int tid = threadIdx.x;
    if (blockIdx.x == 0) {
        int td = tid >> 2, hh = tid & 3;
        float s0 = 0.f;
        for (int c = 0; c < 64; c++) s0 += le0[td * 256 + hh * 64 + c] * ae0[hh * 64 + c];
        ((float*)g_ve0)[td * 4 + hh] = s0;
        float s1 = 0.f;
        for (int c = 0; c < 16; c++) s1 += le1[td * 64 + hh * 16 + c] * ae1[hh * 16 + c];
        ((float*)g_ve1)[td * 4 + hh] = s1;
        __syncthreads();
        if (td == 0) {
            float a = 0.f, b = 0.f;
            for (int t2 = 0; t2 < TDIM; t2++) {
                a += ((float*)g_ve0)[t2 * 4 + hh];
                b += ((float*)g_ve1)[t2 * 4 + hh];
            }
            ((float*)&g_self0)[hh] = a;
            ((float*)&g_self1)[hh] = b;
        }
        return;
    }
    int gid = (blockIdx.x - 1) * 256 + tid;
    int stride = (gridDim.x - 1) * 256;
    for (int i = gid; i < n; i += stride) deg[i] = 1;
    int nx4 = n * 32;
    for (int i = gid; i < nx4; i += stride) {
        float4 v = *(const float4*)(x + (size_t)i * 4);
        *(__half2*)(xh + (size_t)i * 4) = __floats2half2_rn(v.x, v.y);
        *(__half2*)(xh + (size_t)i * 4 + 2) = __floats2half2_rn(v.z, v.w);
    }
    for (int i = gid; i < 8192; i += stride) {
        float4 v = *(const float4*)(W0 + (size_t)i * 4);
        *(__half2*)(w0h + (size_t)i * 4) = __floats2half2_rn(v.x, v.y);
        *(__half2*)(w0h + (size_t)i * 4 + 2) = __floats2half2_rn(v.z, v.w);
    }
    for (int i = gid; i < 4096; i += stride) {
        float4 v = *(const float4*)(W1 + (size_t)i * 4);
        *(__half2*)(w1h + (size_t)i * 4) = __floats2half2_rn(v.x, v.y);
        *(__half2*)(w1h + (size_t)i * 4 + 2) = __floats2half2_rn(v.z, v.w);
    }
}

// ---------------- per-edge time features + fused deg count ----------------
__global__ void edge_feat_kernel(const float* __restrict__ ts,
                                 const float* __restrict__ tw,
                                 const float* __restrict__ tb,
                                 const int* __restrict__ dst,
                                 int* __restrict__ deg,
                                 float4* __restrict__ aE0, float4* __restrict__ aE1,
                                 int e) {
    __shared__ float2 swb[TDIM];
    __shared__ u64 pv0a[TDIM], pv0b[TDIM], pv1a[TDIM], pv1b[TDIM];
    int tid = threadIdx.x;
    if (tid < TDIM) {
        swb[tid] = make_float2(tw[tid], tb[tid]);
        float4 v0 = g_ve0[tid];
        float4 v1 = g_ve1[tid];
        pv0a[tid] = pack2(v0.x, v0.y);
        pv0b[tid] = pack2(v0.z, v0.w);
        pv1a[tid] = pack2(v1.x, v1.y);
        pv1b[tid] = pack2(v1.z, v1.w);
    }
    __syncthreads();
    int iA = blockIdx.x * 512 + tid;
    int iB = iA + 256;
    float tA = (iA < e) ? ts[iA] : 0.f;
    float tB = (iB < e) ? ts[iB] : 0.f;
    if (iA < e) atomicAdd(&deg[dst[iA]], 1);
    if (iB < e) atomicAdd(&deg[dst[iB]], 1);
    u64 A0xy = 0, A0zw = 0, A1xy = 0, A1zw = 0;
    u64 B0xy = 0, B0zw = 0, B1xy = 0, B1zw = 0;
    #pragma unroll 8
    for (int td = 0; td < TDIM; td++) {
        float2 wb = swb[td];
        float aA = fabsf(__cosf(fmaf(tA, wb.x, wb.y)));
        float aB = fabsf(__cosf(fmaf(tB, wb.x, wb.y)));
        u64 ccA = pack2(aA, aA);
        u64 ccB = pack2(aB, aB);
        u64 v0a = pv0a[td], v0b = pv0b[td], v1a = pv1a[td], v1b = pv1b[td];
        ffma2(A0xy, ccA, v0a); ffma2(A0zw, ccA, v0b);
        ffma2(A1xy, ccA, v1a); ffma2(A1zw, ccA, v1b);
        ffma2(B0xy, ccB, v0a); ffma2(B0zw, ccB, v0b);
        ffma2(B1xy, ccB, v1a); ffma2(B1zw, ccB, v1b);
    }
    if (iA < e) {
        float4 r0, r1;
        unpack2(r0.x, r0.y, A0xy); unpack2(r0.z, r0.w, A0zw);
        unpack2(r1.x, r1.y, A1xy); unpack2(r1.z, r1.w, A1zw);
        aE0[iA] = r0; aE1[iA] = r1;
    }
    if (iB < e) {
        float4 r0, r1;
        unpack2(r0.x, r0.y, B0xy); unpack2(r0.z, r0.w, B0zw);
        unpack2(r1.x, r1.y, B1xy); unpack2(r1.z, r1.w, B1zw);
        aE0[iB] = r0; aE1[iB] = r1;
    }
}

// ---------------- multi-block scan, phase 1 ----------------
__global__ void scan1_kernel(const int* __restrict__ deg, int* __restrict__ rowptr,
                             int* __restrict__ blocksum, int n) {
    __shared__ int wsum[32];
    int t = threadIdx.x;
    int lane = t & 31, wid = t >> 5;
    int base = blockIdx.x * SCAN_TILE + t * 4;
    int4 v = make_int4(0, 0, 0, 0);
    if (base + 3 < n) {
        v = *(const int4*)(deg + base);
    } else {
        if (base + 0 < n) v.x = deg[base + 0];
        if (base + 1 < n) v.y = deg[base + 1];
        if (base + 2 < n) v.z = deg[base + 2];
        if (base + 3 < n) v.w = deg[base + 3];
    }
    int mysum = v.x + v.y + v.z + v.w;
    int incl = mysum;
    #pragma unroll
    for (int off = 1; off < 32; off <<= 1) {
        int x = __shfl_up_sync(0xffffffffu, incl, off);
        if (lane >= off) incl += x;
    }
    if (lane == 31) wsum[wid] = incl;
    __syncthreads();
    if (wid == 0) {
        int w = wsum[lane];
        #pragma unroll
        for (int off = 1; off < 32; off <<= 1) {
            int x = __shfl_up_sync(0xffffffffu, w, off);
            if (lane >= off) w += x;
        }
        wsum[lane] = w;
    }
    __syncthreads();
    int excl = (wid ? wsum[wid - 1] : 0) + incl - mysum;
    int4 o;
    o.x = excl;
    o.y = o.x + v.x;
    o.z = o.y + v.y;
    o.w = o.z + v.z;
    if (base + 3 < n) {
        *(int4*)(rowptr + base) = o;
    } else {
        if (base + 0 < n) rowptr[base + 0] = o.x;
        if (base + 1 < n) rowptr[base + 1] = o.y;
        if (base + 2 < n) rowptr[base + 2] = o.z;
        if (base + 3 < n) rowptr[base + 3] = o.w;
    }
    if (t == 1023) blocksum[blockIdx.x] = wsum[31];
}

// ---------------- phase 2+3 fused ----------------
__global__ void scan3_kernel(int* __restrict__ rowptr, int* __restrict__ cursor,
                             const int* __restrict__ blocksum, int n, int nb) {
    __shared__ int soff[33];
    int t = threadIdx.x;
    if (t < 32) {
        int v = (t < nb) ? blocksum[t] : 0;
        int incl = v;
        #pragma unroll
        for (int off = 1; off < 32; off <<= 1) {
            int x = __shfl_up_sync(0xffffffffu, incl, off);
            if (t >= off) incl += x;
        }
        soff[t] = incl - v;
        if (t == 31) soff[32] = incl;
    }
    __syncthreads();
    int i = blockIdx.x * blockDim.x + t;
    if (i < n) {
        int val = rowptr[i] + soff[i / SCAN_TILE];
        rowptr[i] = val;
        cursor[i] = val;
    }
    if (blockIdx.x == 0 && t == 0) rowptr[n] = soff[32];
}

// ---------------- scatter ----------------
__global__ void scatter_kernel(const int* __restrict__ src, const int* __restrict__ dst,
                               const float4* __restrict__ aE0, const float4* __restrict__ aE1,
                               int* cursor, int* colsrc,
                               float4* __restrict__ aE0c, float4* __restrict__ aE1c,
                               int e, int n) {
    int i = blockIdx.x * blockDim.x + threadIdx.x;
    int tot = e + n;
    if (i >= tot) return;
    if (i < e) {
        int d = dst[i];
        int p = atomicAdd(&cursor[d], 1);
        colsrc[p] = src[i];
        aE0c[p] = aE0[i];
        aE1c[p] = aE1[i];
    } else {
        int node = i - e;
        int p = atomicAdd(&cursor[node], 1);
        colsrc[p] = node;
        aE0c[p] = g_self0;
        aE1c[p] = g_self1;
    }
}

// ---------------- fp16 tensor-core GEMM (cp.async 2-stage) + optional fused score ------
// SCOREC=64: BN==head width; head = blockIdx.x (cross warp-pair reduce via smem).
// SCOREC=16: each 8-col nt block lies in head (wn+nt*8)>>4; each warp owns 2 heads.
template <int SCOREC>
__global__ void hgemm_kernel(const __half* __restrict__ A, const __half* __restrict__ B,
                             __half* __restrict__ C, int M, int K, int N,
                             const float* __restrict__ asrc, const float* __restrict__ adst,
                             float* __restrict__ ssrc, float* __restrict__ sdst) {
    __shared__ __half As[2][128][40];
    __shared__ __half Bs[2][32][72];
    __shared__ float2 sred[128];
    const int AS_B = 128 * 40 * 2;
    const int BS_B = 32 * 72 * 2;
    int bm = blockIdx.y * 128, bn = blockIdx.x * 64;
    int tid = threadIdx.x;
    int wid = tid >> 5, lane = tid & 31;
    int wm = (wid >> 1) * 32, wn = (wid & 1) * 32;
    float acc[2][4][4];
    #pragma unroll
    for (int mt = 0; mt < 2; mt++)
        #pragma unroll
        for (int nt = 0; nt < 4; nt++)
            #pragma unroll
            for (int r = 0; r < 4; r++) acc[mt][nt][r] = 0.f;

    u32 as_base = (u32)__cvta_generic_to_shared(&As[0][0][0]);
    u32 bs_base = (u32)__cvta_generic_to_shared(&Bs[0][0][0]);

    int a_row0 = tid >> 2, a_c8 = (tid & 3) * 8;
    int b_row = tid >> 3, b_c8 = (tid & 7) * 8;

    {
        #pragma unroll
        for (int it = 0; it < 2; it++) {
            int row = a_row0 + it * 64;
            int gm = bm + row;
            int ok = (gm < M);
            const void* g = A + (size_t)(ok ? gm : 0) * K + a_c8;
            cp_async16(as_base + (u32)(row * 40 + a_c8) * 2, g, ok ? 16 : 0);
        }
        cp_async16(bs_base + (u32)(b_row * 72 + b_c8) * 2,
                   B + (size_t)b_row * N + bn + b_c8, 16);
        CP_COMMIT();
    }

    int KT = K >> 5;
    for (int kt = 0; kt < KT; kt++) {
        if (kt + 1 < KT) {
            int st = (kt + 1) & 1;
            int k0 = (kt + 1) * 32;
            #pragma unroll
            for (int it = 0; it < 2; it++) {
                int row = a_row0 + it * 64;
                int gm = bm + row;
                int ok = (gm < M);
                const void* g = A + (size_t)(ok ? gm : 0) * K + k0 + a_c8;
                cp_async16(as_base + (u32)(st * AS_B) + (u32)(row * 40 + a_c8) * 2, g, ok ? 16 : 0);
            }
            cp_async16(bs_base + (u32)(st * BS_B) + (u32)(b_row * 72 + b_c8) * 2,
                       B + (size_t)(k0 + b_row) * N + bn + b_c8, 16);
            CP_COMMIT();
            CP_WAIT(1);
        } else {
            CP_WAIT(0);
        }
        __syncthreads();
        u32 ab = as_base + (u32)((kt & 1) * AS_B);
        u32 bb = bs_base + (u32)((kt & 1) * BS_B);
        #pragma unroll
        for (int kk = 0; kk < 32; kk += 16) {
            u32 a0[4], a1[4], b0[4], b1[4];
            {
                int arow = wm + (lane & 15);
                int acol = kk + (lane >> 4) * 8;
                ldsm_x4(a0[0], a0[1], a0[2], a0[3], ab + (u32)(arow * 40 + acol) * 2);
            }
            {
                int arow = wm + 16 + (lane & 15);
                int acol = kk + (lane >> 4) * 8;
                ldsm_x4(a1[0], a1[1], a1[2], a1[3], ab + (u32)(arow * 40 + acol) * 2);
            }
            {
                int brow = kk + (lane & 15);
                int bcol = wn + (lane >> 4) * 8;
                ldsm_x4_trans(b0[0], b0[1], b0[2], b0[3], bb + (u32)(brow * 72 + bcol) * 2);
            }
            {
                int brow = kk + (lane & 15);
                int bcol = wn + 16 + (lane >> 4) * 8;
                ldsm_x4_trans(b1[0], b1[1], b1[2], b1[3], bb + (u32)(brow * 72 + bcol) * 2);
            }
            #pragma unroll
            for (int mt = 0; mt < 2; mt++) {
                u32* am = (mt == 0) ? a0 : a1;
                mma16816(acc[mt][0][0], acc[mt][0][1], acc[mt][0][2], acc[mt][0][3],
                         am[0], am[1], am[2], am[3], b0[0], b0[1]);
                mma16816(acc[mt][1][0], acc[mt][1][1], acc[mt][1][2], acc[mt][1][3],
                         am[0], am[1], am[2], am[3], b0[2], b0[3]);
                mma16816(acc[mt][2][0], acc[mt][2][1], acc[mt][2][2], acc[mt][2][3],
                         am[0], am[1], am[2], am[3], b1[0], b1[1]);
                mma16816(acc[mt][3][0], acc[mt][3][1], acc[mt][3][2], acc[mt][3][3],
                         am[0], am[1], am[2], am[3], b1[2], b1[3]);
            }
        }
        __syncthreads();
    }
    // store C
    #pragma unroll
    for (int mt = 0; mt < 2; mt++) {
        #pragma unroll
        for (int r = 0; r < 2; r++) {
            int row = bm + wm + mt * 16 + r * 8 + (lane >> 2);
            if (row < M) {
                #pragma unroll
                for (int nt = 0; nt < 4; nt++) {
                    __half2 h = __floats2half2_rn(acc[mt][nt][r * 2 + 0], acc[mt][nt][r * 2 + 1]);
                    *(__half2*)(C + (size_t)row * N + bn + wn + nt * 8 + (lane & 3) * 2) = h;
                }
            }
        }
    }
    if (SCOREC == 64) {
        int head = blockIdx.x;
        float asv[8], adv[8];
        #pragma unroll
        for (int nt = 0; nt < 4; nt++)
            #pragma unroll
            for (int c = 0; c < 2; c++) {
                int col = bn + wn + nt * 8 + (lane & 3) * 2 + c;
                asv[nt * 2 + c] = __ldg(asrc + col);
                adv[nt * 2 + c] = __ldg(adst + col);
            }
        float spv[4], dpv[4];
        #pragma unroll
        for (int mt = 0; mt < 2; mt++)
            #pragma unroll
            for (int r = 0; r < 2; r++) {
                float sp = 0.f, dp = 0.f;
                #pragma unroll
                for (int nt = 0; nt < 4; nt++)
                    #pragma unroll
                    for (int c = 0; c < 2; c++) {
                        float v = acc[mt][nt][r * 2 + c];
                        sp = fmaf(v, asv[nt * 2 + c], sp);
                        dp = fmaf(v, adv[nt * 2 + c], dp);
                    }
                sp += __shfl_down_sync(0xffffffffu, sp, 2, 4);
                sp += __shfl_down_sync(0xffffffffu, sp, 1, 4);
                dp += __shfl_down_sync(0xffffffffu, dp, 2, 4);
                dp += __shfl_down_sync(0xffffffffu, dp, 1, 4);
                spv[mt * 2 + r] = sp;
                dpv[mt * 2 + r] = dp;
            }
        if ((lane & 3) == 0 && (wid & 1)) {
            #pragma unroll
            for (int mt = 0; mt < 2; mt++)
                #pragma unroll
                for (int r = 0; r < 2; r++) {
                    int rl = wm + mt * 16 + r * 8 + (lane >> 2);
                    sred[rl] = make_float2(spv[mt * 2 + r], dpv[mt * 2 + r]);
                }
        }
        __syncthreads();
        if ((lane & 3) == 0 && !(wid & 1)) {
            #pragma unroll
            for (int mt = 0; mt < 2; mt++)
                #pragma unroll
                for (int r = 0; r < 2; r++) {
                    int rl = wm + mt * 16 + r * 8 + (lane >> 2);
                    float2 o = sred[rl];
                    int row = bm + rl;
                    if (row < M) {
                        ssrc[row * 4 + head] = spv[mt * 2 + r] + o.x;
                        sdst[row * 4 + head] = dpv[mt * 2 + r] + o.y;
                    }
                }
        }
    }
    if (SCOREC == 16) {
        // heads: nt 0,1 -> headA = wn>>4 ; nt 2,3 -> headB = headA+1 (bn == 0)
        int headA = wn >> 4, headB = headA + 1;
        float asv[8], adv[8];
        #pragma unroll
        for (int nt = 0; nt < 4; nt++)
            #pragma unroll
            for (int c = 0; c < 2; c++) {
                int col = bn + wn + nt * 8 + (lane & 3) * 2 + c;
                asv[nt * 2 + c] = __ldg(asrc + col);
                adv[nt * 2 + c] = __ldg(adst + col);
            }
        #pragma unroll
        for (int mt = 0; mt < 2; mt++)
            #pragma unroll
            for (int r = 0; r < 2; r++) {
                float spA = 0.f, dpA = 0.f, spB = 0.f, dpB = 0.f;
                #pragma unroll
                for (int c = 0; c < 2; c++) {
                    spA = fmaf(acc[mt][0][r * 2 + c], asv[0 * 2 + c], spA);
                    spA = fmaf(acc[mt][1][r * 2 + c], asv[1 * 2 + c], spA);
                    dpA = fmaf(acc[mt][0][r * 2 + c], adv[0 * 2 + c], dpA);
                    dpA = fmaf(acc[mt][1][r * 2 + c], adv[1 * 2 + c], dpA);
                    spB = fmaf(acc[mt][2][r * 2 + c], asv[2 * 2 + c], spB);
                    spB = fmaf(acc[mt][3][r * 2 + c], asv[3 * 2 + c], spB);
                    dpB = fmaf(acc[mt][2][r * 2 + c], adv[2 * 2 + c], dpB);
                    dpB = fmaf(acc[mt][3][r * 2 + c], adv[3 * 2 + c], dpB);
                }
                spA += __shfl_down_sync(0xffffffffu, spA, 2, 4);
                spA += __shfl_down_sync(0xffffffffu, spA, 1, 4);
                dpA += __shfl_down_sync(0xffffffffu, dpA, 2, 4);
                dpA += __shfl_down_sync(0xffffffffu, dpA, 1, 4);
                spB += __shfl_down_sync(0xffffffffu, spB, 2, 4);
                spB += __shfl_down_sync(0xffffffffu, spB, 1, 4);
                dpB += __shfl_down_sync(0xffffffffu, dpB, 2, 4);
                dpB += __shfl_down_sync(0xffffffffu, dpB, 1, 4);
                if ((lane & 3) == 0) {
                    int row = bm + wm + mt * 16 + r * 8 + (lane >> 2);
                    if (row < M) {
                        ssrc[row * 4 + headA] = spA;
                        sdst[row * 4 + headA] = dpA;
                        ssrc[row * 4 + headB] = spB;
                        sdst[row * 4 + headB] = dpB;
                    }
                }
            }
    }
}

// ---------------- 2-pass softmax + aggregation, warp/node, 4-edge unroll ----------------
template <int C, typename OutT>
__global__ void agg_kernel(const int* __restrict__ rowptr, const int* __restrict__ colsrc,
                           const float4* __restrict__ aEc,
                           const float4* __restrict__ ssrc, const float4* __restrict__ sdst,
                           const __half* __restrict__ hh, const float* __restrict__ bias,
                           float4* __restrict__ aCSR, OutT* __restrict__ outp, int n_nodes) {
    int warp = (blockIdx.x * blockDim.x + threadIdx.x) >> 5;
    int lane = threadIdx.x & 31;
    if (warp >= n_nodes) return;
    int node = warp;
    int base = rowptr[node], end = rowptr[node + 1];
    float4 sd = __ldg(sdst + node);
    int myhead = lane >> 3;
    float t0 = 0.f, t1 = 0.f, t2 = 0.f, t3 = 0.f;
    for (int j = base + lane; j < end; j += 32) {
        int s = colsrc[j];
        float4 ss = __ldg(ssrc + s);
        float4 ae = __ldg(aEc + j);
        float a0 = ss.x + sd.x + ae.x; a0 = a0 >= 0.f ? a0 : 0.2f * a0;
        float a1 = ss.y + sd.y + ae.y; a1 = a1 >= 0.f ? a1 : 0.2f * a1;
        float a2 = ss.z + sd.z + ae.z; a2 = a2 >= 0.f ? a2 : 0.2f * a2;
        float a3 = ss.w + sd.w + ae.w; a3 = a3 >= 0.f ? a3 : 0.2f * a3;
        float e0 = __expf(a0), e1 = __expf(a1);
        float e2 = __expf(a2), e3 = __expf(a3);
        aCSR[j] = make_float4(e0, e1, e2, e3);
        t0 += e0; t1 += e1; t2 += e2; t3 += e3;
    }
    #pragma unroll
    for (int off = 16; off; off >>= 1) {
        t0 += __shfl_xor_sync(0xffffffffu, t0, off);
        t1 += __shfl_xor_sync(0xffffffffu, t1, off);
        t2 += __shfl_xor_sync(0xffffffffu, t2, off);
        t3 += __shfl_xor_sync(0xffffffffu, t3, off);
    }
    float iv = 1.f / ((myhead == 0 ? t0 : myhead == 1 ? t1 : myhead == 2 ? t2 : t3) + 1e-16f);
    __syncwarp();
    const float* aS = (const float*)aCSR;
    if (C == 64) {
        float accA[8];
        #pragma unroll
        for (int k = 0; k < 8; k++) accA[k] = 0.f;
        int j = base;
        for (; j + 4 <= end; j += 4) {
            int s0 = colsrc[j], s1 = colsrc[j + 1], s2 = colsrc[j + 2], s3 = colsrc[j + 3];
            float e0 = __ldg(aS + (j + 0) * 4 + myhead);
            float e1 = __ldg(aS + (j + 1) * 4 + myhead);
            float e2 = __ldg(aS + (j + 2) * 4 + myhead);
            float e3 = __ldg(aS + (j + 3) * 4 + myhead);
            uint4 r0 = __ldg((const uint4*)(hh + (size_t)s0 * 256) + lane);
            uint4 r1 = __ldg((const uint4*)(hh + (size_t)s1 * 256) + lane);
            uint4 r2 = __ldg((const uint4*)(hh + (size_t)s2 * 256) + lane);
            uint4 r3 = __ldg((const uint4*)(hh + (size_t)s3 * 256) + lane);
            #pragma unroll
            for (int q = 0; q < 4; q++) {
                uint4 r = q == 0 ? r0 : q == 1 ? r1 : q == 2 ? r2 : r3;
                float ew = q == 0 ? e0 : q == 1 ? e1 : q == 2 ? e2 : e3;
                float2 f0 = __half22float2(*(__half2*)&r.x), f1 = __half22float2(*(__half2*)&r.y);
                float2 f2 = __half22float2(*(__half2*)&r.z), f3 = __half22float2(*(__half2*)&r.w);
                accA[0] = fmaf(f0.x, ew, accA[0]); accA[1] = fmaf(f0.y, ew, accA[1]);
                accA[2] = fmaf(f1.x, ew, accA[2]); accA[3] = fmaf(f1.y, ew, accA[3]);
                accA[4] = fmaf(f2.x, ew, accA[4]); accA[5] = fmaf(f2.y, ew, accA[5]);
                accA[6] = fmaf(f3.x, ew, accA[6]); accA[7] = fmaf(f3.y, ew, accA[7]);
            }
        }
        for (; j < end; j++) {
            int s = colsrc[j];
            float ew = __ldg(aS + j * 4 + myhead);
            uint4 r = __ldg((const uint4*)(hh + (size_t)s * 256) + lane);
            float2 f0 = __half22float2(*(__half2*)&r.x), f1 = __half22float2(*(__half2*)&r.y);
            float2 f2 = __half22float2(*(__half2*)&r.z), f3 = __half22float2(*(__half2*)&r.w);
            accA[0] = fmaf(f0.x, ew, accA[0]); accA[1] = fmaf(f0.y, ew, accA[1]);
            accA[2] = fmaf(f1.x, ew, accA[2]); accA[3] = fmaf(f1.y, ew, accA[3]);
            accA[4] = fmaf(f2.x, ew, accA[4]); accA[5] = fmaf(f2.y, ew, accA[5]);
            accA[6] = fmaf(f3.x, ew, accA[6]); accA[7] = fmaf(f3.y, ew, accA[7]);
        }
        float4 bv0 = *(const float4*)(bias + lane * 8);
        float4 bv1 = *(const float4*)(bias + lane * 8 + 4);
        float o0 = accA[0] * iv + bv0.x, o1 = accA[1] * iv + bv0.y;
        float o2 = accA[2] * iv + bv0.z, o3 = accA[3] * iv + bv0.w;
        float o4 = accA[4] * iv + bv1.x, o5 = accA[5] * iv + bv1.y;
        float o6 = accA[6] * iv + bv1.z, o7 = accA[7] * iv + bv1.w;
        if (sizeof(OutT) == 2) {
            __half2 h0 = __floats2half2_rn(o0, o1), h1 = __floats2half2_rn(o2, o3);
            __half2 h2 = __floats2half2_rn(o4, o5), h3 = __floats2half2_rn(o6, o7);
            uint4 pack;
            pack.x = *(u32*)&h0; pack.y = *(u32*)&h1; pack.z = *(u32*)&h2; pack.w = *(u32*)&h3;
            *(uint4*)((__half*)outp + (size_t)node * 256 + lane * 8) = pack;
        } else {
            float* op = (float*)outp + (size_t)node * 256 + lane * 8;
            *(float4*)op = make_float4(o0, o1, o2, o3);
            *(float4*)(op + 4) = make_float4(o4, o5, o6, o7);
        }
    } else {  // C == 16
        float2 acc = make_float2(0.f, 0.f);
        int j = base;
        for (; j + 4 <= end; j += 4) {
            int s0 = colsrc[j], s1 = colsrc[j + 1], s2 = colsrc[j + 2], s3 = colsrc[j + 3];
            float e0 = __ldg(aS + (j + 0) * 4 + myhead);
            float e1 = __ldg(aS + (j + 1) * 4 + myhead);
            float e2 = __ldg(aS + (j + 2) * 4 + myhead);
            float e3 = __ldg(aS + (j + 3) * 4 + myhead);
            float2 f0 = __half22float2(__ldg((const __half2*)(hh + (size_t)s0 * 64) + lane));
            float2 f1 = __half22float2(__ldg((const __half2*)(hh + (size_t)s1 * 64) + lane));
            float2 f2 = __half22float2(__ldg((const __half2*)(hh + (size_t)s2 * 64) + lane));
            float2 f3 = __half22float2(__ldg((const __half2*)(hh + (size_t)s3 * 64) + lane));
            acc.x = fmaf(f0.x, e0, acc.x); acc.y = fmaf(f0.y, e0, acc.y);
            acc.x = fmaf(f1.x, e1, acc.x); acc.y = fmaf(f1.y, e1, acc.y);
            acc.x = fmaf(f2.x, e2, acc.x); acc.y = fmaf(f2.y, e2, acc.y);
            acc.x = fmaf(f3.x, e3, acc.x); acc.y = fmaf(f3.y, e3, acc.y);
        }
        for (; j < end; j++) {
            int s = colsrc[j];
            float ew = __ldg(aS + j * 4 + myhead);
            float2 f = __half22float2(__ldg((const __half2*)(hh + (size_t)s * 64) + lane));
            acc.x = fmaf(f.x, ew, acc.x);
            acc.y = fmaf(f.y, ew, acc.y);
        }
        float2 bv = *(const float2*)(bias + 2 * lane);
        float ox = acc.x * iv + bv.x;
        float oy = acc.y * iv + bv.y;
        if (sizeof(OutT) == 2) {
            *(__half2*)((__half*)outp + (size_t)node * 64 + 2 * lane) = __floats2half2_rn(ox, oy);
        } else {
            *(float2*)((float*)outp + (size_t)node * 64 + 2 * lane) = make_float2(ox, oy);
        }
    }
}

// ---------------- launch ----------------
extern "C" void kernel_launch(void* const* d_in, const int* in_sizes, int n_in,
                              void* d_out, int out_size) {
    const float* x   = (const float*)d_in[0];
    const int*   ei  = (const int*)d_in[1];
    const float* ts  = (const float*)d_in[2];
    const float* tw  = (const float*)d_in[3];
    const float* tb  = (const float*)d_in[4];
    const float* W0  = (const float*)d_in[5];
    const float* as0 = (const float*)d_in[6];
    const float* ad0 = (const float*)d_in[7];
    const float* le0 = (const float*)d_in[8];
    const float* ae0 = (const float*)d_in[9];
    const float* b0  = (const float*)d_in[10];
    const float* W1  = (const float*)d_in[11];
    const float* as1 = (const float*)d_in[12];
    const float* ad1 = (const float*)d_in[13];
    const float* le1 = (const float*)d_in[14];
    const float* ae1 = (const float*)d_in[15];
    const float* b1  = (const float*)d_in[16];

    int n = in_sizes[0] / 128;   // 50000
    int e = in_sizes[2];         // 800000
    int tot = e + n;
    const int* srcp = ei;
    const int* dstp = ei + e;

    void *p_xh, *p_w0h, *p_w1h, *p_hh0, *p_out0h, *p_hh1;
    void *p_aE0, *p_aE1, *p_aE0c, *p_aE1c, *p_aCSR, *p_ss0, *p_sd0, *p_ss1, *p_sd1;
    void *p_deg, *p_rowptr, *p_cursor, *p_colsrc, *p_bsum;
    cudaGetSymbolAddress(&p_xh, g_xh);
    cudaGetSymbolAddress(&p_w0h, g_w0h);
    cudaGetSymbolAddress(&p_w1h, g_w1h);
    cudaGetSymbolAddress(&p_hh0, g_hh0);
    cudaGetSymbolAddress(&p_out0h, g_out0h);
    cudaGetSymbolAddress(&p_hh1, g_hh1);
    cudaGetSymbolAddress(&p_aE0, g_alphaE0);
    cudaGetSymbolAddress(&p_aE1, g_alphaE1);
    cudaGetSymbolAddress(&p_aE0c, g_aE0c);
    cudaGetSymbolAddress(&p_aE1c, g_aE1c);
    cudaGetSymbolAddress(&p_aCSR, g_aCSR);
    cudaGetSymbolAddress(&p_ss0, g_ss0);
    cudaGetSymbolAddress(&p_sd0, g_sd0);
    cudaGetSymbolAddress(&p_ss1, g_ss1);
    cudaGetSymbolAddress(&p_sd1, g_sd1);
    cudaGetSymbolAddress(&p_deg, g_deg);
    cudaGetSymbolAddress(&p_rowptr, g_rowptr);
    cudaGetSymbolAddress(&p_cursor, g_cursor);
    cudaGetSymbolAddress(&p_colsrc, g_colsrc);
    cudaGetSymbolAddress(&p_bsum, g_blocksum);

    __half* xh     = (__half*)p_xh;
    __half* w0h    = (__half*)p_w0h;
    __half* w1h    = (__half*)p_w1h;
    __half* hh0    = (__half*)p_hh0;
    __half* out0h  = (__half*)p_out0h;
    __half* hh1    = (__half*)p_hh1;
    float4* aE0    = (float4*)p_aE0;
    float4* aE1    = (float4*)p_aE1;
    float4* aE0c   = (float4*)p_aE0c;
    float4* aE1c   = (float4*)p_aE1c;
    float4* aCSR   = (float4*)p_aCSR;
    float4* ss0    = (float4*)p_ss0;
    float4* sd0    = (float4*)p_sd0;
    float4* ss1    = (float4*)p_ss1;
    float4* sd1    = (float4*)p_sd1;
    int* deg       = (int*)p_deg;
    int* rowptr    = (int*)p_rowptr;
    int* cursor    = (int*)p_cursor;
    int* colsrc    = (int*)p_colsrc;
    int* bsum      = (int*)p_bsum;

    int nb = (n + SCAN_TILE - 1) / SCAN_TILE;   // 13 for n=50000

    // side stream + fork/join events (created once, on the uncaptured first call)
    static cudaStream_t s1 = 0;
    static cudaEvent_t evFork = 0, evJoin = 0;
    if (s1 == 0) {
        cudaStreamCreateWithFlags(&s1, cudaStreamNonBlocking);
        cudaEventCreateWithFlags(&evFork, cudaEventDisableTiming);
        cudaEventCreateWithFlags(&evJoin, cudaEventDisableTiming);
    }

    setup_kernel<<<1 + 512, 256>>>(le0, ae0, le1, ae1, x, W0, W1, deg, xh, w0h, w1h, n);
    // fork: hgemm0 (+fused score0) runs on s1 concurrently with the CSR build
    cudaEventRecord(evFork, 0);
    cudaStreamWaitEvent(s1, evFork, 0);
    hgemm_kernel<64><<<dim3(256 / 64, (n + 127) / 128), 256, 0, s1>>>(
        xh, w0h, hh0, n, 128, 256, as0, ad0, (float*)ss0, (float*)sd0);
    // CSR build chain on the main stream
    edge_feat_kernel<<<(e + 511) / 512, 256>>>(ts, tw, tb, dstp, deg, aE0, aE1, e);
    scan1_kernel<<<nb, 1024>>>(deg, rowptr, bsum, n);
    scan3_kernel<<<(n + 255) / 256, 256>>>(rowptr, cursor, bsum, n, nb);
    scatter_kernel<<<(tot + 255) / 256, 256>>>(srcp, dstp, aE0, aE1, cursor, colsrc,
                                               aE0c, aE1c, e, n);
    // join: agg0 needs hh0/ss0/sd0 (s1) + CSR (main)
    cudaEventRecord(evJoin, s1);
    cudaStreamWaitEvent(0, evJoin, 0);
    agg_kernel<64, __half><<<(n * 32 + 255) / 256, 256>>>(rowptr, colsrc, aE0c, ss0, sd0,
                                                          hh0, b0, aCSR, out0h, n);
    hgemm_kernel<16><<<dim3(64 / 64, (n + 127) / 128), 256>>>(
        out0h, w1h, hh1, n, 256, 64, as1, ad1, (float*)ss1, (float*)sd1);
    agg_kernel<16, float><<<(n * 32 + 255) / 256, 256>>>(rowptr, colsrc, aE1c, ss1, sd1,
                                                         hh1, b1, aCSR, (float*)d_out, n);
}

// round 16
// speedup vs baseline: 1.8936x; 1.0177x over previous
#include <cuda_runtime.h>
#include <cuda_fp16.h>
#include <stdint.h>
#include <math.h>

typedef unsigned int u32;
typedef unsigned long long u64;

#define NN 50000
#define EE 800000
#define ET (EE + NN)
#define TDIM 64
#define SCAN_TILE 4096   // 1024 threads x 4 elems

// ---------------- scratch (static device globals; no allocation) ----------------
__device__ int    g_deg[NN];
__device__ int    g_rowptr[NN + 1];
__device__ int    g_cursor[NN];
__device__ int    g_blocksum[64];
__device__ int    g_colsrc[ET];
__device__ float4 g_alphaE0[EE];
__device__ float4 g_alphaE1[EE];
__device__ float4 g_aE0c[ET];
__device__ float4 g_aE1c[ET];
__device__ float4 g_aCSR[ET];
__device__ __half g_xh[(size_t)NN * 128];
__device__ __half g_w0h[128 * 256];
__device__ __half g_w1h[256 * 64];
__device__ __half g_hh0[(size_t)NN * 256];
__device__ __half g_out0h[(size_t)NN * 256];
__device__ __half g_hh1[(size_t)NN * 64];
__device__ float4 g_ss0[NN], g_sd0[NN], g_ss1[NN], g_sd1[NN];
__device__ float4 g_ve0[TDIM];
__device__ float4 g_ve1[TDIM];
__device__ float4 g_self0, g_self1;

// ---------------- PTX helpers ----------------
__device__ __forceinline__ void ldsm_x4(u32& r0, u32& r1, u32& r2, u32& r3, u32 addr) {
    asm volatile("ldmatrix.sync.aligned.m8n8.x4.shared.b16 {%0,%1,%2,%3}, [%4];"
                 : "=r"(r0), "=r"(r1), "=r"(r2), "=r"(r3) : "r"(addr));
}
__device__ __forceinline__ void ldsm_x4_trans(u32& r0, u32& r1, u32& r2, u32& r3, u32 addr) {
    asm volatile("ldmatrix.sync.aligned.m8n8.x4.trans.shared.b16 {%0,%1,%2,%3}, [%4];"
                 : "=r"(r0), "=r"(r1), "=r"(r2), "=r"(r3) : "r"(addr));
}
__device__ __forceinline__ void mma16816(float& c0, float& c1, float& c2, float& c3,
                                         u32 a0, u32 a1, u32 a2, u32 a3,
                                         u32 b0, u32 b1) {
    asm volatile(
        "mma.sync.aligned.m16n8k16.row.col.f32.f16.f16.f32 "
        "{%0,%1,%2,%3}, {%4,%5,%6,%7}, {%8,%9}, {%0,%1,%2,%3};"
        : "+f"(c0), "+f"(c1), "+f"(c2), "+f"(c3)
        : "r"(a0), "r"(a1), "r"(a2), "r"(a3), "r"(b0), "r"(b1));
}
__device__ __forceinline__ void cp_async16(u32 saddr, const void* gaddr, int src_bytes) {
    asm volatile("cp.async.ca.shared.global [%0], [%1], 16, %2;"
                 :: "r"(saddr), "l"(gaddr), "r"(src_bytes));
}
#define CP_COMMIT()  asm volatile("cp.async.commit_group;")
#define CP_WAIT(n)   asm volatile("cp.async.wait_group %0;" :: "n"(n))

__device__ __forceinline__ void ffma2(u64& d, u64 a, u64 b) {
    asm("fma.rn.f32x2 %0, %1, %2, %0;" : "+l"(d) : "l"(a), "l"(b));
}
__device__ __forceinline__ u64 pack2(float lo, float hi) {
    u64 r;
    asm("mov.b64 %0, {%1, %2};" : "=l"(r) : "f"(lo), "f"(hi));
    return r;
}
__device__ __forceinline__ void unpack2(float& lo, float& hi, u64 v) {
    asm("mov.b64 {%0, %1}, %2;" : "=f"(lo), "=f"(hi) : "l"(v));
}

// ---------------- prep: ve + self vectors (1 block) ----------------
__global__ void prep_kernel(const float* __restrict__ le0, const float* __restrict__ ae0,
                            const float* __restrict__ le1, const float* __restrict__ ae1) {
    int tid = threadIdx.x;
    int td = tid >> 2, hh = tid & 3;
    float s0 = 0.f;
    for (int c = 0; c < 64; c++) s0 += le0[td * 256 + hh * 64 + c] * ae0[hh * 64 + c];
    ((float*)g_ve0)[td * 4 + hh] = s0;
    float s1 = 0.f;
    for (int c = 0; c < 16; c++) s1 += le1[td * 64 + hh * 16 + c] * ae1[hh * 16 + c];
    ((float*)g_ve1)[td * 4 + hh] = s1;
    __syncthreads();
    if (td == 0) {
        float a = 0.f, b = 0.f;
        for (int t2 = 0; t2 < TDIM; t2++) {
            a += ((float*)g_ve0)[t2 * 4 + hh];
            b += ((float*)g_ve1)[t2 * 4 + hh];
        }
        ((float*)&g_self0)[hh] = a;
        ((float*)&g_self1)[hh] = b;
    }
}

// ---------------- cvt: x, W0, W1 -> fp16 (s1 stream, feeds hgemm0 only) -----------
__global__ void cvt_kernel(const float* __restrict__ x, const float* __restrict__ W0,
                           const float* __restrict__ W1,
                           __half* __restrict__ xh, __half* __restrict__ w0h,
                           __half* __restrict__ w1h, int n) {
    int gid = blockIdx.x * 256 + threadIdx.x;
    int stride = gridDim.x * 256;
    int nx4 = n * 32;
    for (int i = gid; i < nx4; i += stride) {
        float4 v = *(const float4*)(x + (size_t)i * 4);
        *(__half2*)(xh + (size_t)i * 4) = __floats2half2_rn(v.x, v.y);
        *(__half2*)(xh + (size_t)i * 4 + 2) = __floats2half2_rn(v.z, v.w);
    }
    for (int i = gid; i < 8192; i += stride) {
        float4 v = *(const float4*)(W0 + (size_t)i * 4);
        *(__half2*)(w0h + (size_t)i * 4) = __floats2half2_rn(v.x, v.y);
        *(__half2*)(w0h + (size_t)i * 4 + 2) = __floats2half2_rn(v.z, v.w);
    }
    for (int i = gid; i < 4096; i += stride) {
        float4 v = *(const float4*)(W1 + (size_t)i * 4);
        *(__half2*)(w1h + (size_t)i * 4) = __floats2half2_rn(v.x, v.y);
        *(__half2*)(w1h + (size_t)i * 4 + 2) = __floats2half2_rn(v.z, v.w);
    }
}

// ---------------- per-edge time features + fused deg count (deg zero-initialized) ----
__global__ void edge_feat_kernel(const float* __restrict__ ts,
                                 const float* __restrict__ tw,
                                 const float* __restrict__ tb,
                                 const int* __restrict__ dst,
                                 int* __restrict__ deg,
                                 float4* __restrict__ aE0, float4* __restrict__ aE1,
                                 int e) {
    __shared__ float2 swb[TDIM];
    __shared__ u64 pv0a[TDIM], pv0b[TDIM], pv1a[TDIM], pv1b[TDIM];
    int tid = threadIdx.x;
    if (tid < TDIM) {
        swb[tid] = make_float2(tw[tid], tb[tid]);
        float4 v0 = g_ve0[tid];
        float4 v1 = g_ve1[tid];
        pv0a[tid] = pack2(v0.x, v0.y);
        pv0b[tid] = pack2(v0.z, v0.w);
        pv1a[tid] = pack2(v1.x, v1.y);
        pv1b[tid] = pack2(v1.z, v1.w);
    }
    __syncthreads();
    int iA = blockIdx.x * 512 + tid;
    int iB = iA + 256;
    float tA = (iA < e) ? ts[iA] : 0.f;
    float tB = (iB < e) ? ts[iB] : 0.f;
    if (iA < e) atomicAdd(&deg[dst[iA]], 1);
    if (iB < e) atomicAdd(&deg[dst[iB]], 1);
    u64 A0xy = 0, A0zw = 0, A1xy = 0, A1zw = 0;
    u64 B0xy = 0, B0zw = 0, B1xy = 0, B1zw = 0;
    #pragma unroll 8
    for (int td = 0; td < TDIM; td++) {
        float2 wb = swb[td];
        float aA = fabsf(__cosf(fmaf(tA, wb.x, wb.y)));
        float aB = fabsf(__cosf(fmaf(tB, wb.x, wb.y)));
        u64 ccA = pack2(aA, aA);
        u64 ccB = pack2(aB, aB);
        u64 v0a = pv0a[td], v0b = pv0b[td], v1a = pv1a[td], v1b = pv1b[td];
        ffma2(A0xy, ccA, v0a); ffma2(A0zw, ccA, v0b);
        ffma2(A1xy, ccA, v1a); ffma2(A1zw, ccA, v1b);
        ffma2(B0xy, ccB, v0a); ffma2(B0zw, ccB, v0b);
        ffma2(B1xy, ccB, v1a); ffma2(B1zw, ccB, v1b);
    }
    if (iA < e) {
        float4 r0, r1;
        unpack2(r0.x, r0.y, A0xy); unpack2(r0.z, r0.w, A0zw);
        unpack2(r1.x, r1.y, A1xy); unpack2(r1.z, r1.w, A1zw);
        aE0[iA] = r0; aE1[iA] = r1;
    }
    if (iB < e) {
        float4 r0, r1;
        unpack2(r0.x, r0.y, B0xy); unpack2(r0.z, r0.w, B0zw);
        unpack2(r1.x, r1.y, B1xy); unpack2(r1.z, r1.w, B1zw);
        aE0[iB] = r0; aE1[iB] = r1;
    }
}

// ---------------- multi-block scan, phase 1 (adds self-loop +1 per node) -------------
__global__ void scan1_kernel(const int* __restrict__ deg, int* __restrict__ rowptr,
                             int* __restrict__ blocksum, int n) {
    __shared__ int wsum[32];
    int t = threadIdx.x;
    int lane = t & 31, wid = t >> 5;
    int base = blockIdx.x * SCAN_TILE + t * 4;
    int4 v = make_int4(0, 0, 0, 0);
    if (base + 3 < n) {
        v = *(const int4*)(deg + base);
        v.x += 1; v.y += 1; v.z += 1; v.w += 1;
    } else {
        if (base + 0 < n) v.x = deg[base + 0] + 1;
        if (base + 1 < n) v.y = deg[base + 1] + 1;
        if (base + 2 < n) v.z = deg[base + 2] + 1;
        if (base + 3 < n) v.w = deg[base + 3] + 1;
    }
    int mysum = v.x + v.y + v.z + v.w;
    int incl = mysum;
    #pragma unroll
    for (int off = 1; off < 32; off <<= 1) {
        int x = __shfl_up_sync(0xffffffffu, incl, off);
        if (lane >= off) incl += x;
    }
    if (lane == 31) wsum[wid] = incl;
    __syncthreads();
    if (wid == 0) {
        int w = wsum[lane];
        #pragma unroll
        for (int off = 1; off < 32; off <<= 1) {
            int x = __shfl_up_sync(0xffffffffu, w, off);
            if (lane >= off) w += x;
        }
        wsum[lane] = w;
    }
    __syncthreads();
    int excl = (wid ? wsum[wid - 1] : 0) + incl - mysum;
    int4 o;
    o.x = excl;
    o.y = o.x + v.x;
    o.z = o.y + v.y;
    o.w = o.z + v.z;
    if (base + 3 < n) {
        *(int4*)(rowptr + base) = o;
    } else {
        if (base + 0 < n) rowptr[base + 0] = o.x;
        if (base + 1 < n) rowptr[base + 1] = o.y;
        if (base + 2 < n) rowptr[base + 2] = o.z;
        if (base + 3 < n) rowptr[base + 3] = o.w;
    }
    if (t == 1023) blocksum[blockIdx.x] = wsum[31];
}

// ---------------- phase 2+3 fused ----------------
__global__ void scan3_kernel(int* __restrict__ rowptr, int* __restrict__ cursor,
                             const int* __restrict__ blocksum, int n, int nb) {
    __shared__ int soff[33];
    int t = threadIdx.x;
    if (t < 32) {
        int v = (t < nb) ? blocksum[t] : 0;
        int incl = v;
        #pragma unroll
        for (int off = 1; off < 32; off <<= 1) {
            int x = __shfl_up_sync(0xffffffffu, incl, off);
            if (t >= off) incl += x;
        }
        soff[t] = incl - v;
        if (t == 31) soff[32] = incl;
    }
    __syncthreads();
    int i = blockIdx.x * blockDim.x + t;
    if (i < n) {
        int val = rowptr[i] + soff[i / SCAN_TILE];
        rowptr[i] = val;
        cursor[i] = val;
    }
    if (blockIdx.x == 0 && t == 0) rowptr[n] = soff[32];
}

// ---------------- scatter ----------------
__global__ void scatter_kernel(const int* __restrict__ src, const int* __restrict__ dst,
                               const float4* __restrict__ aE0, const float4* __restrict__ aE1,
                               int* cursor, int* colsrc,
                               float4* __restrict__ aE0c, float4* __restrict__ aE1c,
                               int e, int n) {
    int i = blockIdx.x * blockDim.x + threadIdx.x;
    int tot = e + n;
    if (i >= tot) return;
    if (i < e) {
        int d = dst[i];
        int p = atomicAdd(&cursor[d], 1);
        colsrc[p] = src[i];
        aE0c[p] = aE0[i];
        aE1c[p] = aE1[i];
    } else {
        int node = i - e;
        int p = atomicAdd(&cursor[node], 1);
        colsrc[p] = node;
        aE0c[p] = g_self0;
        aE1c[p] = g_self1;
    }
}

// ---------------- fp16 tensor-core GEMM (cp.async 2-stage) + fused score epilogue -----
template <int SCOREC>
__global__ void hgemm_kernel(const __half* __restrict__ A, const __half* __restrict__ B,
                             __half* __restrict__ C, int M, int K, int N,
                             const float* __restrict__ asrc, const float* __restrict__ adst,
                             float* __restrict__ ssrc, float* __restrict__ sdst) {
    __shared__ __half As[2][128][40];
    __shared__ __half Bs[2][32][72];
    __shared__ float2 sred[128];
    const int AS_B = 128 * 40 * 2;
    const int BS_B = 32 * 72 * 2;
    int bm = blockIdx.y * 128, bn = blockIdx.x * 64;
    int tid = threadIdx.x;
    int wid = tid >> 5, lane = tid & 31;
    int wm = (wid >> 1) * 32, wn = (wid & 1) * 32;
    float acc[2][4][4];
    #pragma unroll
    for (int mt = 0; mt < 2; mt++)
        #pragma unroll
        for (int nt = 0; nt < 4; nt++)
            #pragma unroll
            for (int r = 0; r < 4; r++) acc[mt][nt][r] = 0.f;

    u32 as_base = (u32)__cvta_generic_to_shared(&As[0][0][0]);
    u32 bs_base = (u32)__cvta_generic_to_shared(&Bs[0][0][0]);

    int a_row0 = tid >> 2, a_c8 = (tid & 3) * 8;
    int b_row = tid >> 3, b_c8 = (tid & 7) * 8;

    {
        #pragma unroll
        for (int it = 0; it < 2; it++) {
            int row = a_row0 + it * 64;
            int gm = bm + row;
            int ok = (gm < M);
            const void* g = A + (size_t)(ok ? gm : 0) * K + a_c8;
            cp_async16(as_base + (u32)(row * 40 + a_c8) * 2, g, ok ? 16 : 0);
        }
        cp_async16(bs_base + (u32)(b_row * 72 + b_c8) * 2,
                   B + (size_t)b_row * N + bn + b_c8, 16);
        CP_COMMIT();
    }

    int KT = K >> 5;
    for (int kt = 0; kt < KT; kt++) {
        if (kt + 1 < KT) {
            int st = (kt + 1) & 1;
            int k0 = (kt + 1) * 32;
            #pragma unroll
            for (int it = 0; it < 2; it++) {
                int row = a_row0 + it * 64;
                int gm = bm + row;
                int ok = (gm < M);
                const void* g = A + (size_t)(ok ? gm : 0) * K + k0 + a_c8;
                cp_async16(as_base + (u32)(st * AS_B) + (u32)(row * 40 + a_c8) * 2, g, ok ? 16 : 0);
            }
            cp_async16(bs_base + (u32)(st * BS_B) + (u32)(b_row * 72 + b_c8) * 2,
                       B + (size_t)(k0 + b_row) * N + bn + b_c8, 16);
            CP_COMMIT();
            CP_WAIT(1);
        } else {
            CP_WAIT(0);
        }
        __syncthreads();
        u32 ab = as_base + (u32)((kt & 1) * AS_B);
        u32 bb = bs_base + (u32)((kt & 1) * BS_B);
        #pragma unroll
        for (int kk = 0; kk < 32; kk += 16) {
            u32 a0[4], a1[4], b0[4], b1[4];
            {
                int arow = wm + (lane & 15);
                int acol = kk + (lane >> 4) * 8;
                ldsm_x4(a0[0], a0[1], a0[2], a0[3], ab + (u32)(arow * 40 + acol) * 2);
            }
            {
                int arow = wm + 16 + (lane & 15);
                int acol = kk + (lane >> 4) * 8;
                ldsm_x4(a1[0], a1[1], a1[2], a1[3], ab + (u32)(arow * 40 + acol) * 2);
            }
            {
                int brow = kk + (lane & 15);
                int bcol = wn + (lane >> 4) * 8;
                ldsm_x4_trans(b0[0], b0[1], b0[2], b0[3], bb + (u32)(brow * 72 + bcol) * 2);
            }
            {
                int brow = kk + (lane & 15);
                int bcol = wn + 16 + (lane >> 4) * 8;
                ldsm_x4_trans(b1[0], b1[1], b1[2], b1[3], bb + (u32)(brow * 72 + bcol) * 2);
            }
            #pragma unroll
            for (int mt = 0; mt < 2; mt++) {
                u32* am = (mt == 0) ? a0 : a1;
                mma16816(acc[mt][0][0], acc[mt][0][1], acc[mt][0][2], acc[mt][0][3],
                         am[0], am[1], am[2], am[3], b0[0], b0[1]);
                mma16816(acc[mt][1][0], acc[mt][1][1], acc[mt][1][2], acc[mt][1][3],
                         am[0], am[1], am[2], am[3], b0[2], b0[3]);
                mma16816(acc[mt][2][0], acc[mt][2][1], acc[mt][2][2], acc[mt][2][3],
                         am[0], am[1], am[2], am[3], b1[0], b1[1]);
                mma16816(acc[mt][3][0], acc[mt][3][1], acc[mt][3][2], acc[mt][3][3],
                         am[0], am[1], am[2], am[3], b1[2], b1[3]);
            }
        }
        __syncthreads();
    }
    // store C
    #pragma unroll
    for (int mt = 0; mt < 2; mt++) {
        #pragma unroll
        for (int r = 0; r < 2; r++) {
            int row = bm + wm + mt * 16 + r * 8 + (lane >> 2);
            if (row < M) {
                #pragma unroll
                for (int nt = 0; nt < 4; nt++) {
                    __half2 h = __floats2half2_rn(acc[mt][nt][r * 2 + 0], acc[mt][nt][r * 2 + 1]);
                    *(__half2*)(C + (size_t)row * N + bn + wn + nt * 8 + (lane & 3) * 2) = h;
                }
            }
        }
    }
    if (SCOREC == 64) {
        int head = blockIdx.x;
        float asv[8], adv[8];
        #pragma unroll
        for (int nt = 0; nt < 4; nt++)
            #pragma unroll
            for (int c = 0; c < 2; c++) {
                int col = bn + wn + nt * 8 + (lane & 3) * 2 + c;
                asv[nt * 2 + c] = __ldg(asrc + col);
                adv[nt * 2 + c] = __ldg(adst + col);
            }
        float spv[4], dpv[4];
        #pragma unroll
        for (int mt = 0; mt < 2; mt++)
            #pragma unroll
            for (int r = 0; r < 2; r++) {
                float sp = 0.f, dp = 0.f;
                #pragma unroll
                for (int nt = 0; nt < 4; nt++)
                    #pragma unroll
                    for (int c = 0; c < 2; c++) {
                        float v = acc[mt][nt][r * 2 + c];
                        sp = fmaf(v, asv[nt * 2 + c], sp);
                        dp = fmaf(v, adv[nt * 2 + c], dp);
                    }
                sp += __shfl_down_sync(0xffffffffu, sp, 2, 4);
                sp += __shfl_down_sync(0xffffffffu, sp, 1, 4);
                dp += __shfl_down_sync(0xffffffffu, dp, 2, 4);
                dp += __shfl_down_sync(0xffffffffu, dp, 1, 4);
                spv[mt * 2 + r] = sp;
                dpv[mt * 2 + r] = dp;
            }
        if ((lane & 3) == 0 && (wid & 1)) {
            #pragma unroll
            for (int mt = 0; mt < 2; mt++)
                #pragma unroll
                for (int r = 0; r < 2; r++) {
                    int rl = wm + mt * 16 + r * 8 + (lane >> 2);
                    sred[rl] = make_float2(spv[mt * 2 + r], dpv[mt * 2 + r]);
                }
        }
        __syncthreads();
        if ((lane & 3) == 0 && !(wid & 1)) {
            #pragma unroll
            for (int mt = 0; mt < 2; mt++)
                #pragma unroll
                for (int r = 0; r < 2; r++) {
                    int rl = wm + mt * 16 + r * 8 + (lane >> 2);
                    float2 o = sred[rl];
                    int row = bm + rl;
                    if (row < M) {
                        ssrc[row * 4 + head] = spv[mt * 2 + r] + o.x;
                        sdst[row * 4 + head] = dpv[mt * 2 + r] + o.y;
                    }
                }
        }
    }
    if (SCOREC == 16) {
        int headA = wn >> 4, headB = headA + 1;
        float asv[8], adv[8];
        #pragma unroll
        for (int nt = 0; nt < 4; nt++)
            #pragma unroll
            for (int c = 0; c < 2; c++) {
                int col = bn + wn + nt * 8 + (lane & 3) * 2 + c;
                asv[nt * 2 + c] = __ldg(asrc + col);
                adv[nt * 2 + c] = __ldg(adst + col);
            }
        #pragma unroll
        for (int mt = 0; mt < 2; mt++)
            #pragma unroll
            for (int r = 0; r < 2; r++) {
                float spA = 0.f, dpA = 0.f, spB = 0.f, dpB = 0.f;
                #pragma unroll
                for (int c = 0; c < 2; c++) {
                    spA = fmaf(acc[mt][0][r * 2 + c], asv[0 * 2 + c], spA);
                    spA = fmaf(acc[mt][1][r * 2 + c], asv[1 * 2 + c], spA);
                    dpA = fmaf(acc[mt][0][r * 2 + c], adv[0 * 2 + c], dpA);
                    dpA = fmaf(acc[mt][1][r * 2 + c], adv[1 * 2 + c], dpA);
                    spB = fmaf(acc[mt][2][r * 2 + c], asv[2 * 2 + c], spB);
                    spB = fmaf(acc[mt][3][r * 2 + c], asv[3 * 2 + c], spB);
                    dpB = fmaf(acc[mt][2][r * 2 + c], adv[2 * 2 + c], dpB);
                    dpB = fmaf(acc[mt][3][r * 2 + c], adv[3 * 2 + c], dpB);
                }
                spA += __shfl_down_sync(0xffffffffu, spA, 2, 4);
                spA += __shfl_down_sync(0xffffffffu, spA, 1, 4);
                dpA += __shfl_down_sync(0xffffffffu, dpA, 2, 4);
                dpA += __shfl_down_sync(0xffffffffu, dpA, 1, 4);
                spB += __shfl_down_sync(0xffffffffu, spB, 2, 4);
                spB += __shfl_down_sync(0xffffffffu, spB, 1, 4);
                dpB += __shfl_down_sync(0xffffffffu, dpB, 2, 4);
                dpB += __shfl_down_sync(0xffffffffu, dpB, 1, 4);
                if ((lane & 3) == 0) {
                    int row = bm + wm + mt * 16 + r * 8 + (lane >> 2);
                    if (row < M) {
                        ssrc[row * 4 + headA] = spA;
                        sdst[row * 4 + headA] = dpA;
                        ssrc[row * 4 + headB] = spB;
                        sdst[row * 4 + headB] = dpB;
                    }
                }
            }
    }
}

// ---------------- 2-pass softmax + aggregation, warp/node, 4-edge unroll ----------------
template <int C, typename OutT>
__global__ void agg_kernel(const int* __restrict__ rowptr, const int* __restrict__ colsrc,
                           const float4* __restrict__ aEc,
                           const float4* __restrict__ ssrc, const float4* __restrict__ sdst,
                           const __half* __restrict__ hh, const float* __restrict__ bias,
                           float4* __restrict__ aCSR, OutT* __restrict__ outp, int n_nodes) {
    int warp = (blockIdx.x * blockDim.x + threadIdx.x) >> 5;
    int lane = threadIdx.x & 31;
    if (warp >= n_nodes) return;
    int node = warp;
    int base = rowptr[node], end = rowptr[node + 1];
    float4 sd = __ldg(sdst + node);
    int myhead = lane >> 3;
    float t0 = 0.f, t1 = 0.f, t2 = 0.f, t3 = 0.f;
    for (int j = base + lane; j < end; j += 32) {
        int s = colsrc[j];
        float4 ss = __ldg(ssrc + s);
        float4 ae = __ldg(aEc + j);
        float a0 = ss.x + sd.x + ae.x; a0 = a0 >= 0.f ? a0 : 0.2f * a0;
        float a1 = ss.y + sd.y + ae.y; a1 = a1 >= 0.f ? a1 : 0.2f * a1;
        float a2 = ss.z + sd.z + ae.z; a2 = a2 >= 0.f ? a2 : 0.2f * a2;
        float a3 = ss.w + sd.w + ae.w; a3 = a3 >= 0.f ? a3 : 0.2f * a3;
        float e0 = __expf(a0), e1 = __expf(a1);
        float e2 = __expf(a2), e3 = __expf(a3);
        aCSR[j] = make_float4(e0, e1, e2, e3);
        t0 += e0; t1 += e1; t2 += e2; t3 += e3;
    }
    #pragma unroll
    for (int off = 16; off; off >>= 1) {
        t0 += __shfl_xor_sync(0xffffffffu, t0, off);
        t1 += __shfl_xor_sync(0xffffffffu, t1, off);
        t2 += __shfl_xor_sync(0xffffffffu, t2, off);
        t3 += __shfl_xor_sync(0xffffffffu, t3, off);
    }
    float iv = 1.f / ((myhead == 0 ? t0 : myhead == 1 ? t1 : myhead == 2 ? t2 : t3) + 1e-16f);
    __syncwarp();
    const float* aS = (const float*)aCSR;
    if (C == 64) {
        float accA[8];
        #pragma unroll
        for (int k = 0; k < 8; k++) accA[k] = 0.f;
        int j = base;
        for (; j + 4 <= end; j += 4) {
            int s0 = colsrc[j], s1 = colsrc[j + 1], s2 = colsrc[j + 2], s3 = colsrc[j + 3];
            float e0 = __ldg(aS + (j + 0) * 4 + myhead);
            float e1 = __ldg(aS + (j + 1) * 4 + myhead);
            float e2 = __ldg(aS + (j + 2) * 4 + myhead);
            float e3 = __ldg(aS + (j + 3) * 4 + myhead);
            uint4 r0 = __ldg((const uint4*)(hh + (size_t)s0 * 256) + lane);
            uint4 r1 = __ldg((const uint4*)(hh + (size_t)s1 * 256) + lane);
            uint4 r2 = __ldg((const uint4*)(hh + (size_t)s2 * 256) + lane);
            uint4 r3 = __ldg((const uint4*)(hh + (size_t)s3 * 256) + lane);
            #pragma unroll
            for (int q = 0; q < 4; q++) {
                uint4 r = q == 0 ? r0 : q == 1 ? r1 : q == 2 ? r2 : r3;
                float ew = q == 0 ? e0 : q == 1 ? e1 : q == 2 ? e2 : e3;
                float2 f0 = __half22float2(*(__half2*)&r.x), f1 = __half22float2(*(__half2*)&r.y);
                float2 f2 = __half22float2(*(__half2*)&r.z), f3 = __half22float2(*(__half2*)&r.w);
                accA[0] = fmaf(f0.x, ew, accA[0]); accA[1] = fmaf(f0.y, ew, accA[1]);
                accA[2] = fmaf(f1.x, ew, accA[2]); accA[3] = fmaf(f1.y, ew, accA[3]);
                accA[4] = fmaf(f2.x, ew, accA[4]); accA[5] = fmaf(f2.y, ew, accA[5]);
                accA[6] = fmaf(f3.x, ew, accA[6]); accA[7] = fmaf(f3.y, ew, accA[7]);
            }
        }
        for (; j < end; j++) {
            int s = colsrc[j];
            float ew = __ldg(aS + j * 4 + myhead);
            uint4 r = __ldg((const uint4*)(hh + (size_t)s * 256) + lane);
            float2 f0 = __half22float2(*(__half2*)&r.x), f1 = __half22float2(*(__half2*)&r.y);
            float2 f2 = __half22float2(*(__half2*)&r.z), f3 = __half22float2(*(__half2*)&r.w);
            accA[0] = fmaf(f0.x, ew, accA[0]); accA[1] = fmaf(f0.y, ew, accA[1]);
            accA[2] = fmaf(f1.x, ew, accA[2]); accA[3] = fmaf(f1.y, ew, accA[3]);
            accA[4] = fmaf(f2.x, ew, accA[4]); accA[5] = fmaf(f2.y, ew, accA[5]);
            accA[6] = fmaf(f3.x, ew, accA[6]); accA[7] = fmaf(f3.y, ew, accA[7]);
        }
        float4 bv0 = *(const float4*)(bias + lane * 8);
        float4 bv1 = *(const float4*)(bias + lane * 8 + 4);
        float o0 = accA[0] * iv + bv0.x, o1 = accA[1] * iv + bv0.y;
        float o2 = accA[2] * iv + bv0.z, o3 = accA[3] * iv + bv0.w;
        float o4 = accA[4] * iv + bv1.x, o5 = accA[5] * iv + bv1.y;
        float o6 = accA[6] * iv + bv1.z, o7 = accA[7] * iv + bv1.w;
        if (sizeof(OutT) == 2) {
            __half2 h0 = __floats2half2_rn(o0, o1), h1 = __floats2half2_rn(o2, o3);
            __half2 h2 = __floats2half2_rn(o4, o5), h3 = __floats2half2_rn(o6, o7);
            uint4 pack;
            pack.x = *(u32*)&h0; pack.y = *(u32*)&h1; pack.z = *(u32*)&h2; pack.w = *(u32*)&h3;
            *(uint4*)((__half*)outp + (size_t)node * 256 + lane * 8) = pack;
        } else {
            float* op = (float*)outp + (size_t)node * 256 + lane * 8;
            *(float4*)op = make_float4(o0, o1, o2, o3);
            *(float4*)(op + 4) = make_float4(o4, o5, o6, o7);
        }
    } else {  // C == 16
        float2 acc = make_float2(0.f, 0.f);
        int j = base;
        for (; j + 4 <= end; j += 4) {
            int s0 = colsrc[j], s1 = colsrc[j + 1], s2 = colsrc[j + 2], s3 = colsrc[j + 3];
            float e0 = __ldg(aS + (j + 0) * 4 + myhead);
            float e1 = __ldg(aS + (j + 1) * 4 + myhead);
            float e2 = __ldg(aS + (j + 2) * 4 + myhead);
            float e3 = __ldg(aS + (j + 3) * 4 + myhead);
            float2 f0 = __half22float2(__ldg((const __half2*)(hh + (size_t)s0 * 64) + lane));
            float2 f1 = __half22float2(__ldg((const __half2*)(hh + (size_t)s1 * 64) + lane));
            float2 f2 = __half22float2(__ldg((const __half2*)(hh + (size_t)s2 * 64) + lane));
            float2 f3 = __half22float2(__ldg((const __half2*)(hh + (size_t)s3 * 64) + lane));
            acc.x = fmaf(f0.x, e0, acc.x); acc.y = fmaf(f0.y, e0, acc.y);
            acc.x = fmaf(f1.x, e1, acc.x); acc.y = fmaf(f1.y, e1, acc.y);
            acc.x = fmaf(f2.x, e2, acc.x); acc.y = fmaf(f2.y, e2, acc.y);
            acc.x = fmaf(f3.x, e3, acc.x); acc.y = fmaf(f3.y, e3, acc.y);
        }
        for (; j < end; j++) {
            int s = colsrc[j];
            float ew = __ldg(aS + j * 4 + myhead);
            float2 f = __half22float2(__ldg((const __half2*)(hh + (size_t)s * 64) + lane));
            acc.x = fmaf(f.x, ew, acc.x);
            acc.y = fmaf(f.y, ew, acc.y);
        }
        float2 bv = *(const float2*)(bias + 2 * lane);
        float ox = acc.x * iv + bv.x;
        float oy = acc.y * iv + bv.y;
        if (sizeof(OutT) == 2) {
            *(__half2*)((__half*)outp + (size_t)node * 64 + 2 * lane) = __floats2half2_rn(ox, oy);
        } else {
            *(float2*)((float*)outp + (size_t)node * 64 + 2 * lane) = make_float2(ox, oy);
        }
    }
}

// ---------------- launch ----------------
extern "C" void kernel_launch(void* const* d_in, const int* in_sizes, int n_in,
                              void* d_out, int out_size) {
    const float* x   = (const float*)d_in[0];
    const int*   ei  = (const int*)d_in[1];
    const float* ts  = (const float*)d_in[2];
    const float* tw  = (const float*)d_in[3];
    const float* tb  = (const float*)d_in[4];
    const float* W0  = (const float*)d_in[5];
    const float* as0 = (const float*)d_in[6];
    const float* ad0 = (const float*)d_in[7];
    const float* le0 = (const float*)d_in[8];
    const float* ae0 = (const float*)d_in[9];
    const float* b0  = (const float*)d_in[10];
    const float* W1  = (const float*)d_in[11];
    const float* as1 = (const float*)d_in[12];
    const float* ad1 = (const float*)d_in[13];
    const float* le1 = (const float*)d_in[14];
    const float* ae1 = (const float*)d_in[15];
    const float* b1  = (const float*)d_in[16];

    int n = in_sizes[0] / 128;   // 50000
    int e = in_sizes[2];         // 800000
    int tot = e + n;
    const int* srcp = ei;
    const int* dstp = ei + e;

    void *p_xh, *p_w0h, *p_w1h, *p_hh0, *p_out0h, *p_hh1;
    void *p_aE0, *p_aE1, *p_aE0c, *p_aE1c, *p_aCSR, *p_ss0, *p_sd0, *p_ss1, *p_sd1;
    void *p_deg, *p_rowptr, *p_cursor, *p_colsrc, *p_bsum;
    cudaGetSymbolAddress(&p_xh, g_xh);
    cudaGetSymbolAddress(&p_w0h, g_w0h);
    cudaGetSymbolAddress(&p_w1h, g_w1h);
    cudaGetSymbolAddress(&p_hh0, g_hh0);
    cudaGetSymbolAddress(&p_out0h, g_out0h);
    cudaGetSymbolAddress(&p_hh1, g_hh1);
    cudaGetSymbolAddress(&p_aE0, g_alphaE0);
    cudaGetSymbolAddress(&p_aE1, g_alphaE1);
    cudaGetSymbolAddress(&p_aE0c, g_aE0c);
    cudaGetSymbolAddress(&p_aE1c, g_aE1c);
    cudaGetSymbolAddress(&p_aCSR, g_aCSR);
    cudaGetSymbolAddress(&p_ss0, g_ss0);
    cudaGetSymbolAddress(&p_sd0, g_sd0);
    cudaGetSymbolAddress(&p_ss1, g_ss1);
    cudaGetSymbolAddress(&p_sd1, g_sd1);
    cudaGetSymbolAddress(&p_deg, g_deg);
    cudaGetSymbolAddress(&p_rowptr, g_rowptr);
    cudaGetSymbolAddress(&p_cursor, g_cursor);
    cudaGetSymbolAddress(&p_colsrc, g_colsrc);
    cudaGetSymbolAddress(&p_bsum, g_blocksum);

    __half* xh     = (__half*)p_xh;
    __half* w0h    = (__half*)p_w0h;
    __half* w1h    = (__half*)p_w1h;
    __half* hh0    = (__half*)p_hh0;
    __half* out0h  = (__half*)p_out0h;
    __half* hh1    = (__half*)p_hh1;
    float4* aE0    = (float4*)p_aE0;
    float4* aE1    = (float4*)p_aE1;
    float4* aE0c   = (float4*)p_aE0c;
    float4* aE1c   = (float4*)p_aE1c;
    float4* aCSR   = (float4*)p_aCSR;
    float4* ss0    = (float4*)p_ss0;
    float4* sd0    = (float4*)p_sd0;
    float4* ss1    = (float4*)p_ss1;
    float4* sd1    = (float4*)p_sd1;
    int* deg       = (int*)p_deg;
    int* rowptr    = (int*)p_rowptr;
    int* cursor    = (int*)p_cursor;
    int* colsrc    = (int*)p_colsrc;
    int* bsum      = (int*)p_bsum;

    int nb = (n + SCAN_TILE - 1) / SCAN_TILE;   // 13 for n=50000

    static cudaStream_t s1 = 0;
    static cudaEvent_t evFork = 0, evJoin = 0;
    if (s1 == 0) {
        cudaStreamCreateWithFlags(&s1, cudaStreamNonBlocking);
        cudaEventCreateWithFlags(&evFork, cudaEventDisableTiming);
        cudaEventCreateWithFlags(&evJoin, cudaEventDisableTiming);
    }

    // fork immediately: s1 runs cvt -> hgemm0 (independent of CSR chain)
    cudaEventRecord(evFork, 0);
    cudaStreamWaitEvent(s1, evFork, 0);
    cvt_kernel<<<512, 256, 0, s1>>>(x, W0, W1, xh, w0h, w1h, n);
    hgemm_kernel<64><<<dim3(256 / 64, (n + 127) / 128), 256, 0, s1>>>(
        xh, w0h, hh0, n, 128, 256, as0, ad0, (float*)ss0, (float*)sd0);
    cudaEventRecord(evJoin, s1);

    // main: CSR chain starts right away
    cudaMemsetAsync(deg, 0, (size_t)n * sizeof(int), 0);
    prep_kernel<<<1, 256>>>(le0, ae0, le1, ae1);
    edge_feat_kernel<<<(e + 511) / 512, 256>>>(ts, tw, tb, dstp, deg, aE0, aE1, e);
    scan1_kernel<<<nb, 1024>>>(deg, rowptr, bsum, n);
    scan3_kernel<<<(n + 255) / 256, 256>>>(rowptr, cursor, bsum, n, nb);
    scatter_kernel<<<(tot + 255) / 256, 256>>>(srcp, dstp, aE0, aE1, cursor, colsrc,
                                               aE0c, aE1c, e, n);
    // join: agg0 needs hh0/ss0/sd0 from s1 + CSR from main
    cudaStreamWaitEvent(0, evJoin, 0);
    agg_kernel<64, __half><<<(n * 32 + 255) / 256, 256>>>(rowptr, colsrc, aE0c, ss0, sd0,
                                                          hh0, b0, aCSR, out0h, n);
    hgemm_kernel<16><<<dim3(64 / 64, (n + 127) / 128), 256>>>(
        out0h, w1h, hh1, n, 256, 64, as1, ad1, (float*)ss1, (float*)sd1);
    agg_kernel<16, float><<<(n * 32 + 255) / 256, 256>>>(rowptr, colsrc, aE1c, ss1, sd1,
                                                         hh1, b1, aCSR, (float*)d_out, n);
}